// round 12
// baseline (speedup 1.0000x reference)
#include <cuda_runtime.h>
#include <cuda_bf16.h>
#include <math.h>
#include <stdint.h>

// Problem constants
#define LSEQ   8192
#define NFFT   16384
#define CH     1024
#define BATCH  2
#define MTOT   (BATCH*LSEQ)      // 16384 rows

// ---------------- scratch (device globals; no allocations allowed) ----------
__device__ float g_Vcm  [CH*MTOT];     // in_proj v branch, channel-major [c][m]
__device__ float g_X2t  [CH*MTOT];     // x2 branch, channel-major [c][m]
__device__ float g_COEFt[CH*LSEQ];     // filter coefs order-1, channel-major [c][l]

// bf16 split operands for the tensor-core GEMMs
__device__ __nv_bfloat16 g_Xh [MTOT*CH], g_Xl [MTOT*CH];     // x, [m][k]
__device__ __nv_bfloat16 g_Gh [CH*MTOT], g_Gl [CH*MTOT];     // gated, [c][m] (k-major)
__device__ __nv_bfloat16 g_Wih[2048*CH], g_Wil[2048*CH];     // in_proj cols, [n][k]
__device__ __nv_bfloat16 g_Woh[CH*CH],   g_Wol[CH*CH];       // out_w^T, [n][k]

// ---------------- generic helpers -------------------------------------------
__device__ __forceinline__ float gelu_exact(float x) {
    return 0.5f * x * (1.0f + erff(x * 0.70710678118654752f));
}
__device__ __forceinline__ float2 cmulf(float2 a, float2 b) {
    return make_float2(a.x*b.x - a.y*b.y, a.x*b.y + a.y*b.x);
}
__device__ __forceinline__ float2 cmulconjf(float2 a, float2 w) {  // a * conj(w)
    return make_float2(a.x*w.x + a.y*w.y, a.y*w.x - a.x*w.y);
}
__device__ __forceinline__ float2 caddf(float2 a, float2 b) {
    return make_float2(a.x + b.x, a.y + b.y);
}
__device__ __forceinline__ float2 csubf(float2 a, float2 b) {
    return make_float2(a.x - b.x, a.y - b.y);
}
__device__ __forceinline__ void bf16_split(float v, __nv_bfloat16 &h, __nv_bfloat16 &l) {
    h = __float2bfloat16(v);
    l = __float2bfloat16(v - __bfloat162float(h));
}
__device__ __forceinline__ uint32_t smem_u32(const void* p) {
    uint32_t a;
    asm("{ .reg .u64 t; cvta.to.shared.u64 t, %1; cvt.u32.u64 %0, t; }"
        : "=r"(a) : "l"(p));
    return a;
}

#define CP_ASYNC16(sm, gp) \
    asm volatile("cp.async.cg.shared.global [%0], [%1], 16;" \
                 :: "r"(sm), "l"(__cvta_generic_to_global(gp)) : "memory")
#define CP_COMMIT() asm volatile("cp.async.commit_group;" ::: "memory")
#define CP_WAIT0()  asm volatile("cp.async.wait_group 0;" ::: "memory")

#define LDSM4(r0, r1, r2, r3, ad) \
    asm volatile("ldmatrix.sync.aligned.m8n8.x4.shared.b16 {%0,%1,%2,%3}, [%4];" \
                 : "=r"(r0), "=r"(r1), "=r"(r2), "=r"(r3) : "r"(ad))
#define LDSM4T(r0, r1, r2, r3, ad) \
    asm volatile("ldmatrix.sync.aligned.m8n8.x4.trans.shared.b16 {%0,%1,%2,%3}, [%4];" \
                 : "=r"(r0), "=r"(r1), "=r"(r2), "=r"(r3) : "r"(ad))

__device__ __forceinline__ void mma_bf16(float* c, const uint32_t* a, const uint32_t* b) {
    asm volatile("mma.sync.aligned.m16n8k16.row.col.f32.bf16.bf16.f32 "
        "{%0,%1,%2,%3}, {%4,%5,%6,%7}, {%8,%9}, {%0,%1,%2,%3};"
        : "+f"(c[0]), "+f"(c[1]), "+f"(c[2]), "+f"(c[3])
        : "r"(a[0]), "r"(a[1]), "r"(a[2]), "r"(a[3]), "r"(b[0]), "r"(b[1]));
}

// ============================================================================
// prep_split: one kernel, three roles by block range.
//   [0, 16384)        : x -> g_Xh/g_Xl          ([m][k] bf16 hi/lo)
//   [16384, 17408)    : in_proj weight gather -> g_Wih/g_Wil ([n][k])
//   [17408, 18432)    : out_w transpose       -> g_Woh/g_Wol ([n][k])
// ============================================================================
__global__ __launch_bounds__(256) void prep_split(
    const float* __restrict__ x, const float* __restrict__ ipw,
    const float* __restrict__ ow)
{
    const int b   = blockIdx.x;
    const int tid = threadIdx.x;

    if (b < 16384) {
        size_t i = ((size_t)b * 256 + tid) * 4;
        float4 v = *(const float4*)&x[i];
        __nv_bfloat16 h[4], l[4];
        bf16_split(v.x, h[0], l[0]); bf16_split(v.y, h[1], l[1]);
        bf16_split(v.z, h[2], l[2]); bf16_split(v.w, h[3], l[3]);
        *(__nv_bfloat162*)&g_Xh[i]   = __nv_bfloat162(h[0], h[1]);
        *(__nv_bfloat162*)&g_Xh[i+2] = __nv_bfloat162(h[2], h[3]);
        *(__nv_bfloat162*)&g_Xl[i]   = __nv_bfloat162(l[0], l[1]);
        *(__nv_bfloat162*)&g_Xl[i+2] = __nv_bfloat162(l[2], l[3]);
        return;
    }

    if (b < 17408) {
        // in_proj gather: tile [32 k][96 j] through smem
        __shared__ float s[32][97];
        const int bid2 = b - 16384;
        const int c0 = (bid2 & 31) * 32;
        const int k0 = (bid2 >> 5) * 32;
        for (int idx = tid; idx < 32*96; idx += 256) {
            const int r = idx / 96, cc = idx % 96;
            s[r][cc] = ipw[(size_t)(k0 + r) * 3072 + 3*c0 + cc];
        }
        __syncthreads();
        const int dc = tid >> 3;
        const int kq = (tid & 7) * 4;
        const int c  = c0 + dc;
        __nv_bfloat16 vh[4], vl[4], xh[4], xl[4];
        #pragma unroll
        for (int u = 0; u < 4; u++) {
            bf16_split(s[kq+u][3*dc],     vh[u], vl[u]);
            bf16_split(s[kq+u][3*dc + 2], xh[u], xl[u]);
        }
        const size_t ov = (size_t)c * 1024 + k0 + kq;
        const size_t ox = (size_t)(1024 + c) * 1024 + k0 + kq;
        *(__nv_bfloat162*)&g_Wih[ov]   = __nv_bfloat162(vh[0], vh[1]);
        *(__nv_bfloat162*)&g_Wih[ov+2] = __nv_bfloat162(vh[2], vh[3]);
        *(__nv_bfloat162*)&g_Wil[ov]   = __nv_bfloat162(vl[0], vl[1]);
        *(__nv_bfloat162*)&g_Wil[ov+2] = __nv_bfloat162(vl[2], vl[3]);
        *(__nv_bfloat162*)&g_Wih[ox]   = __nv_bfloat162(xh[0], xh[1]);
        *(__nv_bfloat162*)&g_Wih[ox+2] = __nv_bfloat162(xh[2], xh[3]);
        *(__nv_bfloat162*)&g_Wil[ox]   = __nv_bfloat162(xl[0], xl[1]);
        *(__nv_bfloat162*)&g_Wil[ox+2] = __nv_bfloat162(xl[2], xl[3]);
        return;
    }

    {
        // out_w [k][n] -> [n][k] transpose + split (32x32 tile, 4 row-iters)
        __shared__ float s[32][33];
        const int bid2 = b - 17408;
        const int c0 = (bid2 & 31) * 32;
        const int k0 = (bid2 >> 5) * 32;
        const int tx  = tid & 31;
        const int ty0 = tid >> 5;            // 0..7
        #pragma unroll
        for (int rr = 0; rr < 4; rr++) {
            const int r = ty0 + rr * 8;
            s[r][tx] = ow[(size_t)(k0 + r) * CH + c0 + tx];
        }
        __syncthreads();
        #pragma unroll
        for (int rr = 0; rr < 4; rr++) {
            const int ty = ty0 + rr * 8;
            __nv_bfloat16 h, l;
            bf16_split(s[tx][ty], h, l);
            g_Woh[(size_t)(c0 + ty) * 1024 + k0 + tx] = h;
            g_Wol[(size_t)(c0 + ty) * 1024 + k0 + tx] = l;
        }
    }
}

// ============================================================================
// bf16 mma.sync GEMM (single 64KB buffer, KC=64, 2 syncs).  Frozen mainloop.
// MODE 0: in_proj. A = g_Xh/l [m][k]. Epilogue transposes -> g_Vcm/g_X2t.
// MODE 1: out proj. A = g_Gh/l [k][m], ldmatrix.trans. Epilogue -> out.
// ============================================================================
#define GSM_BYTES 65536

template<int MODE>
__global__ __launch_bounds__(256, 2) void gemm_bf16_tc(
    const float* __restrict__ bias, float* __restrict__ out)
{
    extern __shared__ char dsm[];
    const uint32_t sb  = smem_u32(dsm);
    const uint32_t sAh = sb, sBh = sb + 32768;

    const int tid  = threadIdx.x;
    const int lane = tid & 31;
    const int wid  = tid >> 5;
    const int wm   = wid >> 1;
    const int wn   = wid & 1;
    const int m0   = blockIdx.y * 128;
    const int bx   = blockIdx.x;
    const int n0   = bx * 128;

    const __nv_bfloat16* Ah = (MODE == 0) ? g_Xh : g_Gh;
    const __nv_bfloat16* Al = (MODE == 0) ? g_Xl : g_Gl;
    const __nv_bfloat16* Bh = (MODE == 0) ? g_Wih : g_Woh;
    const __nv_bfloat16* Bl = (MODE == 0) ? g_Wil : g_Wol;

    float acc[2][8][4];
    #pragma unroll
    for (int i = 0; i < 2; i++)
        #pragma unroll
        for (int j = 0; j < 8; j++)
            #pragma unroll
            for (int q = 0; q < 4; q++) acc[i][j][q] = 0.f;

    for (int it = 0; it < 16; ++it) {
        const size_t kc0 = (size_t)it * 64;
        if (MODE == 0) {
            #pragma unroll
            for (int u = 0; u < 4; u++) {
                const int s = tid + u * 256;
                const int row = s >> 3, seg = s & 7;
                const uint32_t so = (uint32_t)(row * 128 + ((seg * 16) ^ ((row & 7) << 4)));
                const size_t ga = (size_t)(m0 + row) * 1024 + kc0 + seg * 8;
                const size_t gb = (size_t)(n0 + row) * 1024 + kc0 + seg * 8;
                CP_ASYNC16(sAh + so, Ah + ga);
                CP_ASYNC16(sAh + 16384 + so, Al + ga);
                CP_ASYNC16(sBh + so, Bh + gb);
                CP_ASYNC16(sBh + 16384 + so, Bl + gb);
            }
        } else {
            #pragma unroll
            for (int u = 0; u < 4; u++) {
                const int s = tid + u * 256;
                const int row = s >> 4, seg = s & 15;
                const uint32_t so = (uint32_t)(row * 256 + ((seg * 16) ^ ((row & 7) << 4)));
                const size_t ga = (size_t)(kc0 + row) * MTOT + m0 + seg * 8;
                CP_ASYNC16(sAh + so, Ah + ga);
                CP_ASYNC16(sAh + 16384 + so, Al + ga);
            }
            #pragma unroll
            for (int u = 0; u < 4; u++) {
                const int s = tid + u * 256;
                const int row = s >> 3, seg = s & 7;
                const uint32_t so = (uint32_t)(row * 128 + ((seg * 16) ^ ((row & 7) << 4)));
                const size_t gb = (size_t)(n0 + row) * 1024 + kc0 + seg * 8;
                CP_ASYNC16(sBh + so, Bh + gb);
                CP_ASYNC16(sBh + 16384 + so, Bl + gb);
            }
        }
        CP_COMMIT();
        CP_WAIT0();
        __syncthreads();

        #pragma unroll
        for (int ks = 0; ks < 4; ks++) {
            uint32_t ah[2][4], al[2][4];
            #pragma unroll
            for (int mt = 0; mt < 2; mt++) {
                if (MODE == 0) {
                    const int row = wm * 32 + mt * 16 + (lane & 15);
                    const uint32_t r4 = (row & 7) << 4;
                    const uint32_t cb = (uint32_t)(ks * 32 + ((lane >> 4) << 4));
                    const uint32_t ad = sAh + row * 128 + (cb ^ r4);
                    LDSM4(ah[mt][0], ah[mt][1], ah[mt][2], ah[mt][3], ad);
                    LDSM4(al[mt][0], al[mt][1], al[mt][2], al[mt][3], ad + 16384);
                } else {
                    const int rowk = ks * 16 + (lane & 7) + ((lane >> 4) << 3);
                    const int mcol = wm * 32 + mt * 16 + (((lane >> 3) & 1) << 3);
                    const uint32_t ad = sAh + rowk * 256 +
                        (((uint32_t)(2 * mcol)) ^ ((uint32_t)(rowk & 7) << 4));
                    LDSM4T(ah[mt][0], ah[mt][1], ah[mt][2], ah[mt][3], ad);
                    LDSM4T(al[mt][0], al[mt][1], al[mt][2], al[mt][3], ad + 16384);
                }
            }
            uint32_t bh[8][2], bl[8][2];
            #pragma unroll
            for (int nt2 = 0; nt2 < 4; nt2++) {
                const int n = wn * 64 + nt2 * 16 + (lane & 7) + ((lane >> 4) << 3);
                const uint32_t r4 = (n & 7) << 4;
                const uint32_t cb = (uint32_t)(ks * 32 + (((lane >> 3) & 1) << 4));
                const uint32_t ad = sBh + n * 128 + (cb ^ r4);
                LDSM4(bh[2*nt2][0], bh[2*nt2][1], bh[2*nt2+1][0], bh[2*nt2+1][1], ad);
                LDSM4(bl[2*nt2][0], bl[2*nt2][1], bl[2*nt2+1][0], bl[2*nt2+1][1], ad + 16384);
            }
            #pragma unroll
            for (int mt = 0; mt < 2; mt++)
                #pragma unroll
                for (int nt = 0; nt < 8; nt++) {
                    mma_bf16(acc[mt][nt], ah[mt], bh[nt]);
                    mma_bf16(acc[mt][nt], ah[mt], bl[nt]);
                    mma_bf16(acc[mt][nt], al[mt], bh[nt]);
                }
        }
        __syncthreads();
    }

    if (MODE == 0) {
        float* stage = (float*)dsm;          // [128][65] floats = 33 KB
        const bool is_v = (bx < 8);
        const int cbase = (is_v ? bx : bx - 8) * 128;
        #pragma unroll
        for (int h = 0; h < 2; h++) {
            __syncthreads();
            if (wn == h) {
                #pragma unroll
                for (int mt = 0; mt < 2; mt++) {
                    const int rl = wm * 32 + mt * 16 + (lane >> 2);
                    #pragma unroll
                    for (int nt = 0; nt < 8; nt++) {
                        const int cl = nt * 8 + ((lane & 3) << 1);
                        stage[rl * 65 + cl]           = acc[mt][nt][0];
                        stage[rl * 65 + cl + 1]       = acc[mt][nt][1];
                        stage[(rl + 8) * 65 + cl]     = acc[mt][nt][2];
                        stage[(rl + 8) * 65 + cl + 1] = acc[mt][nt][3];
                    }
                }
            }
            __syncthreads();
            const int cl  = tid >> 2;
            const int mch = (tid & 3) << 5;
            const int c   = cbase + h * 64 + cl;
            const float b = is_v ? bias[3*c] : bias[3*c + 2];
            float* dst = (is_v ? g_Vcm : g_X2t) + (size_t)c * MTOT + m0 + mch;
            #pragma unroll
            for (int j = 0; j < 32; j += 4) {
                float4 o = make_float4(stage[(mch+j)*65   + cl] + b,
                                       stage[(mch+j+1)*65 + cl] + b,
                                       stage[(mch+j+2)*65 + cl] + b,
                                       stage[(mch+j+3)*65 + cl] + b);
                *(float4*)&dst[j] = o;
            }
        }
    } else {
        #pragma unroll
        for (int mt = 0; mt < 2; mt++) {
            const int r = m0 + wm * 32 + mt * 16 + (lane >> 2);
            #pragma unroll
            for (int nt = 0; nt < 8; nt++) {
                const int c = n0 + wn * 64 + nt * 8 + ((lane & 3) << 1);
                const float b0 = bias[c], b1 = bias[c + 1];
                *(float2*)&out[(size_t)r * CH + c] =
                    make_float2(acc[mt][nt][0] + b0, acc[mt][nt][1] + b1);
                *(float2*)&out[(size_t)(r + 8) * CH + c] =
                    make_float2(acc[mt][nt][2] + b0, acc[mt][nt][3] + b1);
            }
        }
    }
}

// ============================================================================
// GEMM coef with the filter MLP fused:
//   h2 block (128 l x 128 t) computed in-kernel into smem, then
//   COEFt[c][l] = (h2 @ fw3[:,2c+1] + fb3[2c+1]) with transposed epilogue.
// Dynamic smem: h2b[128 t][129 m] (66KB); epilogue stage aliases it (33KB).
// ============================================================================
#define COEF_SMEM (128 * 129 * 4)

__global__ __launch_bounds__(256) void gemm_coef_fused(
    const float* __restrict__ fw1, const float* __restrict__ fb1,
    const float* __restrict__ fw2, const float* __restrict__ fb2,
    const float* __restrict__ fw3, const float* __restrict__ fb3)
{
    extern __shared__ float csm[];
    float* h2b = csm;                    // [t][m], pitch 129
    __shared__ float Bs[8][128];
    const int tid = threadIdx.x;
    const int tx = tid & 15, ty = tid >> 4;
    const int m0 = blockIdx.y * 128;
    const int n0 = blockIdx.x * 128;

    // ---- build h2 block: thread pair per row; each handles 64 t-outputs ----
    {
        const int r  = tid >> 1;
        const int t0 = (tid & 1) * 64;
        const float pos = (float)(m0 + r) * (1.0f / (float)(LSEQ - 1));
        float h1[64];
        #pragma unroll
        for (int j = 0; j < 64; j++)
            h1[j] = gelu_exact(pos * fw1[j] + fb1[j]);
        for (int dt = 0; dt < 64; dt++) {
            const int t = t0 + dt;
            float s = fb2[t];
            #pragma unroll 8
            for (int j = 0; j < 64; j++) s += h1[j] * fw2[j*128 + t];
            h2b[t * 129 + r] = gelu_exact(s);
        }
    }
    __syncthreads();

    float acc[8][8];
    #pragma unroll
    for (int i = 0; i < 8; i++)
        #pragma unroll
        for (int j = 0; j < 8; j++) acc[i][j] = 0.f;

    const int bn = tid & 127;
    const int jm = 2 * (n0 + bn) + 1;
    const int kk0 = (tid >> 7) * 4;

    for (int k0 = 0; k0 < 128; k0 += 8) {
        #pragma unroll
        for (int r = 0; r < 4; r++)
            Bs[kk0 + r][bn] = fw3[(size_t)(k0 + kk0 + r) * 2048 + jm];
        __syncthreads();
        #pragma unroll
        for (int kk = 0; kk < 8; kk++) {
            float a[8], b[8];
            #pragma unroll
            for (int i = 0; i < 8; i++) a[i] = h2b[(k0 + kk) * 129 + ty*8 + i];
            #pragma unroll
            for (int j = 0; j < 8; j++) b[j] = Bs[kk][tx*8 + j];
            #pragma unroll
            for (int i = 0; i < 8; i++)
                #pragma unroll
                for (int j = 0; j < 8; j++) acc[i][j] += a[i] * b[j];
        }
        __syncthreads();
    }

    float bo[8];
    #pragma unroll
    for (int j = 0; j < 8; j++) bo[j] = fb3[2*(n0 + tx*8 + j) + 1];

    // transposed epilogue (stage aliases h2b; h2b is dead now)
    float* stage = csm;                  // [128][65]
    #pragma unroll
    for (int h = 0; h < 2; h++) {
        __syncthreads();
        if ((tx >> 3) == h) {
            #pragma unroll
            for (int i = 0; i < 8; i++)
                #pragma unroll
                for (int j = 0; j < 8; j++)
                    stage[(ty*8 + i) * 65 + (tx & 7) * 8 + j] = acc[i][j] + bo[j];
        }
        __syncthreads();
        const int cl  = tid >> 2;
        const int lch = (tid & 3) << 5;
        const int c   = n0 + h * 64 + cl;
        float* dst = g_COEFt + (size_t)c * LSEQ + m0 + lch;
        #pragma unroll
        for (int j = 0; j < 32; j += 4) {
            float4 o = make_float4(stage[(lch+j)*65   + cl],
                                   stage[(lch+j+1)*65 + cl],
                                   stage[(lch+j+2)*65 + cl],
                                   stage[(lch+j+3)*65 + cl]);
            *(float4*)&dst[j] = o;
        }
    }
}

// ============================================================================
// FFT convolution — radix-16 passes, padded smem, smem Hermitian half-
// spectrum; filter stash fused into the filter FFT's final pass. (unchanged)
// ============================================================================
#define FFT_T    512
#define ZI(i) ((i) + ((i) >> 4))
#define Z_PAD_SZ  17408                 // float2
#define HS_PAD_SZ 8232                  // float2
#define COS_SZ    4104                  // floats
#define HsI(k) ((k) + ((k) >> 8))
#define FFT_SMEM ((Z_PAD_SZ + HS_PAD_SZ) * 8 + COS_SZ * 4)

__device__ __forceinline__ int digrev4_14(int j) {
    unsigned r = __brev((unsigned)j) >> 18;
    return (int)(((r & 0x2AAAu) >> 1) | ((r & 0x1555u) << 1));
}
__device__ __forceinline__ int digrev4_10(int g) {
    unsigned r = __brev((unsigned)g) >> 22;
    return (int)(((r & 0x155u) << 1) | ((r >> 1) & 0x155u));
}
__device__ __forceinline__ float2 twc(const float* __restrict__ C, int k) {
    return make_float2(C[k], -C[4096 - k]);
}
__device__ __forceinline__ float conv3(const float* __restrict__ q, int l,
                                       float w0, float w1, float w2, float b) {
    float s = w1 * q[l] + b;
    if (l > 0)        s += w0 * q[l-1];
    if (l < LSEQ - 1) s += w2 * q[l+1];
    return s;
}

__device__ void fft_dif_first(float2* Z, const float* C,
                              const float* __restrict__ re, int tid) {
    for (int p = tid; p < 4096; p += FFT_T) {
        float2 a = make_float2(re[p], 0.f);
        float2 b = make_float2(re[p + 4096], 0.f);
        float2 w1 = twc(C, p);
        float2 w2 = cmulf(w1, w1);
        float2 w3 = cmulf(w2, w1);
        Z[ZI(p)]         = caddf(a, b);
        Z[ZI(p + 4096)]  = cmulf(make_float2(a.x + b.y, a.y - b.x), w1);
        Z[ZI(p + 8192)]  = cmulf(csubf(a, b),                       w2);
        Z[ZI(p + 12288)] = cmulf(make_float2(a.x - b.y, a.y + b.x), w3);
    }
    __syncthreads();
}

__device__ void fft_dif_first_conv(float2* Z, const float* C,
                                   const float* __restrict__ v0,
                                   float w0, float w1, float w2, float cb, int tid) {
    const float* v1 = v0 + LSEQ;
    for (int p = tid; p < 4096; p += FFT_T) {
        float2 a = make_float2(conv3(v0, p, w0, w1, w2, cb),
                               conv3(v1, p, w0, w1, w2, cb));
        float2 b = make_float2(conv3(v0, p + 4096, w0, w1, w2, cb),
                               conv3(v1, p + 4096, w0, w1, w2, cb));
        float2 t1 = twc(C, p);
        float2 t2 = cmulf(t1, t1);
        float2 t3 = cmulf(t2, t1);
        Z[ZI(p)]         = caddf(a, b);
        Z[ZI(p + 4096)]  = cmulf(make_float2(a.x + b.y, a.y - b.x), t1);
        Z[ZI(p + 8192)]  = cmulf(csubf(a, b),                       t2);
        Z[ZI(p + 12288)] = cmulf(make_float2(a.x - b.y, a.y + b.x), t3);
    }
    __syncthreads();
}

template<int LA, int TWA>
__device__ void fft_dif_pass16(float2* Z, const float* C, int tid) {
    constexpr int qA = LA / 4, qB = LA / 16;
    constexpr int TWB = TWA + 2;
    const int p2 = tid & (qB - 1);
    float2 wA1[4], wA2[4], wA3[4];
    #pragma unroll
    for (int a = 0; a < 4; a++) {
        const int k = (p2 + a*qB) << TWA;
        wA1[a] = twc(C, k);
        wA2[a] = cmulf(wA1[a], wA1[a]);
        wA3[a] = cmulf(wA2[a], wA1[a]);
    }
    const int k2 = p2 << TWB;
    const float2 wB1 = twc(C, k2);
    const float2 wB2 = cmulf(wB1, wB1);
    const float2 wB3 = cmulf(wB2, wB1);
    #pragma unroll
    for (int half = 0; half < 2; half++) {
        const int g = tid + half * FFT_T;
        const int base = (g / qB) * LA + p2;
        float2 x[4][4];
        #pragma unroll
        for (int b = 0; b < 4; b++)
            #pragma unroll
            for (int a = 0; a < 4; a++)
                x[b][a] = Z[ZI(base + a*qB + b*qA)];
        #pragma unroll
        for (int a = 0; a < 4; a++) {
            float2 t0 = caddf(x[0][a], x[2][a]);
            float2 t1 = csubf(x[0][a], x[2][a]);
            float2 t2 = caddf(x[1][a], x[3][a]);
            float2 bd = csubf(x[1][a], x[3][a]);
            float2 t3 = make_float2(bd.y, -bd.x);
            x[0][a] = caddf(t0, t2);
            x[1][a] = cmulf(caddf(t1, t3), wA1[a]);
            x[2][a] = cmulf(csubf(t0, t2), wA2[a]);
            x[3][a] = cmulf(csubf(t1, t3), wA3[a]);
        }
        #pragma unroll
        for (int b = 0; b < 4; b++) {
            float2 t0 = caddf(x[b][0], x[b][2]);
            float2 t1 = csubf(x[b][0], x[b][2]);
            float2 t2 = caddf(x[b][1], x[b][3]);
            float2 bd = csubf(x[b][1], x[b][3]);
            float2 t3 = make_float2(bd.y, -bd.x);
            Z[ZI(base + 0*qB + b*qA)] = caddf(t0, t2);
            Z[ZI(base + 1*qB + b*qA)] = cmulf(caddf(t1, t3), wB1);
            Z[ZI(base + 2*qB + b*qA)] = cmulf(csubf(t0, t2), wB2);
            Z[ZI(base + 3*qB + b*qA)] = cmulf(csubf(t1, t3), wB3);
        }
    }
    __syncthreads();
}

__device__ void fft_dif_pass16_stash(float2* Z, const float* C,
                                     float2* __restrict__ Hs, int tid) {
    float2 wA1[4], wA2[4], wA3[4];
    #pragma unroll
    for (int a = 0; a < 4; a++) {
        const int k = a << 10;
        wA1[a] = twc(C, k);
        wA2[a] = cmulf(wA1[a], wA1[a]);
        wA3[a] = cmulf(wA2[a], wA1[a]);
    }
    #pragma unroll
    for (int half = 0; half < 2; half++) {
        const int g = tid + half * FFT_T;
        const int base = g * 16;
        const int kg = digrev4_10(g);
        float2 x[4][4];
        #pragma unroll
        for (int b = 0; b < 4; b++)
            #pragma unroll
            for (int a = 0; a < 4; a++)
                x[b][a] = Z[ZI(base + a + 4*b)];
        #pragma unroll
        for (int a = 0; a < 4; a++) {
            float2 t0 = caddf(x[0][a], x[2][a]);
            float2 t1 = csubf(x[0][a], x[2][a]);
            float2 t2 = caddf(x[1][a], x[3][a]);
            float2 bd = csubf(x[1][a], x[3][a]);
            float2 t3 = make_float2(bd.y, -bd.x);
            x[0][a] = caddf(t0, t2);
            x[1][a] = cmulf(caddf(t1, t3), wA1[a]);
            x[2][a] = cmulf(csubf(t0, t2), wA2[a]);
            x[3][a] = cmulf(csubf(t1, t3), wA3[a]);
        }
        #pragma unroll
        for (int b = 0; b < 4; b++) {
            float2 t0 = caddf(x[b][0], x[b][2]);
            float2 t1 = csubf(x[b][0], x[b][2]);
            float2 t2 = caddf(x[b][1], x[b][3]);
            float2 bd = csubf(x[b][1], x[b][3]);
            float2 t3 = make_float2(bd.y, -bd.x);
            const int k0 = kg + b * 1024;
            Hs[HsI(k0)]        = caddf(t0, t2);      // o=0
            Hs[HsI(k0 + 4096)] = caddf(t1, t3);      // o=1
            if (k0 == 0) Hs[HsI(8192)] = csubf(t0, t2);  // k=8192 edge
        }
    }
    __syncthreads();
}

__device__ void ifft_first_mult(float2* Z, const float2* __restrict__ Hs, int tid) {
    for (int b = tid; b < NFFT/4; b += FFT_T) {
        const int i0 = 4*b;
        const int kb = digrev4_14(i0);
        float2 zz[4];
        #pragma unroll
        for (int s2 = 0; s2 < 4; s2++) {
            const int k = kb + s2 * 4096;
            float2 H;
            if (k <= 8192) H = Hs[HsI(k)];
            else { const int kc = 16384 - k; H = Hs[HsI(kc)]; H.y = -H.y; }
            zz[s2] = cmulf(Z[ZI(i0 + s2)], H);
        }
        float2 t0 = caddf(zz[0], zz[2]), t1 = csubf(zz[0], zz[2]);
        float2 t2 = caddf(zz[1], zz[3]);
        float2 bd = csubf(zz[1], zz[3]);
        float2 t3 = make_float2(-bd.y, bd.x);
        Z[ZI(i0)]     = caddf(t0, t2);
        Z[ZI(i0 + 1)] = caddf(t1, t3);
        Z[ZI(i0 + 2)] = csubf(t0, t2);
        Z[ZI(i0 + 3)] = csubf(t1, t3);
    }
    __syncthreads();
}

template<int L1, int TW1>
__device__ void ifft_dit_pass16(float2* Z, const float* C, int tid) {
    constexpr int q1 = L1 / 4, L2 = 4 * L1;
    constexpr int TW2 = TW1 - 2;
    const int p = tid & (q1 - 1);
    const int k1 = p << TW1;
    const float2 u1 = twc(C, k1);
    const float2 u2 = cmulf(u1, u1);
    const float2 u3 = cmulf(u2, u1);
    float2 v1[4], v2[4], v3[4];
    #pragma unroll
    for (int a = 0; a < 4; a++) {
        const int kk = (p + a*q1) << TW2;
        v1[a] = twc(C, kk);
        v2[a] = cmulf(v1[a], v1[a]);
        v3[a] = cmulf(v2[a], v1[a]);
    }
    #pragma unroll
    for (int half = 0; half < 2; half++) {
        const int g = tid + half * FFT_T;
        const int base = (g / q1) * L2 + p;
        float2 x[4][4];
        #pragma unroll
        for (int b = 0; b < 4; b++)
            #pragma unroll
            for (int a = 0; a < 4; a++)
                x[b][a] = Z[ZI(base + a*q1 + b*L1)];
        #pragma unroll
        for (int b = 0; b < 4; b++) {
            float2 a0 = x[b][0];
            float2 a1 = cmulconjf(x[b][1], u1);
            float2 a2 = cmulconjf(x[b][2], u2);
            float2 a3 = cmulconjf(x[b][3], u3);
            float2 t0 = caddf(a0, a2), t1 = csubf(a0, a2);
            float2 t2 = caddf(a1, a3);
            float2 bd = csubf(a1, a3);
            float2 t3 = make_float2(-bd.y, bd.x);
            x[b][0] = caddf(t0, t2);
            x[b][1] = caddf(t1, t3);
            x[b][2] = csubf(t0, t2);
            x[b][3] = csubf(t1, t3);
        }
        #pragma unroll
        for (int a = 0; a < 4; a++) {
            float2 b0 = x[0][a];
            float2 b1 = cmulconjf(x[1][a], v1[a]);
            float2 b2 = cmulconjf(x[2][a], v2[a]);
            float2 b3 = cmulconjf(x[3][a], v3[a]);
            float2 t0 = caddf(b0, b2), t1 = csubf(b0, b2);
            float2 t2 = caddf(b1, b3);
            float2 bd = csubf(b1, b3);
            float2 t3 = make_float2(-bd.y, bd.x);
            Z[ZI(base + a*q1 + 0*L1)] = caddf(t0, t2);
            Z[ZI(base + a*q1 + 1*L1)] = caddf(t1, t3);
            Z[ZI(base + a*q1 + 2*L1)] = csubf(t0, t2);
            Z[ZI(base + a*q1 + 3*L1)] = csubf(t1, t3);
        }
    }
    __syncthreads();
}

__global__ __launch_bounds__(FFT_T, 1) void fft_conv_kernel(
    const float* __restrict__ sw, const float* __restrict__ sb)
{
    extern __shared__ float2 sm[];
    float2* Z  = sm;
    float2* Hs = sm + Z_PAD_SZ;
    float*  C  = (float*)(sm + Z_PAD_SZ + HS_PAD_SZ);
    const int c   = blockIdx.x;
    const int tid = threadIdx.x;

    for (int k = tid; k <= 4096; k += FFT_T)
        C[k] = cosf(3.834951969714103e-4f * (float)k);   // cos(2*pi*k/16384)
    __syncthreads();

    // ---- filter FFT; final pass writes half-spectrum straight to smem Hs ----
    fft_dif_first(Z, C, g_COEFt + (size_t)c * LSEQ, tid);
    fft_dif_pass16<4096, 2>(Z, C, tid);
    fft_dif_pass16<256, 6>(Z, C, tid);
    fft_dif_pass16_stash(Z, C, Hs, tid);

    // ---- v FFT with fused depthwise short-conv ----
    const float w0 = sw[c*3], w1 = sw[c*3+1], w2 = sw[c*3+2], cb = sb[c];
    fft_dif_first_conv(Z, C, g_Vcm + (size_t)c * MTOT, w0, w1, w2, cb, tid);
    fft_dif_pass16<4096, 2>(Z, C, tid);
    fft_dif_pass16<256, 6>(Z, C, tid);
    fft_dif_pass16<16, 10>(Z, C, tid);

    // ---- inverse: multiply (from smem half-spectrum) fused into len-4 stage
    ifft_first_mult(Z, Hs, tid);
    ifft_dit_pass16<16, 10>(Z, C, tid);
    ifft_dit_pass16<256, 6>(Z, C, tid);

    // ---- final paired pass fused with gate + bf16 hi/lo store ([c][m]) ----
    const float* x2 = g_X2t + (size_t)c * MTOT;
    __nv_bfloat16* goh = g_Gh + (size_t)c * MTOT;
    __nv_bfloat16* gol = g_Gl + (size_t)c * MTOT;
    const float scale = 1.0f / (float)NFFT;
    for (int p = tid; p < 1024; p += FFT_T) {
        float2 x[4][4];
        #pragma unroll
        for (int b = 0; b < 4; b++)
            #pragma unroll
            for (int a = 0; a < 4; a++)
                x[b][a] = Z[ZI(p + a*1024 + b*4096)];
        const float2 u1 = twc(C, p << 2);
        const float2 u2 = cmulf(u1, u1);
        const float2 u3 = cmulf(u2, u1);
        #pragma unroll
        for (int b = 0; b < 4; b++) {
            float2 a0 = x[b][0];
            float2 a1 = cmulconjf(x[b][1], u1);
            float2 a2 = cmulconjf(x[b][2], u2);
            float2 a3 = cmulconjf(x[b][3], u3);
            float2 t0 = caddf(a0, a2), t1 = csubf(a0, a2);
            float2 t2 = caddf(a1, a3);
            float2 bd = csubf(a1, a3);
            float2 t3 = make_float2(-bd.y, bd.x);
            x[b][0] = caddf(t0, t2);
            x[b][1] = caddf(t1, t3);
            x[b][2] = csubf(t0, t2);
            x[b][3] = csubf(t1, t3);
        }
        #pragma unroll
        for (int a = 0; a < 4; a++) {
            const int k2 = p + a*1024;
            const float2 q1 = twc(C, k2);
            const float2 q2 = cmulf(q1, q1);
            const float2 q3 = cmulf(q2, q1);
            float2 b0 = x[0][a];
            float2 b1 = cmulconjf(x[1][a], q1);
            float2 b2 = cmulconjf(x[2][a], q2);
            float2 b3 = cmulconjf(x[3][a], q3);
            float2 t0 = caddf(b0, b2), t1 = csubf(b0, b2);
            float2 t2 = caddf(b1, b3);
            float2 bd = csubf(b1, b3);
            float2 t3 = make_float2(-bd.y, bd.x);
            float2 o0 = caddf(t0, t2);         // time t
            float2 o1 = caddf(t1, t3);         // time t+4096
            const int t = p + a*1024;
            float gv;
            __nv_bfloat16 hh, ll;
            gv = x2[t]               * (o0.x * scale); bf16_split(gv, hh, ll);
            goh[t] = hh;               gol[t] = ll;
            gv = x2[LSEQ + t]        * (o0.y * scale); bf16_split(gv, hh, ll);
            goh[LSEQ + t] = hh;        gol[LSEQ + t] = ll;
            gv = x2[t + 4096]        * (o1.x * scale); bf16_split(gv, hh, ll);
            goh[t + 4096] = hh;        gol[t + 4096] = ll;
            gv = x2[LSEQ + t + 4096] * (o1.y * scale); bf16_split(gv, hh, ll);
            goh[LSEQ + t + 4096] = hh; gol[LSEQ + t + 4096] = ll;
        }
    }
}

// ============================================================================
extern "C" void kernel_launch(void* const* d_in, const int* in_sizes, int n_in,
                              void* d_out, int out_size)
{
    const float* x   = (const float*)d_in[0];
    const float* ipw = (const float*)d_in[1];
    const float* ipb = (const float*)d_in[2];
    const float* sw  = (const float*)d_in[3];
    const float* sb  = (const float*)d_in[4];
    const float* fw1 = (const float*)d_in[5];
    const float* fb1 = (const float*)d_in[6];
    const float* fw2 = (const float*)d_in[7];
    const float* fb2 = (const float*)d_in[8];
    const float* fw3 = (const float*)d_in[9];
    const float* fb3 = (const float*)d_in[10];
    const float* ow  = (const float*)d_in[11];
    const float* ob  = (const float*)d_in[12];
    float* out = (float*)d_out;

    cudaFuncSetAttribute(fft_conv_kernel,
                         cudaFuncAttributeMaxDynamicSharedMemorySize, FFT_SMEM);
    cudaFuncSetAttribute(gemm_bf16_tc<0>,
                         cudaFuncAttributeMaxDynamicSharedMemorySize, GSM_BYTES);
    cudaFuncSetAttribute(gemm_bf16_tc<1>,
                         cudaFuncAttributeMaxDynamicSharedMemorySize, GSM_BYTES);
    cudaFuncSetAttribute(gemm_coef_fused,
                         cudaFuncAttributeMaxDynamicSharedMemorySize, COEF_SMEM);

    // 1) one prep kernel: x split + in_proj gather + out_w transpose
    prep_split<<<18432, 256>>>(x, ipw, ow);
    // 2) in_proj GEMM; epilogue writes v/x2 directly in channel-major
    gemm_bf16_tc<0><<<dim3(16, 128), 256, GSM_BYTES>>>(ipb, nullptr);
    // 3) coef GEMM with filter MLP fused (transposed epilogue -> COEFt)
    gemm_coef_fused<<<dim3(8, 64), 256, COEF_SMEM>>>(fw1, fb1, fw2, fb2, fw3, fb3);
    // 4) FFT long conv (fused short-conv, stash, mult, gate, bf16 split out)
    fft_conv_kernel<<<CH, FFT_T, FFT_SMEM>>>(sw, sb);
    // 5) out GEMM reads gated activations k-major via ldmatrix.trans
    gemm_bf16_tc<1><<<dim3(8, 128), 256, GSM_BYTES>>>(ob, out);
}

// round 13
// speedup vs baseline: 1.5384x; 1.5384x over previous
#include <cuda_runtime.h>
#include <cuda_bf16.h>
#include <math.h>
#include <stdint.h>

// Problem constants
#define LSEQ   8192
#define NFFT   16384
#define CH     1024
#define BATCH  2
#define MTOT   (BATCH*LSEQ)      // 16384 rows

// ---------------- scratch (device globals; no allocations allowed) ----------
__device__ float g_Vcm  [CH*MTOT];     // in_proj v branch, channel-major [c][m]
__device__ float g_X2t  [CH*MTOT];     // x2 branch, channel-major [c][m]
__device__ float g_H2   [LSEQ*128];    // filter MLP hidden (L x 128)
__device__ float g_COEFt[CH*LSEQ];     // filter coefs order-1, channel-major [c][l]

// bf16 split operands for the tensor-core GEMMs
__device__ __nv_bfloat16 g_Xh [MTOT*CH], g_Xl [MTOT*CH];     // x, [m][k]
__device__ __nv_bfloat16 g_Gh [CH*MTOT], g_Gl [CH*MTOT];     // gated, [c][m] (k-major)
__device__ __nv_bfloat16 g_Wih[2048*CH], g_Wil[2048*CH];     // in_proj cols, [n][k]
__device__ __nv_bfloat16 g_Woh[CH*CH],   g_Wol[CH*CH];       // out_w^T, [n][k]

// ---------------- generic helpers -------------------------------------------
__device__ __forceinline__ float gelu_exact(float x) {
    return 0.5f * x * (1.0f + erff(x * 0.70710678118654752f));
}
__device__ __forceinline__ float2 cmulf(float2 a, float2 b) {
    return make_float2(a.x*b.x - a.y*b.y, a.x*b.y + a.y*b.x);
}
__device__ __forceinline__ float2 cmulconjf(float2 a, float2 w) {  // a * conj(w)
    return make_float2(a.x*w.x + a.y*w.y, a.y*w.x - a.x*w.y);
}
__device__ __forceinline__ float2 caddf(float2 a, float2 b) {
    return make_float2(a.x + b.x, a.y + b.y);
}
__device__ __forceinline__ float2 csubf(float2 a, float2 b) {
    return make_float2(a.x - b.x, a.y - b.y);
}
__device__ __forceinline__ void bf16_split(float v, __nv_bfloat16 &h, __nv_bfloat16 &l) {
    h = __float2bfloat16(v);
    l = __float2bfloat16(v - __bfloat162float(h));
}
__device__ __forceinline__ uint32_t smem_u32(const void* p) {
    uint32_t a;
    asm("{ .reg .u64 t; cvta.to.shared.u64 t, %1; cvt.u32.u64 %0, t; }"
        : "=r"(a) : "l"(p));
    return a;
}

#define CP_ASYNC16(sm, gp) \
    asm volatile("cp.async.cg.shared.global [%0], [%1], 16;" \
                 :: "r"(sm), "l"(__cvta_generic_to_global(gp)) : "memory")
#define CP_COMMIT() asm volatile("cp.async.commit_group;" ::: "memory")
#define CP_WAIT0()  asm volatile("cp.async.wait_group 0;" ::: "memory")

#define LDSM4(r0, r1, r2, r3, ad) \
    asm volatile("ldmatrix.sync.aligned.m8n8.x4.shared.b16 {%0,%1,%2,%3}, [%4];" \
                 : "=r"(r0), "=r"(r1), "=r"(r2), "=r"(r3) : "r"(ad))
#define LDSM4T(r0, r1, r2, r3, ad) \
    asm volatile("ldmatrix.sync.aligned.m8n8.x4.trans.shared.b16 {%0,%1,%2,%3}, [%4];" \
                 : "=r"(r0), "=r"(r1), "=r"(r2), "=r"(r3) : "r"(ad))

__device__ __forceinline__ void mma_bf16(float* c, const uint32_t* a, const uint32_t* b) {
    asm volatile("mma.sync.aligned.m16n8k16.row.col.f32.bf16.bf16.f32 "
        "{%0,%1,%2,%3}, {%4,%5,%6,%7}, {%8,%9}, {%0,%1,%2,%3};"
        : "+f"(c[0]), "+f"(c[1]), "+f"(c[2]), "+f"(c[3])
        : "r"(a[0]), "r"(a[1]), "r"(a[2]), "r"(a[3]), "r"(b[0]), "r"(b[1]));
}

// ============================================================================
// prep_split: one kernel, three roles by block range.
//   [0, 16384)        : x -> g_Xh/g_Xl          ([m][k] bf16 hi/lo)
//   [16384, 17408)    : in_proj weight gather -> g_Wih/g_Wil ([n][k])
//   [17408, 18432)    : out_w transpose       -> g_Woh/g_Wol ([n][k])
// ============================================================================
__global__ __launch_bounds__(256) void prep_split(
    const float* __restrict__ x, const float* __restrict__ ipw,
    const float* __restrict__ ow)
{
    const int b   = blockIdx.x;
    const int tid = threadIdx.x;

    if (b < 16384) {
        size_t i = ((size_t)b * 256 + tid) * 4;
        float4 v = *(const float4*)&x[i];
        __nv_bfloat16 h[4], l[4];
        bf16_split(v.x, h[0], l[0]); bf16_split(v.y, h[1], l[1]);
        bf16_split(v.z, h[2], l[2]); bf16_split(v.w, h[3], l[3]);
        *(__nv_bfloat162*)&g_Xh[i]   = __nv_bfloat162(h[0], h[1]);
        *(__nv_bfloat162*)&g_Xh[i+2] = __nv_bfloat162(h[2], h[3]);
        *(__nv_bfloat162*)&g_Xl[i]   = __nv_bfloat162(l[0], l[1]);
        *(__nv_bfloat162*)&g_Xl[i+2] = __nv_bfloat162(l[2], l[3]);
        return;
    }

    if (b < 17408) {
        __shared__ float s[32][97];
        const int bid2 = b - 16384;
        const int c0 = (bid2 & 31) * 32;
        const int k0 = (bid2 >> 5) * 32;
        for (int idx = tid; idx < 32*96; idx += 256) {
            const int r = idx / 96, cc = idx % 96;
            s[r][cc] = ipw[(size_t)(k0 + r) * 3072 + 3*c0 + cc];
        }
        __syncthreads();
        const int dc = tid >> 3;
        const int kq = (tid & 7) * 4;
        const int c  = c0 + dc;
        __nv_bfloat16 vh[4], vl[4], xh[4], xl[4];
        #pragma unroll
        for (int u = 0; u < 4; u++) {
            bf16_split(s[kq+u][3*dc],     vh[u], vl[u]);
            bf16_split(s[kq+u][3*dc + 2], xh[u], xl[u]);
        }
        const size_t ov = (size_t)c * 1024 + k0 + kq;
        const size_t ox = (size_t)(1024 + c) * 1024 + k0 + kq;
        *(__nv_bfloat162*)&g_Wih[ov]   = __nv_bfloat162(vh[0], vh[1]);
        *(__nv_bfloat162*)&g_Wih[ov+2] = __nv_bfloat162(vh[2], vh[3]);
        *(__nv_bfloat162*)&g_Wil[ov]   = __nv_bfloat162(vl[0], vl[1]);
        *(__nv_bfloat162*)&g_Wil[ov+2] = __nv_bfloat162(vl[2], vl[3]);
        *(__nv_bfloat162*)&g_Wih[ox]   = __nv_bfloat162(xh[0], xh[1]);
        *(__nv_bfloat162*)&g_Wih[ox+2] = __nv_bfloat162(xh[2], xh[3]);
        *(__nv_bfloat162*)&g_Wil[ox]   = __nv_bfloat162(xl[0], xl[1]);
        *(__nv_bfloat162*)&g_Wil[ox+2] = __nv_bfloat162(xl[2], xl[3]);
        return;
    }

    {
        __shared__ float s[32][33];
        const int bid2 = b - 17408;
        const int c0 = (bid2 & 31) * 32;
        const int k0 = (bid2 >> 5) * 32;
        const int tx  = tid & 31;
        const int ty0 = tid >> 5;            // 0..7
        #pragma unroll
        for (int rr = 0; rr < 4; rr++) {
            const int r = ty0 + rr * 8;
            s[r][tx] = ow[(size_t)(k0 + r) * CH + c0 + tx];
        }
        __syncthreads();
        #pragma unroll
        for (int rr = 0; rr < 4; rr++) {
            const int ty = ty0 + rr * 8;
            __nv_bfloat16 h, l;
            bf16_split(s[tx][ty], h, l);
            g_Woh[(size_t)(c0 + ty) * 1024 + k0 + tx] = h;
            g_Wol[(size_t)(c0 + ty) * 1024 + k0 + tx] = l;
        }
    }
}

// ============================================================================
// bf16 mma.sync GEMM (single 64KB buffer, KC=64, 2 syncs).  Frozen mainloop.
// MODE 0: in_proj. A = g_Xh/l [m][k]. Epilogue transposes -> g_Vcm/g_X2t.
// MODE 1: out proj. A = g_Gh/l [k][m], ldmatrix.trans. Epilogue -> out.
// ============================================================================
#define GSM_BYTES 65536

template<int MODE>
__global__ __launch_bounds__(256, 2) void gemm_bf16_tc(
    const float* __restrict__ bias, float* __restrict__ out)
{
    extern __shared__ char dsm[];
    const uint32_t sb  = smem_u32(dsm);
    const uint32_t sAh = sb, sBh = sb + 32768;

    const int tid  = threadIdx.x;
    const int lane = tid & 31;
    const int wid  = tid >> 5;
    const int wm   = wid >> 1;
    const int wn   = wid & 1;
    const int m0   = blockIdx.y * 128;
    const int bx   = blockIdx.x;
    const int n0   = bx * 128;

    const __nv_bfloat16* Ah = (MODE == 0) ? g_Xh : g_Gh;
    const __nv_bfloat16* Al = (MODE == 0) ? g_Xl : g_Gl;
    const __nv_bfloat16* Bh = (MODE == 0) ? g_Wih : g_Woh;
    const __nv_bfloat16* Bl = (MODE == 0) ? g_Wil : g_Wol;

    float acc[2][8][4];
    #pragma unroll
    for (int i = 0; i < 2; i++)
        #pragma unroll
        for (int j = 0; j < 8; j++)
            #pragma unroll
            for (int q = 0; q < 4; q++) acc[i][j][q] = 0.f;

    for (int it = 0; it < 16; ++it) {
        const size_t kc0 = (size_t)it * 64;
        if (MODE == 0) {
            #pragma unroll
            for (int u = 0; u < 4; u++) {
                const int s = tid + u * 256;
                const int row = s >> 3, seg = s & 7;
                const uint32_t so = (uint32_t)(row * 128 + ((seg * 16) ^ ((row & 7) << 4)));
                const size_t ga = (size_t)(m0 + row) * 1024 + kc0 + seg * 8;
                const size_t gb = (size_t)(n0 + row) * 1024 + kc0 + seg * 8;
                CP_ASYNC16(sAh + so, Ah + ga);
                CP_ASYNC16(sAh + 16384 + so, Al + ga);
                CP_ASYNC16(sBh + so, Bh + gb);
                CP_ASYNC16(sBh + 16384 + so, Bl + gb);
            }
        } else {
            #pragma unroll
            for (int u = 0; u < 4; u++) {
                const int s = tid + u * 256;
                const int row = s >> 4, seg = s & 15;
                const uint32_t so = (uint32_t)(row * 256 + ((seg * 16) ^ ((row & 7) << 4)));
                const size_t ga = (size_t)(kc0 + row) * MTOT + m0 + seg * 8;
                CP_ASYNC16(sAh + so, Ah + ga);
                CP_ASYNC16(sAh + 16384 + so, Al + ga);
            }
            #pragma unroll
            for (int u = 0; u < 4; u++) {
                const int s = tid + u * 256;
                const int row = s >> 3, seg = s & 7;
                const uint32_t so = (uint32_t)(row * 128 + ((seg * 16) ^ ((row & 7) << 4)));
                const size_t gb = (size_t)(n0 + row) * 1024 + kc0 + seg * 8;
                CP_ASYNC16(sBh + so, Bh + gb);
                CP_ASYNC16(sBh + 16384 + so, Bl + gb);
            }
        }
        CP_COMMIT();
        CP_WAIT0();
        __syncthreads();

        #pragma unroll
        for (int ks = 0; ks < 4; ks++) {
            uint32_t ah[2][4], al[2][4];
            #pragma unroll
            for (int mt = 0; mt < 2; mt++) {
                if (MODE == 0) {
                    const int row = wm * 32 + mt * 16 + (lane & 15);
                    const uint32_t r4 = (row & 7) << 4;
                    const uint32_t cb = (uint32_t)(ks * 32 + ((lane >> 4) << 4));
                    const uint32_t ad = sAh + row * 128 + (cb ^ r4);
                    LDSM4(ah[mt][0], ah[mt][1], ah[mt][2], ah[mt][3], ad);
                    LDSM4(al[mt][0], al[mt][1], al[mt][2], al[mt][3], ad + 16384);
                } else {
                    const int rowk = ks * 16 + (lane & 7) + ((lane >> 4) << 3);
                    const int mcol = wm * 32 + mt * 16 + (((lane >> 3) & 1) << 3);
                    const uint32_t ad = sAh + rowk * 256 +
                        (((uint32_t)(2 * mcol)) ^ ((uint32_t)(rowk & 7) << 4));
                    LDSM4T(ah[mt][0], ah[mt][1], ah[mt][2], ah[mt][3], ad);
                    LDSM4T(al[mt][0], al[mt][1], al[mt][2], al[mt][3], ad + 16384);
                }
            }
            uint32_t bh[8][2], bl[8][2];
            #pragma unroll
            for (int nt2 = 0; nt2 < 4; nt2++) {
                const int n = wn * 64 + nt2 * 16 + (lane & 7) + ((lane >> 4) << 3);
                const uint32_t r4 = (n & 7) << 4;
                const uint32_t cb = (uint32_t)(ks * 32 + (((lane >> 3) & 1) << 4));
                const uint32_t ad = sBh + n * 128 + (cb ^ r4);
                LDSM4(bh[2*nt2][0], bh[2*nt2][1], bh[2*nt2+1][0], bh[2*nt2+1][1], ad);
                LDSM4(bl[2*nt2][0], bl[2*nt2][1], bl[2*nt2+1][0], bl[2*nt2+1][1], ad + 16384);
            }
            #pragma unroll
            for (int mt = 0; mt < 2; mt++)
                #pragma unroll
                for (int nt = 0; nt < 8; nt++) {
                    mma_bf16(acc[mt][nt], ah[mt], bh[nt]);
                    mma_bf16(acc[mt][nt], ah[mt], bl[nt]);
                    mma_bf16(acc[mt][nt], al[mt], bh[nt]);
                }
        }
        __syncthreads();
    }

    if (MODE == 0) {
        float* stage = (float*)dsm;          // [128][65] floats = 33 KB
        const bool is_v = (bx < 8);
        const int cbase = (is_v ? bx : bx - 8) * 128;
        #pragma unroll
        for (int h = 0; h < 2; h++) {
            __syncthreads();
            if (wn == h) {
                #pragma unroll
                for (int mt = 0; mt < 2; mt++) {
                    const int rl = wm * 32 + mt * 16 + (lane >> 2);
                    #pragma unroll
                    for (int nt = 0; nt < 8; nt++) {
                        const int cl = nt * 8 + ((lane & 3) << 1);
                        stage[rl * 65 + cl]           = acc[mt][nt][0];
                        stage[rl * 65 + cl + 1]       = acc[mt][nt][1];
                        stage[(rl + 8) * 65 + cl]     = acc[mt][nt][2];
                        stage[(rl + 8) * 65 + cl + 1] = acc[mt][nt][3];
                    }
                }
            }
            __syncthreads();
            const int cl  = tid >> 2;
            const int mch = (tid & 3) << 5;
            const int c   = cbase + h * 64 + cl;
            const float b = is_v ? bias[3*c] : bias[3*c + 2];
            float* dst = (is_v ? g_Vcm : g_X2t) + (size_t)c * MTOT + m0 + mch;
            #pragma unroll
            for (int j = 0; j < 32; j += 4) {
                float4 o = make_float4(stage[(mch+j)*65   + cl] + b,
                                       stage[(mch+j+1)*65 + cl] + b,
                                       stage[(mch+j+2)*65 + cl] + b,
                                       stage[(mch+j+3)*65 + cl] + b);
                *(float4*)&dst[j] = o;
            }
        }
    } else {
        #pragma unroll
        for (int mt = 0; mt < 2; mt++) {
            const int r = m0 + wm * 32 + mt * 16 + (lane >> 2);
            #pragma unroll
            for (int nt = 0; nt < 8; nt++) {
                const int c = n0 + wn * 64 + nt * 8 + ((lane & 3) << 1);
                const float b0 = bias[c], b1 = bias[c + 1];
                *(float2*)&out[(size_t)r * CH + c] =
                    make_float2(acc[mt][nt][0] + b0, acc[mt][nt][1] + b1);
                *(float2*)&out[(size_t)(r + 8) * CH + c] =
                    make_float2(acc[mt][nt][2] + b0, acc[mt][nt][3] + b1);
            }
        }
    }
}

// ============================================================================
// Filter MLP (R11 version — computed ONCE into g_H2)
// ============================================================================
__global__ void filter_h2(const float* __restrict__ fw1, const float* __restrict__ fb1,
                          const float* __restrict__ fw2, const float* __restrict__ fb2)
{
    __shared__ float h1[64];
    const int l = blockIdx.x;
    const int t = threadIdx.x;
    const float pos = (float)l / (float)(LSEQ - 1);
    if (t < 64) h1[t] = gelu_exact(pos * fw1[t] + fb1[t]);
    __syncthreads();
    float s = fb2[t];
    #pragma unroll 8
    for (int j = 0; j < 64; j++) s += h1[j] * fw2[j*128 + t];
    g_H2[(size_t)l*128 + t] = gelu_exact(s);
}

// ============================================================================
// GEMM coef (R11 version): COEFt[c][l] = (h2 @ fw3[:,2c+1] + fb3[2c+1]),
// transposed epilogue.
// ============================================================================
__global__ __launch_bounds__(256) void gemm_coef(
    const float* __restrict__ fw3, const float* __restrict__ fb3)
{
    __shared__ float As[8][128];
    __shared__ float Bs[8][128];
    __shared__ float stage[128 * 65];     // 33 KB transpose stage
    const int tid = threadIdx.x;
    const int tx = tid & 15, ty = tid >> 4;
    const int m0 = blockIdx.y * 128;
    const int n0 = blockIdx.x * 128;

    float acc[8][8];
    #pragma unroll
    for (int i = 0; i < 8; i++)
        #pragma unroll
        for (int j = 0; j < 8; j++) acc[i][j] = 0.f;

    const int arow = tid >> 1, akq = (tid & 1) * 4;
    const int bn = tid & 127;
    const int jm = 2 * (n0 + bn) + 1;
    const int kk0 = (tid >> 7) * 4;

    for (int k0 = 0; k0 < 128; k0 += 8) {
        float4 av = *(const float4*)&g_H2[(size_t)(m0 + arow) * 128 + k0 + akq];
        As[akq+0][arow] = av.x; As[akq+1][arow] = av.y;
        As[akq+2][arow] = av.z; As[akq+3][arow] = av.w;
        #pragma unroll
        for (int r = 0; r < 4; r++)
            Bs[kk0 + r][bn] = fw3[(size_t)(k0 + kk0 + r) * 2048 + jm];
        __syncthreads();
        #pragma unroll
        for (int kk = 0; kk < 8; kk++) {
            float a[8], b[8];
            #pragma unroll
            for (int i = 0; i < 8; i++) a[i] = As[kk][ty*8 + i];
            #pragma unroll
            for (int j = 0; j < 8; j++) b[j] = Bs[kk][tx*8 + j];
            #pragma unroll
            for (int i = 0; i < 8; i++)
                #pragma unroll
                for (int j = 0; j < 8; j++) acc[i][j] += a[i] * b[j];
        }
        __syncthreads();
    }

    float bo[8];
    #pragma unroll
    for (int j = 0; j < 8; j++) bo[j] = fb3[2*(n0 + tx*8 + j) + 1];

    // transposed epilogue: stage 128l x 64c half-tiles, write [c][l] coalesced
    #pragma unroll
    for (int h = 0; h < 2; h++) {
        __syncthreads();
        if ((tx >> 3) == h) {
            #pragma unroll
            for (int i = 0; i < 8; i++)
                #pragma unroll
                for (int j = 0; j < 8; j++)
                    stage[(ty*8 + i) * 65 + (tx & 7) * 8 + j] = acc[i][j] + bo[j];
        }
        __syncthreads();
        const int cl  = tid >> 2;            // 0..63
        const int lch = (tid & 3) << 5;      // 0,32,64,96
        const int c   = n0 + h * 64 + cl;
        float* dst = g_COEFt + (size_t)c * LSEQ + m0 + lch;
        #pragma unroll
        for (int j = 0; j < 32; j += 4) {
            float4 o = make_float4(stage[(lch+j)*65   + cl],
                                   stage[(lch+j+1)*65 + cl],
                                   stage[(lch+j+2)*65 + cl],
                                   stage[(lch+j+3)*65 + cl]);
            *(float4*)&dst[j] = o;
        }
    }
}

// ============================================================================
// FFT convolution — radix-16 passes, padded smem, smem Hermitian half-
// spectrum; filter stash fused into the filter FFT's final pass. (unchanged)
// ============================================================================
#define FFT_T    512
#define ZI(i) ((i) + ((i) >> 4))
#define Z_PAD_SZ  17408                 // float2
#define HS_PAD_SZ 8232                  // float2
#define COS_SZ    4104                  // floats
#define HsI(k) ((k) + ((k) >> 8))
#define FFT_SMEM ((Z_PAD_SZ + HS_PAD_SZ) * 8 + COS_SZ * 4)

__device__ __forceinline__ int digrev4_14(int j) {
    unsigned r = __brev((unsigned)j) >> 18;
    return (int)(((r & 0x2AAAu) >> 1) | ((r & 0x1555u) << 1));
}
__device__ __forceinline__ int digrev4_10(int g) {
    unsigned r = __brev((unsigned)g) >> 22;
    return (int)(((r & 0x155u) << 1) | ((r >> 1) & 0x155u));
}
__device__ __forceinline__ float2 twc(const float* __restrict__ C, int k) {
    return make_float2(C[k], -C[4096 - k]);
}
__device__ __forceinline__ float conv3(const float* __restrict__ q, int l,
                                       float w0, float w1, float w2, float b) {
    float s = w1 * q[l] + b;
    if (l > 0)        s += w0 * q[l-1];
    if (l < LSEQ - 1) s += w2 * q[l+1];
    return s;
}

__device__ void fft_dif_first(float2* Z, const float* C,
                              const float* __restrict__ re, int tid) {
    for (int p = tid; p < 4096; p += FFT_T) {
        float2 a = make_float2(re[p], 0.f);
        float2 b = make_float2(re[p + 4096], 0.f);
        float2 w1 = twc(C, p);
        float2 w2 = cmulf(w1, w1);
        float2 w3 = cmulf(w2, w1);
        Z[ZI(p)]         = caddf(a, b);
        Z[ZI(p + 4096)]  = cmulf(make_float2(a.x + b.y, a.y - b.x), w1);
        Z[ZI(p + 8192)]  = cmulf(csubf(a, b),                       w2);
        Z[ZI(p + 12288)] = cmulf(make_float2(a.x - b.y, a.y + b.x), w3);
    }
    __syncthreads();
}

__device__ void fft_dif_first_conv(float2* Z, const float* C,
                                   const float* __restrict__ v0,
                                   float w0, float w1, float w2, float cb, int tid) {
    const float* v1 = v0 + LSEQ;
    for (int p = tid; p < 4096; p += FFT_T) {
        float2 a = make_float2(conv3(v0, p, w0, w1, w2, cb),
                               conv3(v1, p, w0, w1, w2, cb));
        float2 b = make_float2(conv3(v0, p + 4096, w0, w1, w2, cb),
                               conv3(v1, p + 4096, w0, w1, w2, cb));
        float2 t1 = twc(C, p);
        float2 t2 = cmulf(t1, t1);
        float2 t3 = cmulf(t2, t1);
        Z[ZI(p)]         = caddf(a, b);
        Z[ZI(p + 4096)]  = cmulf(make_float2(a.x + b.y, a.y - b.x), t1);
        Z[ZI(p + 8192)]  = cmulf(csubf(a, b),                       t2);
        Z[ZI(p + 12288)] = cmulf(make_float2(a.x - b.y, a.y + b.x), t3);
    }
    __syncthreads();
}

template<int LA, int TWA>
__device__ void fft_dif_pass16(float2* Z, const float* C, int tid) {
    constexpr int qA = LA / 4, qB = LA / 16;
    constexpr int TWB = TWA + 2;
    const int p2 = tid & (qB - 1);
    float2 wA1[4], wA2[4], wA3[4];
    #pragma unroll
    for (int a = 0; a < 4; a++) {
        const int k = (p2 + a*qB) << TWA;
        wA1[a] = twc(C, k);
        wA2[a] = cmulf(wA1[a], wA1[a]);
        wA3[a] = cmulf(wA2[a], wA1[a]);
    }
    const int k2 = p2 << TWB;
    const float2 wB1 = twc(C, k2);
    const float2 wB2 = cmulf(wB1, wB1);
    const float2 wB3 = cmulf(wB2, wB1);
    #pragma unroll
    for (int half = 0; half < 2; half++) {
        const int g = tid + half * FFT_T;
        const int base = (g / qB) * LA + p2;
        float2 x[4][4];
        #pragma unroll
        for (int b = 0; b < 4; b++)
            #pragma unroll
            for (int a = 0; a < 4; a++)
                x[b][a] = Z[ZI(base + a*qB + b*qA)];
        #pragma unroll
        for (int a = 0; a < 4; a++) {
            float2 t0 = caddf(x[0][a], x[2][a]);
            float2 t1 = csubf(x[0][a], x[2][a]);
            float2 t2 = caddf(x[1][a], x[3][a]);
            float2 bd = csubf(x[1][a], x[3][a]);
            float2 t3 = make_float2(bd.y, -bd.x);
            x[0][a] = caddf(t0, t2);
            x[1][a] = cmulf(caddf(t1, t3), wA1[a]);
            x[2][a] = cmulf(csubf(t0, t2), wA2[a]);
            x[3][a] = cmulf(csubf(t1, t3), wA3[a]);
        }
        #pragma unroll
        for (int b = 0; b < 4; b++) {
            float2 t0 = caddf(x[b][0], x[b][2]);
            float2 t1 = csubf(x[b][0], x[b][2]);
            float2 t2 = caddf(x[b][1], x[b][3]);
            float2 bd = csubf(x[b][1], x[b][3]);
            float2 t3 = make_float2(bd.y, -bd.x);
            Z[ZI(base + 0*qB + b*qA)] = caddf(t0, t2);
            Z[ZI(base + 1*qB + b*qA)] = cmulf(caddf(t1, t3), wB1);
            Z[ZI(base + 2*qB + b*qA)] = cmulf(csubf(t0, t2), wB2);
            Z[ZI(base + 3*qB + b*qA)] = cmulf(csubf(t1, t3), wB3);
        }
    }
    __syncthreads();
}

__device__ void fft_dif_pass16_stash(float2* Z, const float* C,
                                     float2* __restrict__ Hs, int tid) {
    float2 wA1[4], wA2[4], wA3[4];
    #pragma unroll
    for (int a = 0; a < 4; a++) {
        const int k = a << 10;
        wA1[a] = twc(C, k);
        wA2[a] = cmulf(wA1[a], wA1[a]);
        wA3[a] = cmulf(wA2[a], wA1[a]);
    }
    #pragma unroll
    for (int half = 0; half < 2; half++) {
        const int g = tid + half * FFT_T;
        const int base = g * 16;
        const int kg = digrev4_10(g);
        float2 x[4][4];
        #pragma unroll
        for (int b = 0; b < 4; b++)
            #pragma unroll
            for (int a = 0; a < 4; a++)
                x[b][a] = Z[ZI(base + a + 4*b)];
        #pragma unroll
        for (int a = 0; a < 4; a++) {
            float2 t0 = caddf(x[0][a], x[2][a]);
            float2 t1 = csubf(x[0][a], x[2][a]);
            float2 t2 = caddf(x[1][a], x[3][a]);
            float2 bd = csubf(x[1][a], x[3][a]);
            float2 t3 = make_float2(bd.y, -bd.x);
            x[0][a] = caddf(t0, t2);
            x[1][a] = cmulf(caddf(t1, t3), wA1[a]);
            x[2][a] = cmulf(csubf(t0, t2), wA2[a]);
            x[3][a] = cmulf(csubf(t1, t3), wA3[a]);
        }
        #pragma unroll
        for (int b = 0; b < 4; b++) {
            float2 t0 = caddf(x[b][0], x[b][2]);
            float2 t1 = csubf(x[b][0], x[b][2]);
            float2 t2 = caddf(x[b][1], x[b][3]);
            float2 bd = csubf(x[b][1], x[b][3]);
            float2 t3 = make_float2(bd.y, -bd.x);
            const int k0 = kg + b * 1024;
            Hs[HsI(k0)]        = caddf(t0, t2);      // o=0
            Hs[HsI(k0 + 4096)] = caddf(t1, t3);      // o=1
            if (k0 == 0) Hs[HsI(8192)] = csubf(t0, t2);  // k=8192 edge
        }
    }
    __syncthreads();
}

__device__ void ifft_first_mult(float2* Z, const float2* __restrict__ Hs, int tid) {
    for (int b = tid; b < NFFT/4; b += FFT_T) {
        const int i0 = 4*b;
        const int kb = digrev4_14(i0);
        float2 zz[4];
        #pragma unroll
        for (int s2 = 0; s2 < 4; s2++) {
            const int k = kb + s2 * 4096;
            float2 H;
            if (k <= 8192) H = Hs[HsI(k)];
            else { const int kc = 16384 - k; H = Hs[HsI(kc)]; H.y = -H.y; }
            zz[s2] = cmulf(Z[ZI(i0 + s2)], H);
        }
        float2 t0 = caddf(zz[0], zz[2]), t1 = csubf(zz[0], zz[2]);
        float2 t2 = caddf(zz[1], zz[3]);
        float2 bd = csubf(zz[1], zz[3]);
        float2 t3 = make_float2(-bd.y, bd.x);
        Z[ZI(i0)]     = caddf(t0, t2);
        Z[ZI(i0 + 1)] = caddf(t1, t3);
        Z[ZI(i0 + 2)] = csubf(t0, t2);
        Z[ZI(i0 + 3)] = csubf(t1, t3);
    }
    __syncthreads();
}

template<int L1, int TW1>
__device__ void ifft_dit_pass16(float2* Z, const float* C, int tid) {
    constexpr int q1 = L1 / 4, L2 = 4 * L1;
    constexpr int TW2 = TW1 - 2;
    const int p = tid & (q1 - 1);
    const int k1 = p << TW1;
    const float2 u1 = twc(C, k1);
    const float2 u2 = cmulf(u1, u1);
    const float2 u3 = cmulf(u2, u1);
    float2 v1[4], v2[4], v3[4];
    #pragma unroll
    for (int a = 0; a < 4; a++) {
        const int kk = (p + a*q1) << TW2;
        v1[a] = twc(C, kk);
        v2[a] = cmulf(v1[a], v1[a]);
        v3[a] = cmulf(v2[a], v1[a]);
    }
    #pragma unroll
    for (int half = 0; half < 2; half++) {
        const int g = tid + half * FFT_T;
        const int base = (g / q1) * L2 + p;
        float2 x[4][4];
        #pragma unroll
        for (int b = 0; b < 4; b++)
            #pragma unroll
            for (int a = 0; a < 4; a++)
                x[b][a] = Z[ZI(base + a*q1 + b*L1)];
        #pragma unroll
        for (int b = 0; b < 4; b++) {
            float2 a0 = x[b][0];
            float2 a1 = cmulconjf(x[b][1], u1);
            float2 a2 = cmulconjf(x[b][2], u2);
            float2 a3 = cmulconjf(x[b][3], u3);
            float2 t0 = caddf(a0, a2), t1 = csubf(a0, a2);
            float2 t2 = caddf(a1, a3);
            float2 bd = csubf(a1, a3);
            float2 t3 = make_float2(-bd.y, bd.x);
            x[b][0] = caddf(t0, t2);
            x[b][1] = caddf(t1, t3);
            x[b][2] = csubf(t0, t2);
            x[b][3] = csubf(t1, t3);
        }
        #pragma unroll
        for (int a = 0; a < 4; a++) {
            float2 b0 = x[0][a];
            float2 b1 = cmulconjf(x[1][a], v1[a]);
            float2 b2 = cmulconjf(x[2][a], v2[a]);
            float2 b3 = cmulconjf(x[3][a], v3[a]);
            float2 t0 = caddf(b0, b2), t1 = csubf(b0, b2);
            float2 t2 = caddf(b1, b3);
            float2 bd = csubf(b1, b3);
            float2 t3 = make_float2(-bd.y, bd.x);
            Z[ZI(base + a*q1 + 0*L1)] = caddf(t0, t2);
            Z[ZI(base + a*q1 + 1*L1)] = caddf(t1, t3);
            Z[ZI(base + a*q1 + 2*L1)] = csubf(t0, t2);
            Z[ZI(base + a*q1 + 3*L1)] = csubf(t1, t3);
        }
    }
    __syncthreads();
}

__global__ __launch_bounds__(FFT_T, 1) void fft_conv_kernel(
    const float* __restrict__ sw, const float* __restrict__ sb)
{
    extern __shared__ float2 sm[];
    float2* Z  = sm;
    float2* Hs = sm + Z_PAD_SZ;
    float*  C  = (float*)(sm + Z_PAD_SZ + HS_PAD_SZ);
    const int c   = blockIdx.x;
    const int tid = threadIdx.x;

    for (int k = tid; k <= 4096; k += FFT_T)
        C[k] = cosf(3.834951969714103e-4f * (float)k);   // cos(2*pi*k/16384)
    __syncthreads();

    // ---- filter FFT; final pass writes half-spectrum straight to smem Hs ----
    fft_dif_first(Z, C, g_COEFt + (size_t)c * LSEQ, tid);
    fft_dif_pass16<4096, 2>(Z, C, tid);
    fft_dif_pass16<256, 6>(Z, C, tid);
    fft_dif_pass16_stash(Z, C, Hs, tid);

    // ---- v FFT with fused depthwise short-conv ----
    const float w0 = sw[c*3], w1 = sw[c*3+1], w2 = sw[c*3+2], cb = sb[c];
    fft_dif_first_conv(Z, C, g_Vcm + (size_t)c * MTOT, w0, w1, w2, cb, tid);
    fft_dif_pass16<4096, 2>(Z, C, tid);
    fft_dif_pass16<256, 6>(Z, C, tid);
    fft_dif_pass16<16, 10>(Z, C, tid);

    // ---- inverse: multiply (from smem half-spectrum) fused into len-4 stage
    ifft_first_mult(Z, Hs, tid);
    ifft_dit_pass16<16, 10>(Z, C, tid);
    ifft_dit_pass16<256, 6>(Z, C, tid);

    // ---- final paired pass fused with gate + bf16 hi/lo store ([c][m]) ----
    const float* x2 = g_X2t + (size_t)c * MTOT;
    __nv_bfloat16* goh = g_Gh + (size_t)c * MTOT;
    __nv_bfloat16* gol = g_Gl + (size_t)c * MTOT;
    const float scale = 1.0f / (float)NFFT;
    for (int p = tid; p < 1024; p += FFT_T) {
        float2 x[4][4];
        #pragma unroll
        for (int b = 0; b < 4; b++)
            #pragma unroll
            for (int a = 0; a < 4; a++)
                x[b][a] = Z[ZI(p + a*1024 + b*4096)];
        const float2 u1 = twc(C, p << 2);
        const float2 u2 = cmulf(u1, u1);
        const float2 u3 = cmulf(u2, u1);
        #pragma unroll
        for (int b = 0; b < 4; b++) {
            float2 a0 = x[b][0];
            float2 a1 = cmulconjf(x[b][1], u1);
            float2 a2 = cmulconjf(x[b][2], u2);
            float2 a3 = cmulconjf(x[b][3], u3);
            float2 t0 = caddf(a0, a2), t1 = csubf(a0, a2);
            float2 t2 = caddf(a1, a3);
            float2 bd = csubf(a1, a3);
            float2 t3 = make_float2(-bd.y, bd.x);
            x[b][0] = caddf(t0, t2);
            x[b][1] = caddf(t1, t3);
            x[b][2] = csubf(t0, t2);
            x[b][3] = csubf(t1, t3);
        }
        #pragma unroll
        for (int a = 0; a < 4; a++) {
            const int k2 = p + a*1024;
            const float2 q1 = twc(C, k2);
            const float2 q2 = cmulf(q1, q1);
            const float2 q3 = cmulf(q2, q1);
            float2 b0 = x[0][a];
            float2 b1 = cmulconjf(x[1][a], q1);
            float2 b2 = cmulconjf(x[2][a], q2);
            float2 b3 = cmulconjf(x[3][a], q3);
            float2 t0 = caddf(b0, b2), t1 = csubf(b0, b2);
            float2 t2 = caddf(b1, b3);
            float2 bd = csubf(b1, b3);
            float2 t3 = make_float2(-bd.y, bd.x);
            float2 o0 = caddf(t0, t2);         // time t
            float2 o1 = caddf(t1, t3);         // time t+4096
            const int t = p + a*1024;
            float gv;
            __nv_bfloat16 hh, ll;
            gv = x2[t]               * (o0.x * scale); bf16_split(gv, hh, ll);
            goh[t] = hh;               gol[t] = ll;
            gv = x2[LSEQ + t]        * (o0.y * scale); bf16_split(gv, hh, ll);
            goh[LSEQ + t] = hh;        gol[LSEQ + t] = ll;
            gv = x2[t + 4096]        * (o1.x * scale); bf16_split(gv, hh, ll);
            goh[t + 4096] = hh;        gol[t + 4096] = ll;
            gv = x2[LSEQ + t + 4096] * (o1.y * scale); bf16_split(gv, hh, ll);
            goh[LSEQ + t + 4096] = hh; gol[LSEQ + t + 4096] = ll;
        }
    }
}

// ============================================================================
extern "C" void kernel_launch(void* const* d_in, const int* in_sizes, int n_in,
                              void* d_out, int out_size)
{
    const float* x   = (const float*)d_in[0];
    const float* ipw = (const float*)d_in[1];
    const float* ipb = (const float*)d_in[2];
    const float* sw  = (const float*)d_in[3];
    const float* sb  = (const float*)d_in[4];
    const float* fw1 = (const float*)d_in[5];
    const float* fb1 = (const float*)d_in[6];
    const float* fw2 = (const float*)d_in[7];
    const float* fb2 = (const float*)d_in[8];
    const float* fw3 = (const float*)d_in[9];
    const float* fb3 = (const float*)d_in[10];
    const float* ow  = (const float*)d_in[11];
    const float* ob  = (const float*)d_in[12];
    float* out = (float*)d_out;

    cudaFuncSetAttribute(fft_conv_kernel,
                         cudaFuncAttributeMaxDynamicSharedMemorySize, FFT_SMEM);
    cudaFuncSetAttribute(gemm_bf16_tc<0>,
                         cudaFuncAttributeMaxDynamicSharedMemorySize, GSM_BYTES);
    cudaFuncSetAttribute(gemm_bf16_tc<1>,
                         cudaFuncAttributeMaxDynamicSharedMemorySize, GSM_BYTES);

    // 1) one prep kernel: x split + in_proj gather + out_w transpose
    prep_split<<<18432, 256>>>(x, ipw, ow);
    // 2) in_proj GEMM; epilogue writes v/x2 directly in channel-major
    gemm_bf16_tc<0><<<dim3(16, 128), 256, GSM_BYTES>>>(ipb, nullptr);
    // 3) filter MLP (once) + coef GEMM (transposed epilogue -> COEFt)
    filter_h2<<<LSEQ, 128>>>(fw1, fb1, fw2, fb2);
    gemm_coef<<<dim3(8, 64), 256>>>(fw3, fb3);
    // 4) FFT long conv (fused short-conv, stash, mult, gate, bf16 split out)
    fft_conv_kernel<<<CH, FFT_T, FFT_SMEM>>>(sw, sb);
    // 5) out GEMM reads gated activations k-major via ldmatrix.trans
    gemm_bf16_tc<1><<<dim3(8, 128), 256, GSM_BYTES>>>(ob, out);
}

// round 14
// speedup vs baseline: 1.5616x; 1.0151x over previous
#include <cuda_runtime.h>
#include <cuda_bf16.h>
#include <math.h>
#include <stdint.h>

// Problem constants
#define LSEQ   8192
#define NFFT   16384
#define CH     1024
#define BATCH  2
#define MTOT   (BATCH*LSEQ)      // 16384 rows

// ---------------- scratch (device globals; no allocations allowed) ----------
__device__ float g_Vcm  [CH*MTOT];     // in_proj v branch, channel-major [c][m]
__device__ float g_X2t  [CH*MTOT];     // x2 branch, channel-major [c][m]
__device__ float g_H2   [LSEQ*128];    // filter MLP hidden (L x 128)
__device__ float g_COEFt[CH*LSEQ];     // filter coefs order-1, channel-major [c][l]

// bf16 split operands for the tensor-core GEMMs
__device__ __nv_bfloat16 g_Xh [MTOT*CH], g_Xl [MTOT*CH];     // x, [m][k]
__device__ __nv_bfloat16 g_Gh [CH*MTOT], g_Gl [CH*MTOT];     // gated, [c][m] (k-major)
__device__ __nv_bfloat16 g_Wih[2048*CH], g_Wil[2048*CH];     // in_proj cols, [n][k]
__device__ __nv_bfloat16 g_Woh[CH*CH],   g_Wol[CH*CH];       // out_w^T, [n][k]

// ---------------- generic helpers -------------------------------------------
__device__ __forceinline__ float gelu_exact(float x) {
    return 0.5f * x * (1.0f + erff(x * 0.70710678118654752f));
}
__device__ __forceinline__ float2 cmulf(float2 a, float2 b) {
    return make_float2(a.x*b.x - a.y*b.y, a.x*b.y + a.y*b.x);
}
__device__ __forceinline__ float2 cmulconjf(float2 a, float2 w) {  // a * conj(w)
    return make_float2(a.x*w.x + a.y*w.y, a.y*w.x - a.x*w.y);
}
__device__ __forceinline__ float2 caddf(float2 a, float2 b) {
    return make_float2(a.x + b.x, a.y + b.y);
}
__device__ __forceinline__ float2 csubf(float2 a, float2 b) {
    return make_float2(a.x - b.x, a.y - b.y);
}
__device__ __forceinline__ void bf16_split(float v, __nv_bfloat16 &h, __nv_bfloat16 &l) {
    h = __float2bfloat16(v);
    l = __float2bfloat16(v - __bfloat162float(h));
}
__device__ __forceinline__ uint32_t smem_u32(const void* p) {
    uint32_t a;
    asm("{ .reg .u64 t; cvta.to.shared.u64 t, %1; cvt.u32.u64 %0, t; }"
        : "=r"(a) : "l"(p));
    return a;
}

#define CP_ASYNC16(sm, gp) \
    asm volatile("cp.async.cg.shared.global [%0], [%1], 16;" \
                 :: "r"(sm), "l"(__cvta_generic_to_global(gp)) : "memory")
#define CP_COMMIT() asm volatile("cp.async.commit_group;" ::: "memory")
#define CP_WAIT0()  asm volatile("cp.async.wait_group 0;" ::: "memory")

#define LDSM4(r0, r1, r2, r3, ad) \
    asm volatile("ldmatrix.sync.aligned.m8n8.x4.shared.b16 {%0,%1,%2,%3}, [%4];" \
                 : "=r"(r0), "=r"(r1), "=r"(r2), "=r"(r3) : "r"(ad))
#define LDSM4T(r0, r1, r2, r3, ad) \
    asm volatile("ldmatrix.sync.aligned.m8n8.x4.trans.shared.b16 {%0,%1,%2,%3}, [%4];" \
                 : "=r"(r0), "=r"(r1), "=r"(r2), "=r"(r3) : "r"(ad))

__device__ __forceinline__ void mma_bf16(float* c, const uint32_t* a, const uint32_t* b) {
    asm volatile("mma.sync.aligned.m16n8k16.row.col.f32.bf16.bf16.f32 "
        "{%0,%1,%2,%3}, {%4,%5,%6,%7}, {%8,%9}, {%0,%1,%2,%3};"
        : "+f"(c[0]), "+f"(c[1]), "+f"(c[2]), "+f"(c[3])
        : "r"(a[0]), "r"(a[1]), "r"(a[2]), "r"(a[3]), "r"(b[0]), "r"(b[1]));
}

// ============================================================================
// prep_split: one kernel, four roles by block range.
//   [0, 16384)        : x -> g_Xh/g_Xl          ([m][k] bf16 hi/lo)
//   [16384, 17408)    : in_proj weight gather -> g_Wih/g_Wil ([n][k])
//   [17408, 18432)    : out_w transpose       -> g_Woh/g_Wol ([n][k])
//   [18432, 22528)    : filter MLP h2 (2 rows per CTA) -> g_H2
// ============================================================================
__global__ __launch_bounds__(256) void prep_split(
    const float* __restrict__ x, const float* __restrict__ ipw,
    const float* __restrict__ ow,
    const float* __restrict__ fw1, const float* __restrict__ fb1,
    const float* __restrict__ fw2, const float* __restrict__ fb2)
{
    const int b   = blockIdx.x;
    const int tid = threadIdx.x;

    if (b < 16384) {
        size_t i = ((size_t)b * 256 + tid) * 4;
        float4 v = *(const float4*)&x[i];
        __nv_bfloat16 h[4], l[4];
        bf16_split(v.x, h[0], l[0]); bf16_split(v.y, h[1], l[1]);
        bf16_split(v.z, h[2], l[2]); bf16_split(v.w, h[3], l[3]);
        *(__nv_bfloat162*)&g_Xh[i]   = __nv_bfloat162(h[0], h[1]);
        *(__nv_bfloat162*)&g_Xh[i+2] = __nv_bfloat162(h[2], h[3]);
        *(__nv_bfloat162*)&g_Xl[i]   = __nv_bfloat162(l[0], l[1]);
        *(__nv_bfloat162*)&g_Xl[i+2] = __nv_bfloat162(l[2], l[3]);
        return;
    }

    if (b < 17408) {
        __shared__ float s[32][97];
        const int bid2 = b - 16384;
        const int c0 = (bid2 & 31) * 32;
        const int k0 = (bid2 >> 5) * 32;
        for (int idx = tid; idx < 32*96; idx += 256) {
            const int r = idx / 96, cc = idx % 96;
            s[r][cc] = ipw[(size_t)(k0 + r) * 3072 + 3*c0 + cc];
        }
        __syncthreads();
        const int dc = tid >> 3;
        const int kq = (tid & 7) * 4;
        const int c  = c0 + dc;
        __nv_bfloat16 vh[4], vl[4], xh[4], xl[4];
        #pragma unroll
        for (int u = 0; u < 4; u++) {
            bf16_split(s[kq+u][3*dc],     vh[u], vl[u]);
            bf16_split(s[kq+u][3*dc + 2], xh[u], xl[u]);
        }
        const size_t ov = (size_t)c * 1024 + k0 + kq;
        const size_t ox = (size_t)(1024 + c) * 1024 + k0 + kq;
        *(__nv_bfloat162*)&g_Wih[ov]   = __nv_bfloat162(vh[0], vh[1]);
        *(__nv_bfloat162*)&g_Wih[ov+2] = __nv_bfloat162(vh[2], vh[3]);
        *(__nv_bfloat162*)&g_Wil[ov]   = __nv_bfloat162(vl[0], vl[1]);
        *(__nv_bfloat162*)&g_Wil[ov+2] = __nv_bfloat162(vl[2], vl[3]);
        *(__nv_bfloat162*)&g_Wih[ox]   = __nv_bfloat162(xh[0], xh[1]);
        *(__nv_bfloat162*)&g_Wih[ox+2] = __nv_bfloat162(xh[2], xh[3]);
        *(__nv_bfloat162*)&g_Wil[ox]   = __nv_bfloat162(xl[0], xl[1]);
        *(__nv_bfloat162*)&g_Wil[ox+2] = __nv_bfloat162(xl[2], xl[3]);
        return;
    }

    if (b < 18432) {
        __shared__ float s[32][33];
        const int bid2 = b - 17408;
        const int c0 = (bid2 & 31) * 32;
        const int k0 = (bid2 >> 5) * 32;
        const int tx  = tid & 31;
        const int ty0 = tid >> 5;            // 0..7
        #pragma unroll
        for (int rr = 0; rr < 4; rr++) {
            const int r = ty0 + rr * 8;
            s[r][tx] = ow[(size_t)(k0 + r) * CH + c0 + tx];
        }
        __syncthreads();
        #pragma unroll
        for (int rr = 0; rr < 4; rr++) {
            const int ty = ty0 + rr * 8;
            __nv_bfloat16 h, l;
            bf16_split(s[tx][ty], h, l);
            g_Woh[(size_t)(c0 + ty) * 1024 + k0 + tx] = h;
            g_Wol[(size_t)(c0 + ty) * 1024 + k0 + tx] = l;
        }
        return;
    }

    {
        // filter MLP: 2 sequence positions per CTA
        __shared__ float h1s[2][64];
        const int lb  = (b - 18432) * 2;
        const int sub = tid >> 7;            // 0/1
        const int t   = tid & 127;
        const int l   = lb + sub;
        const float pos = (float)l / (float)(LSEQ - 1);
        if (t < 64) h1s[sub][t] = gelu_exact(pos * fw1[t] + fb1[t]);
        __syncthreads();
        float s = fb2[t];
        #pragma unroll 8
        for (int j = 0; j < 64; j++) s += h1s[sub][j] * fw2[j*128 + t];
        g_H2[(size_t)l*128 + t] = gelu_exact(s);
    }
}

// ============================================================================
// gemm0_coef: merged launch.
//   blocks [0, 512)      : coef GEMM tiles (COEFt transposed epilogue)
//   blocks [512, 2560)   : in_proj GEMM tiles (MODE-0 path, frozen)
// Coef CTAs are scheduled first so they drain alongside gemm0's long body.
// ============================================================================
#define GSM_BYTES 65536
#define NCOEF_B   512

__global__ __launch_bounds__(256, 2) void gemm0_coef(
    const float* __restrict__ bias,
    const float* __restrict__ fw3, const float* __restrict__ fb3)
{
    extern __shared__ char dsm[];
    const int tid = threadIdx.x;

    if (blockIdx.x < NCOEF_B) {
        // ---------------- coef GEMM (R13 body, smem carved from dsm) --------
        float* As    = (float*)dsm;               // [8][128]
        float* Bs    = As + 8*128;                // [8][128]
        float* stage = Bs + 8*128;                // [128*65]
        const int bid = blockIdx.x;
        const int tx = tid & 15, ty = tid >> 4;
        const int m0 = (bid >> 3) * 128;
        const int n0 = (bid & 7) * 128;

        float acc[8][8];
        #pragma unroll
        for (int i = 0; i < 8; i++)
            #pragma unroll
            for (int j = 0; j < 8; j++) acc[i][j] = 0.f;

        const int arow = tid >> 1, akq = (tid & 1) * 4;
        const int bn = tid & 127;
        const int jm = 2 * (n0 + bn) + 1;
        const int kk0 = (tid >> 7) * 4;

        for (int k0 = 0; k0 < 128; k0 += 8) {
            float4 av = *(const float4*)&g_H2[(size_t)(m0 + arow) * 128 + k0 + akq];
            As[(akq+0)*128 + arow] = av.x; As[(akq+1)*128 + arow] = av.y;
            As[(akq+2)*128 + arow] = av.z; As[(akq+3)*128 + arow] = av.w;
            #pragma unroll
            for (int r = 0; r < 4; r++)
                Bs[(kk0 + r)*128 + bn] = fw3[(size_t)(k0 + kk0 + r) * 2048 + jm];
            __syncthreads();
            #pragma unroll
            for (int kk = 0; kk < 8; kk++) {
                float a[8], bb[8];
                #pragma unroll
                for (int i = 0; i < 8; i++) a[i] = As[kk*128 + ty*8 + i];
                #pragma unroll
                for (int j = 0; j < 8; j++) bb[j] = Bs[kk*128 + tx*8 + j];
                #pragma unroll
                for (int i = 0; i < 8; i++)
                    #pragma unroll
                    for (int j = 0; j < 8; j++) acc[i][j] += a[i] * bb[j];
            }
            __syncthreads();
        }

        float bo[8];
        #pragma unroll
        for (int j = 0; j < 8; j++) bo[j] = fb3[2*(n0 + tx*8 + j) + 1];

        #pragma unroll
        for (int h = 0; h < 2; h++) {
            __syncthreads();
            if ((tx >> 3) == h) {
                #pragma unroll
                for (int i = 0; i < 8; i++)
                    #pragma unroll
                    for (int j = 0; j < 8; j++)
                        stage[(ty*8 + i) * 65 + (tx & 7) * 8 + j] = acc[i][j] + bo[j];
            }
            __syncthreads();
            const int cl  = tid >> 2;
            const int lch = (tid & 3) << 5;
            const int c   = n0 + h * 64 + cl;
            float* dst = g_COEFt + (size_t)c * LSEQ + m0 + lch;
            #pragma unroll
            for (int j = 0; j < 32; j += 4) {
                float4 o = make_float4(stage[(lch+j)*65   + cl],
                                       stage[(lch+j+1)*65 + cl],
                                       stage[(lch+j+2)*65 + cl],
                                       stage[(lch+j+3)*65 + cl]);
                *(float4*)&dst[j] = o;
            }
        }
        return;
    }

    // ---------------- in_proj GEMM (frozen MODE-0 body) ----------------------
    const uint32_t sb  = smem_u32(dsm);
    const uint32_t sAh = sb, sBh = sb + 32768;
    const int lane = tid & 31;
    const int wid  = tid >> 5;
    const int wm   = wid >> 1;
    const int wn   = wid & 1;
    const int gbid = blockIdx.x - NCOEF_B;
    const int bx   = gbid & 15;
    const int m0   = (gbid >> 4) * 128;
    const int n0   = bx * 128;

    float acc[2][8][4];
    #pragma unroll
    for (int i = 0; i < 2; i++)
        #pragma unroll
        for (int j = 0; j < 8; j++)
            #pragma unroll
            for (int q = 0; q < 4; q++) acc[i][j][q] = 0.f;

    for (int it = 0; it < 16; ++it) {
        const size_t kc0 = (size_t)it * 64;
        #pragma unroll
        for (int u = 0; u < 4; u++) {
            const int s = tid + u * 256;
            const int row = s >> 3, seg = s & 7;
            const uint32_t so = (uint32_t)(row * 128 + ((seg * 16) ^ ((row & 7) << 4)));
            const size_t ga = (size_t)(m0 + row) * 1024 + kc0 + seg * 8;
            const size_t gb = (size_t)(n0 + row) * 1024 + kc0 + seg * 8;
            CP_ASYNC16(sAh + so, g_Xh + ga);
            CP_ASYNC16(sAh + 16384 + so, g_Xl + ga);
            CP_ASYNC16(sBh + so, g_Wih + gb);
            CP_ASYNC16(sBh + 16384 + so, g_Wil + gb);
        }
        CP_COMMIT();
        CP_WAIT0();
        __syncthreads();

        #pragma unroll
        for (int ks = 0; ks < 4; ks++) {
            uint32_t ah[2][4], al[2][4];
            #pragma unroll
            for (int mt = 0; mt < 2; mt++) {
                const int row = wm * 32 + mt * 16 + (lane & 15);
                const uint32_t r4 = (row & 7) << 4;
                const uint32_t cb = (uint32_t)(ks * 32 + ((lane >> 4) << 4));
                const uint32_t ad = sAh + row * 128 + (cb ^ r4);
                LDSM4(ah[mt][0], ah[mt][1], ah[mt][2], ah[mt][3], ad);
                LDSM4(al[mt][0], al[mt][1], al[mt][2], al[mt][3], ad + 16384);
            }
            uint32_t bh[8][2], bl[8][2];
            #pragma unroll
            for (int nt2 = 0; nt2 < 4; nt2++) {
                const int n = wn * 64 + nt2 * 16 + (lane & 7) + ((lane >> 4) << 3);
                const uint32_t r4 = (n & 7) << 4;
                const uint32_t cb = (uint32_t)(ks * 32 + (((lane >> 3) & 1) << 4));
                const uint32_t ad = sBh + n * 128 + (cb ^ r4);
                LDSM4(bh[2*nt2][0], bh[2*nt2][1], bh[2*nt2+1][0], bh[2*nt2+1][1], ad);
                LDSM4(bl[2*nt2][0], bl[2*nt2][1], bl[2*nt2+1][0], bl[2*nt2+1][1], ad + 16384);
            }
            #pragma unroll
            for (int mt = 0; mt < 2; mt++)
                #pragma unroll
                for (int nt = 0; nt < 8; nt++) {
                    mma_bf16(acc[mt][nt], ah[mt], bh[nt]);
                    mma_bf16(acc[mt][nt], ah[mt], bl[nt]);
                    mma_bf16(acc[mt][nt], al[mt], bh[nt]);
                }
        }
        __syncthreads();
    }

    {
        float* stage = (float*)dsm;          // [128][65] floats = 33 KB
        const bool is_v = (bx < 8);
        const int cbase = (is_v ? bx : bx - 8) * 128;
        #pragma unroll
        for (int h = 0; h < 2; h++) {
            __syncthreads();
            if (wn == h) {
                #pragma unroll
                for (int mt = 0; mt < 2; mt++) {
                    const int rl = wm * 32 + mt * 16 + (lane >> 2);
                    #pragma unroll
                    for (int nt = 0; nt < 8; nt++) {
                        const int cl = nt * 8 + ((lane & 3) << 1);
                        stage[rl * 65 + cl]           = acc[mt][nt][0];
                        stage[rl * 65 + cl + 1]       = acc[mt][nt][1];
                        stage[(rl + 8) * 65 + cl]     = acc[mt][nt][2];
                        stage[(rl + 8) * 65 + cl + 1] = acc[mt][nt][3];
                    }
                }
            }
            __syncthreads();
            const int cl  = tid >> 2;
            const int mch = (tid & 3) << 5;
            const int c   = cbase + h * 64 + cl;
            const float b = is_v ? bias[3*c] : bias[3*c + 2];
            float* dst = (is_v ? g_Vcm : g_X2t) + (size_t)c * MTOT + m0 + mch;
            #pragma unroll
            for (int j = 0; j < 32; j += 4) {
                float4 o = make_float4(stage[(mch+j)*65   + cl] + b,
                                       stage[(mch+j+1)*65 + cl] + b,
                                       stage[(mch+j+2)*65 + cl] + b,
                                       stage[(mch+j+3)*65 + cl] + b);
                *(float4*)&dst[j] = o;
            }
        }
    }
}

// ============================================================================
// out-proj GEMM (frozen MODE-1 body, standalone)
// ============================================================================
__global__ __launch_bounds__(256, 2) void gemm_out_tc(
    const float* __restrict__ bias, float* __restrict__ out)
{
    extern __shared__ char dsm[];
    const uint32_t sb  = smem_u32(dsm);
    const uint32_t sAh = sb, sBh = sb + 32768;

    const int tid  = threadIdx.x;
    const int lane = tid & 31;
    const int wid  = tid >> 5;
    const int wm   = wid >> 1;
    const int wn   = wid & 1;
    const int m0   = blockIdx.y * 128;
    const int n0   = blockIdx.x * 128;

    float acc[2][8][4];
    #pragma unroll
    for (int i = 0; i < 2; i++)
        #pragma unroll
        for (int j = 0; j < 8; j++)
            #pragma unroll
            for (int q = 0; q < 4; q++) acc[i][j][q] = 0.f;

    for (int it = 0; it < 16; ++it) {
        const size_t kc0 = (size_t)it * 64;
        #pragma unroll
        for (int u = 0; u < 4; u++) {
            const int s = tid + u * 256;
            const int row = s >> 4, seg = s & 15;
            const uint32_t so = (uint32_t)(row * 256 + ((seg * 16) ^ ((row & 7) << 4)));
            const size_t ga = (size_t)(kc0 + row) * MTOT + m0 + seg * 8;
            CP_ASYNC16(sAh + so, g_Gh + ga);
            CP_ASYNC16(sAh + 16384 + so, g_Gl + ga);
        }
        #pragma unroll
        for (int u = 0; u < 4; u++) {
            const int s = tid + u * 256;
            const int row = s >> 3, seg = s & 7;
            const uint32_t so = (uint32_t)(row * 128 + ((seg * 16) ^ ((row & 7) << 4)));
            const size_t gb = (size_t)(n0 + row) * 1024 + kc0 + seg * 8;
            CP_ASYNC16(sBh + so, g_Woh + gb);
            CP_ASYNC16(sBh + 16384 + so, g_Wol + gb);
        }
        CP_COMMIT();
        CP_WAIT0();
        __syncthreads();

        #pragma unroll
        for (int ks = 0; ks < 4; ks++) {
            uint32_t ah[2][4], al[2][4];
            #pragma unroll
            for (int mt = 0; mt < 2; mt++) {
                const int rowk = ks * 16 + (lane & 7) + ((lane >> 4) << 3);
                const int mcol = wm * 32 + mt * 16 + (((lane >> 3) & 1) << 3);
                const uint32_t ad = sAh + rowk * 256 +
                    (((uint32_t)(2 * mcol)) ^ ((uint32_t)(rowk & 7) << 4));
                LDSM4T(ah[mt][0], ah[mt][1], ah[mt][2], ah[mt][3], ad);
                LDSM4T(al[mt][0], al[mt][1], al[mt][2], al[mt][3], ad + 16384);
            }
            uint32_t bh[8][2], bl[8][2];
            #pragma unroll
            for (int nt2 = 0; nt2 < 4; nt2++) {
                const int n = wn * 64 + nt2 * 16 + (lane & 7) + ((lane >> 4) << 3);
                const uint32_t r4 = (n & 7) << 4;
                const uint32_t cb = (uint32_t)(ks * 32 + (((lane >> 3) & 1) << 4));
                const uint32_t ad = sBh + n * 128 + (cb ^ r4);
                LDSM4(bh[2*nt2][0], bh[2*nt2][1], bh[2*nt2+1][0], bh[2*nt2+1][1], ad);
                LDSM4(bl[2*nt2][0], bl[2*nt2][1], bl[2*nt2+1][0], bl[2*nt2+1][1], ad + 16384);
            }
            #pragma unroll
            for (int mt = 0; mt < 2; mt++)
                #pragma unroll
                for (int nt = 0; nt < 8; nt++) {
                    mma_bf16(acc[mt][nt], ah[mt], bh[nt]);
                    mma_bf16(acc[mt][nt], ah[mt], bl[nt]);
                    mma_bf16(acc[mt][nt], al[mt], bh[nt]);
                }
        }
        __syncthreads();
    }

    #pragma unroll
    for (int mt = 0; mt < 2; mt++) {
        const int r = m0 + wm * 32 + mt * 16 + (lane >> 2);
        #pragma unroll
        for (int nt = 0; nt < 8; nt++) {
            const int c = n0 + wn * 64 + nt * 8 + ((lane & 3) << 1);
            const float b0 = bias[c], b1 = bias[c + 1];
            *(float2*)&out[(size_t)r * CH + c] =
                make_float2(acc[mt][nt][0] + b0, acc[mt][nt][1] + b1);
            *(float2*)&out[(size_t)(r + 8) * CH + c] =
                make_float2(acc[mt][nt][2] + b0, acc[mt][nt][3] + b1);
        }
    }
}

// ============================================================================
// FFT convolution — radix-16 passes, padded smem, smem Hermitian half-
// spectrum; filter stash fused into the filter FFT's final pass. (frozen)
// ============================================================================
#define FFT_T    512
#define ZI(i) ((i) + ((i) >> 4))
#define Z_PAD_SZ  17408                 // float2
#define HS_PAD_SZ 8232                  // float2
#define COS_SZ    4104                  // floats
#define HsI(k) ((k) + ((k) >> 8))
#define FFT_SMEM ((Z_PAD_SZ + HS_PAD_SZ) * 8 + COS_SZ * 4)

__device__ __forceinline__ int digrev4_14(int j) {
    unsigned r = __brev((unsigned)j) >> 18;
    return (int)(((r & 0x2AAAu) >> 1) | ((r & 0x1555u) << 1));
}
__device__ __forceinline__ int digrev4_10(int g) {
    unsigned r = __brev((unsigned)g) >> 22;
    return (int)(((r & 0x155u) << 1) | ((r >> 1) & 0x155u));
}
__device__ __forceinline__ float2 twc(const float* __restrict__ C, int k) {
    return make_float2(C[k], -C[4096 - k]);
}
__device__ __forceinline__ float conv3(const float* __restrict__ q, int l,
                                       float w0, float w1, float w2, float b) {
    float s = w1 * q[l] + b;
    if (l > 0)        s += w0 * q[l-1];
    if (l < LSEQ - 1) s += w2 * q[l+1];
    return s;
}

__device__ void fft_dif_first(float2* Z, const float* C,
                              const float* __restrict__ re, int tid) {
    for (int p = tid; p < 4096; p += FFT_T) {
        float2 a = make_float2(re[p], 0.f);
        float2 b = make_float2(re[p + 4096], 0.f);
        float2 w1 = twc(C, p);
        float2 w2 = cmulf(w1, w1);
        float2 w3 = cmulf(w2, w1);
        Z[ZI(p)]         = caddf(a, b);
        Z[ZI(p + 4096)]  = cmulf(make_float2(a.x + b.y, a.y - b.x), w1);
        Z[ZI(p + 8192)]  = cmulf(csubf(a, b),                       w2);
        Z[ZI(p + 12288)] = cmulf(make_float2(a.x - b.y, a.y + b.x), w3);
    }
    __syncthreads();
}

__device__ void fft_dif_first_conv(float2* Z, const float* C,
                                   const float* __restrict__ v0,
                                   float w0, float w1, float w2, float cb, int tid) {
    const float* v1 = v0 + LSEQ;
    for (int p = tid; p < 4096; p += FFT_T) {
        float2 a = make_float2(conv3(v0, p, w0, w1, w2, cb),
                               conv3(v1, p, w0, w1, w2, cb));
        float2 b = make_float2(conv3(v0, p + 4096, w0, w1, w2, cb),
                               conv3(v1, p + 4096, w0, w1, w2, cb));
        float2 t1 = twc(C, p);
        float2 t2 = cmulf(t1, t1);
        float2 t3 = cmulf(t2, t1);
        Z[ZI(p)]         = caddf(a, b);
        Z[ZI(p + 4096)]  = cmulf(make_float2(a.x + b.y, a.y - b.x), t1);
        Z[ZI(p + 8192)]  = cmulf(csubf(a, b),                       t2);
        Z[ZI(p + 12288)] = cmulf(make_float2(a.x - b.y, a.y + b.x), t3);
    }
    __syncthreads();
}

template<int LA, int TWA>
__device__ void fft_dif_pass16(float2* Z, const float* C, int tid) {
    constexpr int qA = LA / 4, qB = LA / 16;
    constexpr int TWB = TWA + 2;
    const int p2 = tid & (qB - 1);
    float2 wA1[4], wA2[4], wA3[4];
    #pragma unroll
    for (int a = 0; a < 4; a++) {
        const int k = (p2 + a*qB) << TWA;
        wA1[a] = twc(C, k);
        wA2[a] = cmulf(wA1[a], wA1[a]);
        wA3[a] = cmulf(wA2[a], wA1[a]);
    }
    const int k2 = p2 << TWB;
    const float2 wB1 = twc(C, k2);
    const float2 wB2 = cmulf(wB1, wB1);
    const float2 wB3 = cmulf(wB2, wB1);
    #pragma unroll
    for (int half = 0; half < 2; half++) {
        const int g = tid + half * FFT_T;
        const int base = (g / qB) * LA + p2;
        float2 x[4][4];
        #pragma unroll
        for (int b = 0; b < 4; b++)
            #pragma unroll
            for (int a = 0; a < 4; a++)
                x[b][a] = Z[ZI(base + a*qB + b*qA)];
        #pragma unroll
        for (int a = 0; a < 4; a++) {
            float2 t0 = caddf(x[0][a], x[2][a]);
            float2 t1 = csubf(x[0][a], x[2][a]);
            float2 t2 = caddf(x[1][a], x[3][a]);
            float2 bd = csubf(x[1][a], x[3][a]);
            float2 t3 = make_float2(bd.y, -bd.x);
            x[0][a] = caddf(t0, t2);
            x[1][a] = cmulf(caddf(t1, t3), wA1[a]);
            x[2][a] = cmulf(csubf(t0, t2), wA2[a]);
            x[3][a] = cmulf(csubf(t1, t3), wA3[a]);
        }
        #pragma unroll
        for (int b = 0; b < 4; b++) {
            float2 t0 = caddf(x[b][0], x[b][2]);
            float2 t1 = csubf(x[b][0], x[b][2]);
            float2 t2 = caddf(x[b][1], x[b][3]);
            float2 bd = csubf(x[b][1], x[b][3]);
            float2 t3 = make_float2(bd.y, -bd.x);
            Z[ZI(base + 0*qB + b*qA)] = caddf(t0, t2);
            Z[ZI(base + 1*qB + b*qA)] = cmulf(caddf(t1, t3), wB1);
            Z[ZI(base + 2*qB + b*qA)] = cmulf(csubf(t0, t2), wB2);
            Z[ZI(base + 3*qB + b*qA)] = cmulf(csubf(t1, t3), wB3);
        }
    }
    __syncthreads();
}

__device__ void fft_dif_pass16_stash(float2* Z, const float* C,
                                     float2* __restrict__ Hs, int tid) {
    float2 wA1[4], wA2[4], wA3[4];
    #pragma unroll
    for (int a = 0; a < 4; a++) {
        const int k = a << 10;
        wA1[a] = twc(C, k);
        wA2[a] = cmulf(wA1[a], wA1[a]);
        wA3[a] = cmulf(wA2[a], wA1[a]);
    }
    #pragma unroll
    for (int half = 0; half < 2; half++) {
        const int g = tid + half * FFT_T;
        const int base = g * 16;
        const int kg = digrev4_10(g);
        float2 x[4][4];
        #pragma unroll
        for (int b = 0; b < 4; b++)
            #pragma unroll
            for (int a = 0; a < 4; a++)
                x[b][a] = Z[ZI(base + a + 4*b)];
        #pragma unroll
        for (int a = 0; a < 4; a++) {
            float2 t0 = caddf(x[0][a], x[2][a]);
            float2 t1 = csubf(x[0][a], x[2][a]);
            float2 t2 = caddf(x[1][a], x[3][a]);
            float2 bd = csubf(x[1][a], x[3][a]);
            float2 t3 = make_float2(bd.y, -bd.x);
            x[0][a] = caddf(t0, t2);
            x[1][a] = cmulf(caddf(t1, t3), wA1[a]);
            x[2][a] = cmulf(csubf(t0, t2), wA2[a]);
            x[3][a] = cmulf(csubf(t1, t3), wA3[a]);
        }
        #pragma unroll
        for (int b = 0; b < 4; b++) {
            float2 t0 = caddf(x[b][0], x[b][2]);
            float2 t1 = csubf(x[b][0], x[b][2]);
            float2 t2 = caddf(x[b][1], x[b][3]);
            float2 bd = csubf(x[b][1], x[b][3]);
            float2 t3 = make_float2(bd.y, -bd.x);
            const int k0 = kg + b * 1024;
            Hs[HsI(k0)]        = caddf(t0, t2);      // o=0
            Hs[HsI(k0 + 4096)] = caddf(t1, t3);      // o=1
            if (k0 == 0) Hs[HsI(8192)] = csubf(t0, t2);  // k=8192 edge
        }
    }
    __syncthreads();
}

__device__ void ifft_first_mult(float2* Z, const float2* __restrict__ Hs, int tid) {
    for (int b = tid; b < NFFT/4; b += FFT_T) {
        const int i0 = 4*b;
        const int kb = digrev4_14(i0);
        float2 zz[4];
        #pragma unroll
        for (int s2 = 0; s2 < 4; s2++) {
            const int k = kb + s2 * 4096;
            float2 H;
            if (k <= 8192) H = Hs[HsI(k)];
            else { const int kc = 16384 - k; H = Hs[HsI(kc)]; H.y = -H.y; }
            zz[s2] = cmulf(Z[ZI(i0 + s2)], H);
        }
        float2 t0 = caddf(zz[0], zz[2]), t1 = csubf(zz[0], zz[2]);
        float2 t2 = caddf(zz[1], zz[3]);
        float2 bd = csubf(zz[1], zz[3]);
        float2 t3 = make_float2(-bd.y, bd.x);
        Z[ZI(i0)]     = caddf(t0, t2);
        Z[ZI(i0 + 1)] = caddf(t1, t3);
        Z[ZI(i0 + 2)] = csubf(t0, t2);
        Z[ZI(i0 + 3)] = csubf(t1, t3);
    }
    __syncthreads();
}

template<int L1, int TW1>
__device__ void ifft_dit_pass16(float2* Z, const float* C, int tid) {
    constexpr int q1 = L1 / 4, L2 = 4 * L1;
    constexpr int TW2 = TW1 - 2;
    const int p = tid & (q1 - 1);
    const int k1 = p << TW1;
    const float2 u1 = twc(C, k1);
    const float2 u2 = cmulf(u1, u1);
    const float2 u3 = cmulf(u2, u1);
    float2 v1[4], v2[4], v3[4];
    #pragma unroll
    for (int a = 0; a < 4; a++) {
        const int kk = (p + a*q1) << TW2;
        v1[a] = twc(C, kk);
        v2[a] = cmulf(v1[a], v1[a]);
        v3[a] = cmulf(v2[a], v1[a]);
    }
    #pragma unroll
    for (int half = 0; half < 2; half++) {
        const int g = tid + half * FFT_T;
        const int base = (g / q1) * L2 + p;
        float2 x[4][4];
        #pragma unroll
        for (int b = 0; b < 4; b++)
            #pragma unroll
            for (int a = 0; a < 4; a++)
                x[b][a] = Z[ZI(base + a*q1 + b*L1)];
        #pragma unroll
        for (int b = 0; b < 4; b++) {
            float2 a0 = x[b][0];
            float2 a1 = cmulconjf(x[b][1], u1);
            float2 a2 = cmulconjf(x[b][2], u2);
            float2 a3 = cmulconjf(x[b][3], u3);
            float2 t0 = caddf(a0, a2), t1 = csubf(a0, a2);
            float2 t2 = caddf(a1, a3);
            float2 bd = csubf(a1, a3);
            float2 t3 = make_float2(-bd.y, bd.x);
            x[b][0] = caddf(t0, t2);
            x[b][1] = caddf(t1, t3);
            x[b][2] = csubf(t0, t2);
            x[b][3] = csubf(t1, t3);
        }
        #pragma unroll
        for (int a = 0; a < 4; a++) {
            float2 b0 = x[0][a];
            float2 b1 = cmulconjf(x[1][a], v1[a]);
            float2 b2 = cmulconjf(x[2][a], v2[a]);
            float2 b3 = cmulconjf(x[3][a], v3[a]);
            float2 t0 = caddf(b0, b2), t1 = csubf(b0, b2);
            float2 t2 = caddf(b1, b3);
            float2 bd = csubf(b1, b3);
            float2 t3 = make_float2(-bd.y, bd.x);
            Z[ZI(base + a*q1 + 0*L1)] = caddf(t0, t2);
            Z[ZI(base + a*q1 + 1*L1)] = caddf(t1, t3);
            Z[ZI(base + a*q1 + 2*L1)] = csubf(t0, t2);
            Z[ZI(base + a*q1 + 3*L1)] = csubf(t1, t3);
        }
    }
    __syncthreads();
}

__global__ __launch_bounds__(FFT_T, 1) void fft_conv_kernel(
    const float* __restrict__ sw, const float* __restrict__ sb)
{
    extern __shared__ float2 sm[];
    float2* Z  = sm;
    float2* Hs = sm + Z_PAD_SZ;
    float*  C  = (float*)(sm + Z_PAD_SZ + HS_PAD_SZ);
    const int c   = blockIdx.x;
    const int tid = threadIdx.x;

    for (int k = tid; k <= 4096; k += FFT_T)
        C[k] = cosf(3.834951969714103e-4f * (float)k);   // cos(2*pi*k/16384)
    __syncthreads();

    // ---- filter FFT; final pass writes half-spectrum straight to smem Hs ----
    fft_dif_first(Z, C, g_COEFt + (size_t)c * LSEQ, tid);
    fft_dif_pass16<4096, 2>(Z, C, tid);
    fft_dif_pass16<256, 6>(Z, C, tid);
    fft_dif_pass16_stash(Z, C, Hs, tid);

    // ---- v FFT with fused depthwise short-conv ----
    const float w0 = sw[c*3], w1 = sw[c*3+1], w2 = sw[c*3+2], cb = sb[c];
    fft_dif_first_conv(Z, C, g_Vcm + (size_t)c * MTOT, w0, w1, w2, cb, tid);
    fft_dif_pass16<4096, 2>(Z, C, tid);
    fft_dif_pass16<256, 6>(Z, C, tid);
    fft_dif_pass16<16, 10>(Z, C, tid);

    // ---- inverse: multiply (from smem half-spectrum) fused into len-4 stage
    ifft_first_mult(Z, Hs, tid);
    ifft_dit_pass16<16, 10>(Z, C, tid);
    ifft_dit_pass16<256, 6>(Z, C, tid);

    // ---- final paired pass fused with gate + bf16 hi/lo store ([c][m]) ----
    const float* x2 = g_X2t + (size_t)c * MTOT;
    __nv_bfloat16* goh = g_Gh + (size_t)c * MTOT;
    __nv_bfloat16* gol = g_Gl + (size_t)c * MTOT;
    const float scale = 1.0f / (float)NFFT;
    for (int p = tid; p < 1024; p += FFT_T) {
        float2 x[4][4];
        #pragma unroll
        for (int b = 0; b < 4; b++)
            #pragma unroll
            for (int a = 0; a < 4; a++)
                x[b][a] = Z[ZI(p + a*1024 + b*4096)];
        const float2 u1 = twc(C, p << 2);
        const float2 u2 = cmulf(u1, u1);
        const float2 u3 = cmulf(u2, u1);
        #pragma unroll
        for (int b = 0; b < 4; b++) {
            float2 a0 = x[b][0];
            float2 a1 = cmulconjf(x[b][1], u1);
            float2 a2 = cmulconjf(x[b][2], u2);
            float2 a3 = cmulconjf(x[b][3], u3);
            float2 t0 = caddf(a0, a2), t1 = csubf(a0, a2);
            float2 t2 = caddf(a1, a3);
            float2 bd = csubf(a1, a3);
            float2 t3 = make_float2(-bd.y, bd.x);
            x[b][0] = caddf(t0, t2);
            x[b][1] = caddf(t1, t3);
            x[b][2] = csubf(t0, t2);
            x[b][3] = csubf(t1, t3);
        }
        #pragma unroll
        for (int a = 0; a < 4; a++) {
            const int k2 = p + a*1024;
            const float2 q1 = twc(C, k2);
            const float2 q2 = cmulf(q1, q1);
            const float2 q3 = cmulf(q2, q1);
            float2 b0 = x[0][a];
            float2 b1 = cmulconjf(x[1][a], q1);
            float2 b2 = cmulconjf(x[2][a], q2);
            float2 b3 = cmulconjf(x[3][a], q3);
            float2 t0 = caddf(b0, b2), t1 = csubf(b0, b2);
            float2 t2 = caddf(b1, b3);
            float2 bd = csubf(b1, b3);
            float2 t3 = make_float2(-bd.y, bd.x);
            float2 o0 = caddf(t0, t2);         // time t
            float2 o1 = caddf(t1, t3);         // time t+4096
            const int t = p + a*1024;
            float gv;
            __nv_bfloat16 hh, ll;
            gv = x2[t]               * (o0.x * scale); bf16_split(gv, hh, ll);
            goh[t] = hh;               gol[t] = ll;
            gv = x2[LSEQ + t]        * (o0.y * scale); bf16_split(gv, hh, ll);
            goh[LSEQ + t] = hh;        gol[LSEQ + t] = ll;
            gv = x2[t + 4096]        * (o1.x * scale); bf16_split(gv, hh, ll);
            goh[t + 4096] = hh;        gol[t + 4096] = ll;
            gv = x2[LSEQ + t + 4096] * (o1.y * scale); bf16_split(gv, hh, ll);
            goh[LSEQ + t + 4096] = hh; gol[LSEQ + t + 4096] = ll;
        }
    }
}

// ============================================================================
extern "C" void kernel_launch(void* const* d_in, const int* in_sizes, int n_in,
                              void* d_out, int out_size)
{
    const float* x   = (const float*)d_in[0];
    const float* ipw = (const float*)d_in[1];
    const float* ipb = (const float*)d_in[2];
    const float* sw  = (const float*)d_in[3];
    const float* sb  = (const float*)d_in[4];
    const float* fw1 = (const float*)d_in[5];
    const float* fb1 = (const float*)d_in[6];
    const float* fw2 = (const float*)d_in[7];
    const float* fb2 = (const float*)d_in[8];
    const float* fw3 = (const float*)d_in[9];
    const float* fb3 = (const float*)d_in[10];
    const float* ow  = (const float*)d_in[11];
    const float* ob  = (const float*)d_in[12];
    float* out = (float*)d_out;

    cudaFuncSetAttribute(fft_conv_kernel,
                         cudaFuncAttributeMaxDynamicSharedMemorySize, FFT_SMEM);
    cudaFuncSetAttribute(gemm0_coef,
                         cudaFuncAttributeMaxDynamicSharedMemorySize, GSM_BYTES);
    cudaFuncSetAttribute(gemm_out_tc,
                         cudaFuncAttributeMaxDynamicSharedMemorySize, GSM_BYTES);

    // 1) one prep kernel: x split + weight gathers + filter MLP h2
    prep_split<<<22528, 256>>>(x, ipw, ow, fw1, fb1, fw2, fb2);
    // 2) merged launch: coef GEMM tiles (first) + in_proj GEMM tiles
    gemm0_coef<<<NCOEF_B + 2048, 256, GSM_BYTES>>>(ipb, fw3, fb3);
    // 3) FFT long conv (fused short-conv, stash, mult, gate, bf16 split out)
    fft_conv_kernel<<<CH, FFT_T, FFT_SMEM>>>(sw, sb);
    // 4) out GEMM reads gated activations k-major via ldmatrix.trans
    gemm_out_tc<<<dim3(8, 128), 256, GSM_BYTES>>>(ob, out);
}

// round 15
// speedup vs baseline: 2.3814x; 1.5250x over previous
#include <cuda_runtime.h>
#include <cuda_fp16.h>
#include <math.h>
#include <stdint.h>

// Problem constants
#define LSEQ   8192
#define NFFT   16384
#define CH     1024
#define BATCH  2
#define MTOT   (BATCH*LSEQ)      // 16384 rows

// ---------------- scratch (device globals; no allocations allowed) ----------
__device__ float g_Vcm  [CH*MTOT];     // in_proj v branch, channel-major [c][m]
__device__ float g_X2t  [CH*MTOT];     // x2 branch, channel-major [c][m]
__device__ float g_H2   [LSEQ*128];    // filter MLP hidden (L x 128)
__device__ float g_COEFt[CH*LSEQ];     // filter coefs order-1, channel-major [c][l]

// fp16 operands for the tensor-core GEMMs (single-term)
__device__ __half g_Xf [MTOT*CH];      // x, [m][k]
__device__ __half g_Gf [CH*MTOT];      // gated, [c][m] (k-major)
__device__ __half g_Wif[2048*CH];      // in_proj cols, [n][k]
__device__ __half g_Wof[CH*CH];        // out_w^T, [n][k]

// ---------------- generic helpers -------------------------------------------
__device__ __forceinline__ float gelu_exact(float x) {
    return 0.5f * x * (1.0f + erff(x * 0.70710678118654752f));
}
__device__ __forceinline__ float2 cmulf(float2 a, float2 b) {
    return make_float2(a.x*b.x - a.y*b.y, a.x*b.y + a.y*b.x);
}
__device__ __forceinline__ float2 cmulconjf(float2 a, float2 w) {  // a * conj(w)
    return make_float2(a.x*w.x + a.y*w.y, a.y*w.x - a.x*w.y);
}
__device__ __forceinline__ float2 caddf(float2 a, float2 b) {
    return make_float2(a.x + b.x, a.y + b.y);
}
__device__ __forceinline__ float2 csubf(float2 a, float2 b) {
    return make_float2(a.x - b.x, a.y - b.y);
}
__device__ __forceinline__ uint32_t smem_u32(const void* p) {
    uint32_t a;
    asm("{ .reg .u64 t; cvta.to.shared.u64 t, %1; cvt.u32.u64 %0, t; }"
        : "=r"(a) : "l"(p));
    return a;
}

#define CP_ASYNC16(sm, gp) \
    asm volatile("cp.async.cg.shared.global [%0], [%1], 16;" \
                 :: "r"(sm), "l"(__cvta_generic_to_global(gp)) : "memory")
#define CP_COMMIT() asm volatile("cp.async.commit_group;" ::: "memory")
#define CP_WAIT0()  asm volatile("cp.async.wait_group 0;" ::: "memory")

#define LDSM4(r0, r1, r2, r3, ad) \
    asm volatile("ldmatrix.sync.aligned.m8n8.x4.shared.b16 {%0,%1,%2,%3}, [%4];" \
                 : "=r"(r0), "=r"(r1), "=r"(r2), "=r"(r3) : "r"(ad))
#define LDSM4T(r0, r1, r2, r3, ad) \
    asm volatile("ldmatrix.sync.aligned.m8n8.x4.trans.shared.b16 {%0,%1,%2,%3}, [%4];" \
                 : "=r"(r0), "=r"(r1), "=r"(r2), "=r"(r3) : "r"(ad))

__device__ __forceinline__ void mma_f16(float* c, const uint32_t* a, const uint32_t* b) {
    asm volatile("mma.sync.aligned.m16n8k16.row.col.f32.f16.f16.f32 "
        "{%0,%1,%2,%3}, {%4,%5,%6,%7}, {%8,%9}, {%0,%1,%2,%3};"
        : "+f"(c[0]), "+f"(c[1]), "+f"(c[2]), "+f"(c[3])
        : "r"(a[0]), "r"(a[1]), "r"(a[2]), "r"(a[3]), "r"(b[0]), "r"(b[1]));
}

// ============================================================================
// prep_split: one kernel, four roles by block range.
//   [0, 16384)        : x -> g_Xf                ([m][k] fp16)
//   [16384, 17408)    : in_proj weight gather -> g_Wif ([n][k])
//   [17408, 18432)    : out_w transpose       -> g_Wof ([n][k])
//   [18432, 22528)    : filter MLP h2 (2 rows per CTA) -> g_H2
// ============================================================================
__global__ __launch_bounds__(256) void prep_split(
    const float* __restrict__ x, const float* __restrict__ ipw,
    const float* __restrict__ ow,
    const float* __restrict__ fw1, const float* __restrict__ fb1,
    const float* __restrict__ fw2, const float* __restrict__ fb2)
{
    const int b   = blockIdx.x;
    const int tid = threadIdx.x;

    if (b < 16384) {
        size_t i = ((size_t)b * 256 + tid) * 4;
        float4 v = *(const float4*)&x[i];
        *(__half2*)&g_Xf[i]   = __floats2half2_rn(v.x, v.y);
        *(__half2*)&g_Xf[i+2] = __floats2half2_rn(v.z, v.w);
        return;
    }

    if (b < 17408) {
        __shared__ float s[32][97];
        const int bid2 = b - 16384;
        const int c0 = (bid2 & 31) * 32;
        const int k0 = (bid2 >> 5) * 32;
        for (int idx = tid; idx < 32*96; idx += 256) {
            const int r = idx / 96, cc = idx % 96;
            s[r][cc] = ipw[(size_t)(k0 + r) * 3072 + 3*c0 + cc];
        }
        __syncthreads();
        const int dc = tid >> 3;
        const int kq = (tid & 7) * 4;
        const int c  = c0 + dc;
        const size_t ov = (size_t)c * 1024 + k0 + kq;
        const size_t ox = (size_t)(1024 + c) * 1024 + k0 + kq;
        *(__half2*)&g_Wif[ov]   = __floats2half2_rn(s[kq+0][3*dc], s[kq+1][3*dc]);
        *(__half2*)&g_Wif[ov+2] = __floats2half2_rn(s[kq+2][3*dc], s[kq+3][3*dc]);
        *(__half2*)&g_Wif[ox]   = __floats2half2_rn(s[kq+0][3*dc+2], s[kq+1][3*dc+2]);
        *(__half2*)&g_Wif[ox+2] = __floats2half2_rn(s[kq+2][3*dc+2], s[kq+3][3*dc+2]);
        return;
    }

    if (b < 18432) {
        __shared__ float s[32][33];
        const int bid2 = b - 17408;
        const int c0 = (bid2 & 31) * 32;
        const int k0 = (bid2 >> 5) * 32;
        const int tx  = tid & 31;
        const int ty0 = tid >> 5;            // 0..7
        #pragma unroll
        for (int rr = 0; rr < 4; rr++) {
            const int r = ty0 + rr * 8;
            s[r][tx] = ow[(size_t)(k0 + r) * CH + c0 + tx];
        }
        __syncthreads();
        #pragma unroll
        for (int rr = 0; rr < 4; rr++) {
            const int ty = ty0 + rr * 8;
            g_Wof[(size_t)(c0 + ty) * 1024 + k0 + tx] = __float2half(s[tx][ty]);
        }
        return;
    }

    {
        // filter MLP: 2 sequence positions per CTA
        __shared__ float h1s[2][64];
        const int lb  = (b - 18432) * 2;
        const int sub = tid >> 7;            // 0/1
        const int t   = tid & 127;
        const int l   = lb + sub;
        const float pos = (float)l / (float)(LSEQ - 1);
        if (t < 64) h1s[sub][t] = gelu_exact(pos * fw1[t] + fb1[t]);
        __syncthreads();
        float s = fb2[t];
        #pragma unroll 8
        for (int j = 0; j < 64; j++) s += h1s[sub][j] * fw2[j*128 + t];
        g_H2[(size_t)l*128 + t] = gelu_exact(s);
    }
}

// ============================================================================
// gemm0_coef: merged launch.
//   blocks [0, 512)      : coef GEMM tiles (COEFt transposed epilogue)
//   blocks [512, 2560)   : in_proj GEMM tiles (fp16 single-term)
// ============================================================================
#define GSM_BYTES 65536
#define NCOEF_B   512

__global__ __launch_bounds__(256, 2) void gemm0_coef(
    const float* __restrict__ bias,
    const float* __restrict__ fw3, const float* __restrict__ fb3)
{
    extern __shared__ char dsm[];
    const int tid = threadIdx.x;

    if (blockIdx.x < NCOEF_B) {
        // ---------------- coef GEMM (frozen body, smem carved from dsm) ------
        float* As    = (float*)dsm;               // [8][128]
        float* Bs    = As + 8*128;                // [8][128]
        float* stage = Bs + 8*128;                // [128*65]
        const int bid = blockIdx.x;
        const int tx = tid & 15, ty = tid >> 4;
        const int m0 = (bid >> 3) * 128;
        const int n0 = (bid & 7) * 128;

        float acc[8][8];
        #pragma unroll
        for (int i = 0; i < 8; i++)
            #pragma unroll
            for (int j = 0; j < 8; j++) acc[i][j] = 0.f;

        const int arow = tid >> 1, akq = (tid & 1) * 4;
        const int bn = tid & 127;
        const int jm = 2 * (n0 + bn) + 1;
        const int kk0 = (tid >> 7) * 4;

        for (int k0 = 0; k0 < 128; k0 += 8) {
            float4 av = *(const float4*)&g_H2[(size_t)(m0 + arow) * 128 + k0 + akq];
            As[(akq+0)*128 + arow] = av.x; As[(akq+1)*128 + arow] = av.y;
            As[(akq+2)*128 + arow] = av.z; As[(akq+3)*128 + arow] = av.w;
            #pragma unroll
            for (int r = 0; r < 4; r++)
                Bs[(kk0 + r)*128 + bn] = fw3[(size_t)(k0 + kk0 + r) * 2048 + jm];
            __syncthreads();
            #pragma unroll
            for (int kk = 0; kk < 8; kk++) {
                float a[8], bb[8];
                #pragma unroll
                for (int i = 0; i < 8; i++) a[i] = As[kk*128 + ty*8 + i];
                #pragma unroll
                for (int j = 0; j < 8; j++) bb[j] = Bs[kk*128 + tx*8 + j];
                #pragma unroll
                for (int i = 0; i < 8; i++)
                    #pragma unroll
                    for (int j = 0; j < 8; j++) acc[i][j] += a[i] * bb[j];
            }
            __syncthreads();
        }

        float bo[8];
        #pragma unroll
        for (int j = 0; j < 8; j++) bo[j] = fb3[2*(n0 + tx*8 + j) + 1];

        #pragma unroll
        for (int h = 0; h < 2; h++) {
            __syncthreads();
            if ((tx >> 3) == h) {
                #pragma unroll
                for (int i = 0; i < 8; i++)
                    #pragma unroll
                    for (int j = 0; j < 8; j++)
                        stage[(ty*8 + i) * 65 + (tx & 7) * 8 + j] = acc[i][j] + bo[j];
            }
            __syncthreads();
            const int cl  = tid >> 2;
            const int lch = (tid & 3) << 5;
            const int c   = n0 + h * 64 + cl;
            float* dst = g_COEFt + (size_t)c * LSEQ + m0 + lch;
            #pragma unroll
            for (int j = 0; j < 32; j += 4) {
                float4 o = make_float4(stage[(lch+j)*65   + cl],
                                       stage[(lch+j+1)*65 + cl],
                                       stage[(lch+j+2)*65 + cl],
                                       stage[(lch+j+3)*65 + cl]);
                *(float4*)&dst[j] = o;
            }
        }
        return;
    }

    // ---------------- in_proj GEMM (fp16 single-term) -------------------------
    const uint32_t sb  = smem_u32(dsm);
    const uint32_t sA = sb, sB = sb + 16384;
    const int lane = tid & 31;
    const int wid  = tid >> 5;
    const int wm   = wid >> 1;
    const int wn   = wid & 1;
    const int gbid = blockIdx.x - NCOEF_B;
    const int bx   = gbid & 15;
    const int m0   = (gbid >> 4) * 128;
    const int n0   = bx * 128;

    float acc[2][8][4];
    #pragma unroll
    for (int i = 0; i < 2; i++)
        #pragma unroll
        for (int j = 0; j < 8; j++)
            #pragma unroll
            for (int q = 0; q < 4; q++) acc[i][j][q] = 0.f;

    for (int it = 0; it < 16; ++it) {
        const size_t kc0 = (size_t)it * 64;
        #pragma unroll
        for (int u = 0; u < 4; u++) {
            const int s = tid + u * 256;
            const int row = s >> 3, seg = s & 7;
            const uint32_t so = (uint32_t)(row * 128 + ((seg * 16) ^ ((row & 7) << 4)));
            const size_t ga = (size_t)(m0 + row) * 1024 + kc0 + seg * 8;
            const size_t gb = (size_t)(n0 + row) * 1024 + kc0 + seg * 8;
            CP_ASYNC16(sA + so, g_Xf + ga);
            CP_ASYNC16(sB + so, g_Wif + gb);
        }
        CP_COMMIT();
        CP_WAIT0();
        __syncthreads();

        #pragma unroll
        for (int ks = 0; ks < 4; ks++) {
            uint32_t ah[2][4];
            #pragma unroll
            for (int mt = 0; mt < 2; mt++) {
                const int row = wm * 32 + mt * 16 + (lane & 15);
                const uint32_t r4 = (row & 7) << 4;
                const uint32_t cb = (uint32_t)(ks * 32 + ((lane >> 4) << 4));
                const uint32_t ad = sA + row * 128 + (cb ^ r4);
                LDSM4(ah[mt][0], ah[mt][1], ah[mt][2], ah[mt][3], ad);
            }
            uint32_t bh[8][2];
            #pragma unroll
            for (int nt2 = 0; nt2 < 4; nt2++) {
                const int n = wn * 64 + nt2 * 16 + (lane & 7) + ((lane >> 4) << 3);
                const uint32_t r4 = (n & 7) << 4;
                const uint32_t cb = (uint32_t)(ks * 32 + (((lane >> 3) & 1) << 4));
                const uint32_t ad = sB + n * 128 + (cb ^ r4);
                LDSM4(bh[2*nt2][0], bh[2*nt2][1], bh[2*nt2+1][0], bh[2*nt2+1][1], ad);
            }
            #pragma unroll
            for (int mt = 0; mt < 2; mt++)
                #pragma unroll
                for (int nt = 0; nt < 8; nt++)
                    mma_f16(acc[mt][nt], ah[mt], bh[nt]);
        }
        __syncthreads();
    }

    {
        float* stage = (float*)dsm;          // [128][65] floats = 33 KB
        const bool is_v = (bx < 8);
        const int cbase = (is_v ? bx : bx - 8) * 128;
        #pragma unroll
        for (int h = 0; h < 2; h++) {
            __syncthreads();
            if (wn == h) {
                #pragma unroll
                for (int mt = 0; mt < 2; mt++) {
                    const int rl = wm * 32 + mt * 16 + (lane >> 2);
                    #pragma unroll
                    for (int nt = 0; nt < 8; nt++) {
                        const int cl = nt * 8 + ((lane & 3) << 1);
                        stage[rl * 65 + cl]           = acc[mt][nt][0];
                        stage[rl * 65 + cl + 1]       = acc[mt][nt][1];
                        stage[(rl + 8) * 65 + cl]     = acc[mt][nt][2];
                        stage[(rl + 8) * 65 + cl + 1] = acc[mt][nt][3];
                    }
                }
            }
            __syncthreads();
            const int cl  = tid >> 2;
            const int mch = (tid & 3) << 5;
            const int c   = cbase + h * 64 + cl;
            const float b = is_v ? bias[3*c] : bias[3*c + 2];
            float* dst = (is_v ? g_Vcm : g_X2t) + (size_t)c * MTOT + m0 + mch;
            #pragma unroll
            for (int j = 0; j < 32; j += 4) {
                float4 o = make_float4(stage[(mch+j)*65   + cl] + b,
                                       stage[(mch+j+1)*65 + cl] + b,
                                       stage[(mch+j+2)*65 + cl] + b,
                                       stage[(mch+j+3)*65 + cl] + b);
                *(float4*)&dst[j] = o;
            }
        }
    }
}

// ============================================================================
// out-proj GEMM (fp16 single-term; A = g_Gf [k][m] via ldmatrix.trans)
// ============================================================================
__global__ __launch_bounds__(256, 2) void gemm_out_tc(
    const float* __restrict__ bias, float* __restrict__ out)
{
    extern __shared__ char dsm[];
    const uint32_t sb  = smem_u32(dsm);
    const uint32_t sA = sb, sB = sb + 32768;

    const int tid  = threadIdx.x;
    const int lane = tid & 31;
    const int wid  = tid >> 5;
    const int wm   = wid >> 1;
    const int wn   = wid & 1;
    const int m0   = blockIdx.y * 128;
    const int n0   = blockIdx.x * 128;

    float acc[2][8][4];
    #pragma unroll
    for (int i = 0; i < 2; i++)
        #pragma unroll
        for (int j = 0; j < 8; j++)
            #pragma unroll
            for (int q = 0; q < 4; q++) acc[i][j][q] = 0.f;

    for (int it = 0; it < 16; ++it) {
        const size_t kc0 = (size_t)it * 64;
        // A: 64 k-rows x 256B ([k][m], contiguous along m)
        #pragma unroll
        for (int u = 0; u < 4; u++) {
            const int s = tid + u * 256;
            const int row = s >> 4, seg = s & 15;
            const uint32_t so = (uint32_t)(row * 256 + ((seg * 16) ^ ((row & 7) << 4)));
            const size_t ga = (size_t)(kc0 + row) * MTOT + m0 + seg * 8;
            CP_ASYNC16(sA + so, g_Gf + ga);
        }
        // B: 128 n-rows x 128B
        #pragma unroll
        for (int u = 0; u < 4; u++) {
            const int s = tid + u * 256;
            const int row = s >> 3, seg = s & 7;
            const uint32_t so = (uint32_t)(row * 128 + ((seg * 16) ^ ((row & 7) << 4)));
            const size_t gb = (size_t)(n0 + row) * 1024 + kc0 + seg * 8;
            CP_ASYNC16(sB + so, g_Wof + gb);
        }
        CP_COMMIT();
        CP_WAIT0();
        __syncthreads();

        #pragma unroll
        for (int ks = 0; ks < 4; ks++) {
            uint32_t ah[2][4];
            #pragma unroll
            for (int mt = 0; mt < 2; mt++) {
                const int rowk = ks * 16 + (lane & 7) + ((lane >> 4) << 3);
                const int mcol = wm * 32 + mt * 16 + (((lane >> 3) & 1) << 3);
                const uint32_t ad = sA + rowk * 256 +
                    (((uint32_t)(2 * mcol)) ^ ((uint32_t)(rowk & 7) << 4));
                LDSM4T(ah[mt][0], ah[mt][1], ah[mt][2], ah[mt][3], ad);
            }
            uint32_t bh[8][2];
            #pragma unroll
            for (int nt2 = 0; nt2 < 4; nt2++) {
                const int n = wn * 64 + nt2 * 16 + (lane & 7) + ((lane >> 4) << 3);
                const uint32_t r4 = (n & 7) << 4;
                const uint32_t cb = (uint32_t)(ks * 32 + (((lane >> 3) & 1) << 4));
                const uint32_t ad = sB + n * 128 + (cb ^ r4);
                LDSM4(bh[2*nt2][0], bh[2*nt2][1], bh[2*nt2+1][0], bh[2*nt2+1][1], ad);
            }
            #pragma unroll
            for (int mt = 0; mt < 2; mt++)
                #pragma unroll
                for (int nt = 0; nt < 8; nt++)
                    mma_f16(acc[mt][nt], ah[mt], bh[nt]);
        }
        __syncthreads();
    }

    #pragma unroll
    for (int mt = 0; mt < 2; mt++) {
        const int r = m0 + wm * 32 + mt * 16 + (lane >> 2);
        #pragma unroll
        for (int nt = 0; nt < 8; nt++) {
            const int c = n0 + wn * 64 + nt * 8 + ((lane & 3) << 1);
            const float b0 = bias[c], b1 = bias[c + 1];
            *(float2*)&out[(size_t)r * CH + c] =
                make_float2(acc[mt][nt][0] + b0, acc[mt][nt][1] + b1);
            *(float2*)&out[(size_t)(r + 8) * CH + c] =
                make_float2(acc[mt][nt][2] + b0, acc[mt][nt][3] + b1);
        }
    }
}

// ============================================================================
// FFT convolution — radix-16 passes, padded smem, smem Hermitian half-
// spectrum; filter stash fused; gate stage writes fp16 [c][m]. (frozen)
// ============================================================================
#define FFT_T    512
#define ZI(i) ((i) + ((i) >> 4))
#define Z_PAD_SZ  17408                 // float2
#define HS_PAD_SZ 8232                  // float2
#define COS_SZ    4104                  // floats
#define HsI(k) ((k) + ((k) >> 8))
#define FFT_SMEM ((Z_PAD_SZ + HS_PAD_SZ) * 8 + COS_SZ * 4)

__device__ __forceinline__ int digrev4_14(int j) {
    unsigned r = __brev((unsigned)j) >> 18;
    return (int)(((r & 0x2AAAu) >> 1) | ((r & 0x1555u) << 1));
}
__device__ __forceinline__ int digrev4_10(int g) {
    unsigned r = __brev((unsigned)g) >> 22;
    return (int)(((r & 0x155u) << 1) | ((r >> 1) & 0x155u));
}
__device__ __forceinline__ float2 twc(const float* __restrict__ C, int k) {
    return make_float2(C[k], -C[4096 - k]);
}
__device__ __forceinline__ float conv3(const float* __restrict__ q, int l,
                                       float w0, float w1, float w2, float b) {
    float s = w1 * q[l] + b;
    if (l > 0)        s += w0 * q[l-1];
    if (l < LSEQ - 1) s += w2 * q[l+1];
    return s;
}

__device__ void fft_dif_first(float2* Z, const float* C,
                              const float* __restrict__ re, int tid) {
    for (int p = tid; p < 4096; p += FFT_T) {
        float2 a = make_float2(re[p], 0.f);
        float2 b = make_float2(re[p + 4096], 0.f);
        float2 w1 = twc(C, p);
        float2 w2 = cmulf(w1, w1);
        float2 w3 = cmulf(w2, w1);
        Z[ZI(p)]         = caddf(a, b);
        Z[ZI(p + 4096)]  = cmulf(make_float2(a.x + b.y, a.y - b.x), w1);
        Z[ZI(p + 8192)]  = cmulf(csubf(a, b),                       w2);
        Z[ZI(p + 12288)] = cmulf(make_float2(a.x - b.y, a.y + b.x), w3);
    }
    __syncthreads();
}

__device__ void fft_dif_first_conv(float2* Z, const float* C,
                                   const float* __restrict__ v0,
                                   float w0, float w1, float w2, float cb, int tid) {
    const float* v1 = v0 + LSEQ;
    for (int p = tid; p < 4096; p += FFT_T) {
        float2 a = make_float2(conv3(v0, p, w0, w1, w2, cb),
                               conv3(v1, p, w0, w1, w2, cb));
        float2 b = make_float2(conv3(v0, p + 4096, w0, w1, w2, cb),
                               conv3(v1, p + 4096, w0, w1, w2, cb));
        float2 t1 = twc(C, p);
        float2 t2 = cmulf(t1, t1);
        float2 t3 = cmulf(t2, t1);
        Z[ZI(p)]         = caddf(a, b);
        Z[ZI(p + 4096)]  = cmulf(make_float2(a.x + b.y, a.y - b.x), t1);
        Z[ZI(p + 8192)]  = cmulf(csubf(a, b),                       t2);
        Z[ZI(p + 12288)] = cmulf(make_float2(a.x - b.y, a.y + b.x), t3);
    }
    __syncthreads();
}

template<int LA, int TWA>
__device__ void fft_dif_pass16(float2* Z, const float* C, int tid) {
    constexpr int qA = LA / 4, qB = LA / 16;
    constexpr int TWB = TWA + 2;
    const int p2 = tid & (qB - 1);
    float2 wA1[4], wA2[4], wA3[4];
    #pragma unroll
    for (int a = 0; a < 4; a++) {
        const int k = (p2 + a*qB) << TWA;
        wA1[a] = twc(C, k);
        wA2[a] = cmulf(wA1[a], wA1[a]);
        wA3[a] = cmulf(wA2[a], wA1[a]);
    }
    const int k2 = p2 << TWB;
    const float2 wB1 = twc(C, k2);
    const float2 wB2 = cmulf(wB1, wB1);
    const float2 wB3 = cmulf(wB2, wB1);
    #pragma unroll
    for (int half = 0; half < 2; half++) {
        const int g = tid + half * FFT_T;
        const int base = (g / qB) * LA + p2;
        float2 x[4][4];
        #pragma unroll
        for (int b = 0; b < 4; b++)
            #pragma unroll
            for (int a = 0; a < 4; a++)
                x[b][a] = Z[ZI(base + a*qB + b*qA)];
        #pragma unroll
        for (int a = 0; a < 4; a++) {
            float2 t0 = caddf(x[0][a], x[2][a]);
            float2 t1 = csubf(x[0][a], x[2][a]);
            float2 t2 = caddf(x[1][a], x[3][a]);
            float2 bd = csubf(x[1][a], x[3][a]);
            float2 t3 = make_float2(bd.y, -bd.x);
            x[0][a] = caddf(t0, t2);
            x[1][a] = cmulf(caddf(t1, t3), wA1[a]);
            x[2][a] = cmulf(csubf(t0, t2), wA2[a]);
            x[3][a] = cmulf(csubf(t1, t3), wA3[a]);
        }
        #pragma unroll
        for (int b = 0; b < 4; b++) {
            float2 t0 = caddf(x[b][0], x[b][2]);
            float2 t1 = csubf(x[b][0], x[b][2]);
            float2 t2 = caddf(x[b][1], x[b][3]);
            float2 bd = csubf(x[b][1], x[b][3]);
            float2 t3 = make_float2(bd.y, -bd.x);
            Z[ZI(base + 0*qB + b*qA)] = caddf(t0, t2);
            Z[ZI(base + 1*qB + b*qA)] = cmulf(caddf(t1, t3), wB1);
            Z[ZI(base + 2*qB + b*qA)] = cmulf(csubf(t0, t2), wB2);
            Z[ZI(base + 3*qB + b*qA)] = cmulf(csubf(t1, t3), wB3);
        }
    }
    __syncthreads();
}

__device__ void fft_dif_pass16_stash(float2* Z, const float* C,
                                     float2* __restrict__ Hs, int tid) {
    float2 wA1[4], wA2[4], wA3[4];
    #pragma unroll
    for (int a = 0; a < 4; a++) {
        const int k = a << 10;
        wA1[a] = twc(C, k);
        wA2[a] = cmulf(wA1[a], wA1[a]);
        wA3[a] = cmulf(wA2[a], wA1[a]);
    }
    #pragma unroll
    for (int half = 0; half < 2; half++) {
        const int g = tid + half * FFT_T;
        const int base = g * 16;
        const int kg = digrev4_10(g);
        float2 x[4][4];
        #pragma unroll
        for (int b = 0; b < 4; b++)
            #pragma unroll
            for (int a = 0; a < 4; a++)
                x[b][a] = Z[ZI(base + a + 4*b)];
        #pragma unroll
        for (int a = 0; a < 4; a++) {
            float2 t0 = caddf(x[0][a], x[2][a]);
            float2 t1 = csubf(x[0][a], x[2][a]);
            float2 t2 = caddf(x[1][a], x[3][a]);
            float2 bd = csubf(x[1][a], x[3][a]);
            float2 t3 = make_float2(bd.y, -bd.x);
            x[0][a] = caddf(t0, t2);
            x[1][a] = cmulf(caddf(t1, t3), wA1[a]);
            x[2][a] = cmulf(csubf(t0, t2), wA2[a]);
            x[3][a] = cmulf(csubf(t1, t3), wA3[a]);
        }
        #pragma unroll
        for (int b = 0; b < 4; b++) {
            float2 t0 = caddf(x[b][0], x[b][2]);
            float2 t1 = csubf(x[b][0], x[b][2]);
            float2 t2 = caddf(x[b][1], x[b][3]);
            float2 bd = csubf(x[b][1], x[b][3]);
            float2 t3 = make_float2(bd.y, -bd.x);
            const int k0 = kg + b * 1024;
            Hs[HsI(k0)]        = caddf(t0, t2);      // o=0
            Hs[HsI(k0 + 4096)] = caddf(t1, t3);      // o=1
            if (k0 == 0) Hs[HsI(8192)] = csubf(t0, t2);  // k=8192 edge
        }
    }
    __syncthreads();
}

__device__ void ifft_first_mult(float2* Z, const float2* __restrict__ Hs, int tid) {
    for (int b = tid; b < NFFT/4; b += FFT_T) {
        const int i0 = 4*b;
        const int kb = digrev4_14(i0);
        float2 zz[4];
        #pragma unroll
        for (int s2 = 0; s2 < 4; s2++) {
            const int k = kb + s2 * 4096;
            float2 H;
            if (k <= 8192) H = Hs[HsI(k)];
            else { const int kc = 16384 - k; H = Hs[HsI(kc)]; H.y = -H.y; }
            zz[s2] = cmulf(Z[ZI(i0 + s2)], H);
        }
        float2 t0 = caddf(zz[0], zz[2]), t1 = csubf(zz[0], zz[2]);
        float2 t2 = caddf(zz[1], zz[3]);
        float2 bd = csubf(zz[1], zz[3]);
        float2 t3 = make_float2(-bd.y, bd.x);
        Z[ZI(i0)]     = caddf(t0, t2);
        Z[ZI(i0 + 1)] = caddf(t1, t3);
        Z[ZI(i0 + 2)] = csubf(t0, t2);
        Z[ZI(i0 + 3)] = csubf(t1, t3);
    }
    __syncthreads();
}

template<int L1, int TW1>
__device__ void ifft_dit_pass16(float2* Z, const float* C, int tid) {
    constexpr int q1 = L1 / 4, L2 = 4 * L1;
    constexpr int TW2 = TW1 - 2;
    const int p = tid & (q1 - 1);
    const int k1 = p << TW1;
    const float2 u1 = twc(C, k1);
    const float2 u2 = cmulf(u1, u1);
    const float2 u3 = cmulf(u2, u1);
    float2 v1[4], v2[4], v3[4];
    #pragma unroll
    for (int a = 0; a < 4; a++) {
        const int kk = (p + a*q1) << TW2;
        v1[a] = twc(C, kk);
        v2[a] = cmulf(v1[a], v1[a]);
        v3[a] = cmulf(v2[a], v1[a]);
    }
    #pragma unroll
    for (int half = 0; half < 2; half++) {
        const int g = tid + half * FFT_T;
        const int base = (g / q1) * L2 + p;
        float2 x[4][4];
        #pragma unroll
        for (int b = 0; b < 4; b++)
            #pragma unroll
            for (int a = 0; a < 4; a++)
                x[b][a] = Z[ZI(base + a*q1 + b*L1)];
        #pragma unroll
        for (int b = 0; b < 4; b++) {
            float2 a0 = x[b][0];
            float2 a1 = cmulconjf(x[b][1], u1);
            float2 a2 = cmulconjf(x[b][2], u2);
            float2 a3 = cmulconjf(x[b][3], u3);
            float2 t0 = caddf(a0, a2), t1 = csubf(a0, a2);
            float2 t2 = caddf(a1, a3);
            float2 bd = csubf(a1, a3);
            float2 t3 = make_float2(-bd.y, bd.x);
            x[b][0] = caddf(t0, t2);
            x[b][1] = caddf(t1, t3);
            x[b][2] = csubf(t0, t2);
            x[b][3] = csubf(t1, t3);
        }
        #pragma unroll
        for (int a = 0; a < 4; a++) {
            float2 b0 = x[0][a];
            float2 b1 = cmulconjf(x[1][a], v1[a]);
            float2 b2 = cmulconjf(x[2][a], v2[a]);
            float2 b3 = cmulconjf(x[3][a], v3[a]);
            float2 t0 = caddf(b0, b2), t1 = csubf(b0, b2);
            float2 t2 = caddf(b1, b3);
            float2 bd = csubf(b1, b3);
            float2 t3 = make_float2(-bd.y, bd.x);
            Z[ZI(base + a*q1 + 0*L1)] = caddf(t0, t2);
            Z[ZI(base + a*q1 + 1*L1)] = caddf(t1, t3);
            Z[ZI(base + a*q1 + 2*L1)] = csubf(t0, t2);
            Z[ZI(base + a*q1 + 3*L1)] = csubf(t1, t3);
        }
    }
    __syncthreads();
}

__global__ __launch_bounds__(FFT_T, 1) void fft_conv_kernel(
    const float* __restrict__ sw, const float* __restrict__ sb)
{
    extern __shared__ float2 sm[];
    float2* Z  = sm;
    float2* Hs = sm + Z_PAD_SZ;
    float*  C  = (float*)(sm + Z_PAD_SZ + HS_PAD_SZ);
    const int c   = blockIdx.x;
    const int tid = threadIdx.x;

    for (int k = tid; k <= 4096; k += FFT_T)
        C[k] = cosf(3.834951969714103e-4f * (float)k);   // cos(2*pi*k/16384)
    __syncthreads();

    // ---- filter FFT; final pass writes half-spectrum straight to smem Hs ----
    fft_dif_first(Z, C, g_COEFt + (size_t)c * LSEQ, tid);
    fft_dif_pass16<4096, 2>(Z, C, tid);
    fft_dif_pass16<256, 6>(Z, C, tid);
    fft_dif_pass16_stash(Z, C, Hs, tid);

    // ---- v FFT with fused depthwise short-conv ----
    const float w0 = sw[c*3], w1 = sw[c*3+1], w2 = sw[c*3+2], cb = sb[c];
    fft_dif_first_conv(Z, C, g_Vcm + (size_t)c * MTOT, w0, w1, w2, cb, tid);
    fft_dif_pass16<4096, 2>(Z, C, tid);
    fft_dif_pass16<256, 6>(Z, C, tid);
    fft_dif_pass16<16, 10>(Z, C, tid);

    // ---- inverse: multiply (from smem half-spectrum) fused into len-4 stage
    ifft_first_mult(Z, Hs, tid);
    ifft_dit_pass16<16, 10>(Z, C, tid);
    ifft_dit_pass16<256, 6>(Z, C, tid);

    // ---- final paired pass fused with gate + fp16 store ([c][m]) ----
    const float* x2 = g_X2t + (size_t)c * MTOT;
    __half* go = g_Gf + (size_t)c * MTOT;
    const float scale = 1.0f / (float)NFFT;
    for (int p = tid; p < 1024; p += FFT_T) {
        float2 x[4][4];
        #pragma unroll
        for (int b = 0; b < 4; b++)
            #pragma unroll
            for (int a = 0; a < 4; a++)
                x[b][a] = Z[ZI(p + a*1024 + b*4096)];
        const float2 u1 = twc(C, p << 2);
        const float2 u2 = cmulf(u1, u1);
        const float2 u3 = cmulf(u2, u1);
        #pragma unroll
        for (int b = 0; b < 4; b++) {
            float2 a0 = x[b][0];
            float2 a1 = cmulconjf(x[b][1], u1);
            float2 a2 = cmulconjf(x[b][2], u2);
            float2 a3 = cmulconjf(x[b][3], u3);
            float2 t0 = caddf(a0, a2), t1 = csubf(a0, a2);
            float2 t2 = caddf(a1, a3);
            float2 bd = csubf(a1, a3);
            float2 t3 = make_float2(-bd.y, bd.x);
            x[b][0] = caddf(t0, t2);
            x[b][1] = caddf(t1, t3);
            x[b][2] = csubf(t0, t2);
            x[b][3] = csubf(t1, t3);
        }
        #pragma unroll
        for (int a = 0; a < 4; a++) {
            const int k2 = p + a*1024;
            const float2 q1 = twc(C, k2);
            const float2 q2 = cmulf(q1, q1);
            const float2 q3 = cmulf(q2, q1);
            float2 b0 = x[0][a];
            float2 b1 = cmulconjf(x[1][a], q1);
            float2 b2 = cmulconjf(x[2][a], q2);
            float2 b3 = cmulconjf(x[3][a], q3);
            float2 t0 = caddf(b0, b2), t1 = csubf(b0, b2);
            float2 t2 = caddf(b1, b3);
            float2 bd = csubf(b1, b3);
            float2 t3 = make_float2(-bd.y, bd.x);
            float2 o0 = caddf(t0, t2);         // time t
            float2 o1 = caddf(t1, t3);         // time t+4096
            const int t = p + a*1024;
            go[t]               = __float2half(x2[t]               * (o0.x * scale));
            go[LSEQ + t]        = __float2half(x2[LSEQ + t]        * (o0.y * scale));
            go[t + 4096]        = __float2half(x2[t + 4096]        * (o1.x * scale));
            go[LSEQ + t + 4096] = __float2half(x2[LSEQ + t + 4096] * (o1.y * scale));
        }
    }
}

// ============================================================================
extern "C" void kernel_launch(void* const* d_in, const int* in_sizes, int n_in,
                              void* d_out, int out_size)
{
    const float* x   = (const float*)d_in[0];
    const float* ipw = (const float*)d_in[1];
    const float* ipb = (const float*)d_in[2];
    const float* sw  = (const float*)d_in[3];
    const float* sb  = (const float*)d_in[4];
    const float* fw1 = (const float*)d_in[5];
    const float* fb1 = (const float*)d_in[6];
    const float* fw2 = (const float*)d_in[7];
    const float* fb2 = (const float*)d_in[8];
    const float* fw3 = (const float*)d_in[9];
    const float* fb3 = (const float*)d_in[10];
    const float* ow  = (const float*)d_in[11];
    const float* ob  = (const float*)d_in[12];
    float* out = (float*)d_out;

    cudaFuncSetAttribute(fft_conv_kernel,
                         cudaFuncAttributeMaxDynamicSharedMemorySize, FFT_SMEM);
    cudaFuncSetAttribute(gemm0_coef,
                         cudaFuncAttributeMaxDynamicSharedMemorySize, GSM_BYTES);
    cudaFuncSetAttribute(gemm_out_tc,
                         cudaFuncAttributeMaxDynamicSharedMemorySize, GSM_BYTES);

    // 1) one prep kernel: x fp16 + weight gathers + filter MLP h2
    prep_split<<<22528, 256>>>(x, ipw, ow, fw1, fb1, fw2, fb2);
    // 2) merged launch: coef GEMM tiles (first) + in_proj GEMM tiles (fp16)
    gemm0_coef<<<NCOEF_B + 2048, 256, GSM_BYTES>>>(ipb, fw3, fb3);
    // 3) FFT long conv (fused short-conv, stash, mult, gate, fp16 out)
    fft_conv_kernel<<<CH, FFT_T, FFT_SMEM>>>(sw, sb);
    // 4) out GEMM (fp16) reads gated activations k-major via ldmatrix.trans
    gemm_out_tc<<<dim3(8, 128), 256, GSM_BYTES>>>(ob, out);
}

// round 16
// speedup vs baseline: 2.6167x; 1.0988x over previous
#include <cuda_runtime.h>
#include <cuda_fp16.h>
#include <math.h>
#include <stdint.h>

// Problem constants
#define LSEQ   8192
#define NFFT   16384
#define CH     1024
#define BATCH  2
#define MTOT   (BATCH*LSEQ)      // 16384 rows

// ---------------- scratch (device globals; no allocations allowed) ----------
__device__ float g_Vcm  [CH*MTOT];     // in_proj v branch, channel-major [c][m]
__device__ float g_X2t  [CH*MTOT];     // x2 branch, channel-major [c][m]
__device__ float g_H2   [LSEQ*128];    // filter MLP hidden (L x 128)
__device__ float g_COEFt[CH*LSEQ];     // filter coefs order-1, channel-major [c][l]

// fp16 operands for the tensor-core GEMMs (single-term)
__device__ __half g_Xf [MTOT*CH];      // x, [m][k]
__device__ __half g_Gf [CH*MTOT];      // gated, [c][m] (k-major)
__device__ __half g_Wif[2048*CH];      // in_proj cols, [n][k]
__device__ __half g_Wof[CH*CH];        // out_w^T, [n][k]

// ---------------- generic helpers -------------------------------------------
__device__ __forceinline__ float gelu_exact(float x) {
    return 0.5f * x * (1.0f + erff(x * 0.70710678118654752f));
}
__device__ __forceinline__ float2 cmulf(float2 a, float2 b) {
    return make_float2(a.x*b.x - a.y*b.y, a.x*b.y + a.y*b.x);
}
__device__ __forceinline__ float2 cmulconjf(float2 a, float2 w) {  // a * conj(w)
    return make_float2(a.x*w.x + a.y*w.y, a.y*w.x - a.x*w.y);
}
__device__ __forceinline__ float2 caddf(float2 a, float2 b) {
    return make_float2(a.x + b.x, a.y + b.y);
}
__device__ __forceinline__ float2 csubf(float2 a, float2 b) {
    return make_float2(a.x - b.x, a.y - b.y);
}
__device__ __forceinline__ uint32_t smem_u32(const void* p) {
    uint32_t a;
    asm("{ .reg .u64 t; cvta.to.shared.u64 t, %1; cvt.u32.u64 %0, t; }"
        : "=r"(a) : "l"(p));
    return a;
}

#define CP_ASYNC16(sm, gp) \
    asm volatile("cp.async.cg.shared.global [%0], [%1], 16;" \
                 :: "r"(sm), "l"(__cvta_generic_to_global(gp)) : "memory")
#define CP_COMMIT() asm volatile("cp.async.commit_group;" ::: "memory")
#define CP_WAIT0()  asm volatile("cp.async.wait_group 0;" ::: "memory")

#define LDSM4(r0, r1, r2, r3, ad) \
    asm volatile("ldmatrix.sync.aligned.m8n8.x4.shared.b16 {%0,%1,%2,%3}, [%4];" \
                 : "=r"(r0), "=r"(r1), "=r"(r2), "=r"(r3) : "r"(ad))
#define LDSM4T(r0, r1, r2, r3, ad) \
    asm volatile("ldmatrix.sync.aligned.m8n8.x4.trans.shared.b16 {%0,%1,%2,%3}, [%4];" \
                 : "=r"(r0), "=r"(r1), "=r"(r2), "=r"(r3) : "r"(ad))

__device__ __forceinline__ void mma_f16(float* c, const uint32_t* a, const uint32_t* b) {
    asm volatile("mma.sync.aligned.m16n8k16.row.col.f32.f16.f16.f32 "
        "{%0,%1,%2,%3}, {%4,%5,%6,%7}, {%8,%9}, {%0,%1,%2,%3};"
        : "+f"(c[0]), "+f"(c[1]), "+f"(c[2]), "+f"(c[3])
        : "r"(a[0]), "r"(a[1]), "r"(a[2]), "r"(a[3]), "r"(b[0]), "r"(b[1]));
}

// ============================================================================
// prep_split: one kernel, four roles by block range. (frozen)
// ============================================================================
__global__ __launch_bounds__(256) void prep_split(
    const float* __restrict__ x, const float* __restrict__ ipw,
    const float* __restrict__ ow,
    const float* __restrict__ fw1, const float* __restrict__ fb1,
    const float* __restrict__ fw2, const float* __restrict__ fb2)
{
    const int b   = blockIdx.x;
    const int tid = threadIdx.x;

    if (b < 16384) {
        size_t i = ((size_t)b * 256 + tid) * 4;
        float4 v = *(const float4*)&x[i];
        *(__half2*)&g_Xf[i]   = __floats2half2_rn(v.x, v.y);
        *(__half2*)&g_Xf[i+2] = __floats2half2_rn(v.z, v.w);
        return;
    }

    if (b < 17408) {
        __shared__ float s[32][97];
        const int bid2 = b - 16384;
        const int c0 = (bid2 & 31) * 32;
        const int k0 = (bid2 >> 5) * 32;
        for (int idx = tid; idx < 32*96; idx += 256) {
            const int r = idx / 96, cc = idx % 96;
            s[r][cc] = ipw[(size_t)(k0 + r) * 3072 + 3*c0 + cc];
        }
        __syncthreads();
        const int dc = tid >> 3;
        const int kq = (tid & 7) * 4;
        const int c  = c0 + dc;
        const size_t ov = (size_t)c * 1024 + k0 + kq;
        const size_t ox = (size_t)(1024 + c) * 1024 + k0 + kq;
        *(__half2*)&g_Wif[ov]   = __floats2half2_rn(s[kq+0][3*dc], s[kq+1][3*dc]);
        *(__half2*)&g_Wif[ov+2] = __floats2half2_rn(s[kq+2][3*dc], s[kq+3][3*dc]);
        *(__half2*)&g_Wif[ox]   = __floats2half2_rn(s[kq+0][3*dc+2], s[kq+1][3*dc+2]);
        *(__half2*)&g_Wif[ox+2] = __floats2half2_rn(s[kq+2][3*dc+2], s[kq+3][3*dc+2]);
        return;
    }

    if (b < 18432) {
        __shared__ float s[32][33];
        const int bid2 = b - 17408;
        const int c0 = (bid2 & 31) * 32;
        const int k0 = (bid2 >> 5) * 32;
        const int tx  = tid & 31;
        const int ty0 = tid >> 5;            // 0..7
        #pragma unroll
        for (int rr = 0; rr < 4; rr++) {
            const int r = ty0 + rr * 8;
            s[r][tx] = ow[(size_t)(k0 + r) * CH + c0 + tx];
        }
        __syncthreads();
        #pragma unroll
        for (int rr = 0; rr < 4; rr++) {
            const int ty = ty0 + rr * 8;
            g_Wof[(size_t)(c0 + ty) * 1024 + k0 + tx] = __float2half(s[tx][ty]);
        }
        return;
    }

    {
        // filter MLP: 2 sequence positions per CTA
        __shared__ float h1s[2][64];
        const int lb  = (b - 18432) * 2;
        const int sub = tid >> 7;            // 0/1
        const int t   = tid & 127;
        const int l   = lb + sub;
        const float pos = (float)l / (float)(LSEQ - 1);
        if (t < 64) h1s[sub][t] = gelu_exact(pos * fw1[t] + fb1[t]);
        __syncthreads();
        float s = fb2[t];
        #pragma unroll 8
        for (int j = 0; j < 64; j++) s += h1s[sub][j] * fw2[j*128 + t];
        g_H2[(size_t)l*128 + t] = gelu_exact(s);
    }
}

// ============================================================================
// gemm0_coef: merged launch (frozen).
// ============================================================================
#define GSM_BYTES 65536
#define NCOEF_B   512

__global__ __launch_bounds__(256, 2) void gemm0_coef(
    const float* __restrict__ bias,
    const float* __restrict__ fw3, const float* __restrict__ fb3)
{
    extern __shared__ char dsm[];
    const int tid = threadIdx.x;

    if (blockIdx.x < NCOEF_B) {
        float* As    = (float*)dsm;               // [8][128]
        float* Bs    = As + 8*128;                // [8][128]
        float* stage = Bs + 8*128;                // [128*65]
        const int bid = blockIdx.x;
        const int tx = tid & 15, ty = tid >> 4;
        const int m0 = (bid >> 3) * 128;
        const int n0 = (bid & 7) * 128;

        float acc[8][8];
        #pragma unroll
        for (int i = 0; i < 8; i++)
            #pragma unroll
            for (int j = 0; j < 8; j++) acc[i][j] = 0.f;

        const int arow = tid >> 1, akq = (tid & 1) * 4;
        const int bn = tid & 127;
        const int jm = 2 * (n0 + bn) + 1;
        const int kk0 = (tid >> 7) * 4;

        for (int k0 = 0; k0 < 128; k0 += 8) {
            float4 av = *(const float4*)&g_H2[(size_t)(m0 + arow) * 128 + k0 + akq];
            As[(akq+0)*128 + arow] = av.x; As[(akq+1)*128 + arow] = av.y;
            As[(akq+2)*128 + arow] = av.z; As[(akq+3)*128 + arow] = av.w;
            #pragma unroll
            for (int r = 0; r < 4; r++)
                Bs[(kk0 + r)*128 + bn] = fw3[(size_t)(k0 + kk0 + r) * 2048 + jm];
            __syncthreads();
            #pragma unroll
            for (int kk = 0; kk < 8; kk++) {
                float a[8], bb[8];
                #pragma unroll
                for (int i = 0; i < 8; i++) a[i] = As[kk*128 + ty*8 + i];
                #pragma unroll
                for (int j = 0; j < 8; j++) bb[j] = Bs[kk*128 + tx*8 + j];
                #pragma unroll
                for (int i = 0; i < 8; i++)
                    #pragma unroll
                    for (int j = 0; j < 8; j++) acc[i][j] += a[i] * bb[j];
            }
            __syncthreads();
        }

        float bo[8];
        #pragma unroll
        for (int j = 0; j < 8; j++) bo[j] = fb3[2*(n0 + tx*8 + j) + 1];

        #pragma unroll
        for (int h = 0; h < 2; h++) {
            __syncthreads();
            if ((tx >> 3) == h) {
                #pragma unroll
                for (int i = 0; i < 8; i++)
                    #pragma unroll
                    for (int j = 0; j < 8; j++)
                        stage[(ty*8 + i) * 65 + (tx & 7) * 8 + j] = acc[i][j] + bo[j];
            }
            __syncthreads();
            const int cl  = tid >> 2;
            const int lch = (tid & 3) << 5;
            const int c   = n0 + h * 64 + cl;
            float* dst = g_COEFt + (size_t)c * LSEQ + m0 + lch;
            #pragma unroll
            for (int j = 0; j < 32; j += 4) {
                float4 o = make_float4(stage[(lch+j)*65   + cl],
                                       stage[(lch+j+1)*65 + cl],
                                       stage[(lch+j+2)*65 + cl],
                                       stage[(lch+j+3)*65 + cl]);
                *(float4*)&dst[j] = o;
            }
        }
        return;
    }

    // ---------------- in_proj GEMM (fp16 single-term, frozen) ----------------
    const uint32_t sb  = smem_u32(dsm);
    const uint32_t sA = sb, sB = sb + 16384;
    const int lane = tid & 31;
    const int wid  = tid >> 5;
    const int wm   = wid >> 1;
    const int wn   = wid & 1;
    const int gbid = blockIdx.x - NCOEF_B;
    const int bx   = gbid & 15;
    const int m0   = (gbid >> 4) * 128;
    const int n0   = bx * 128;

    float acc[2][8][4];
    #pragma unroll
    for (int i = 0; i < 2; i++)
        #pragma unroll
        for (int j = 0; j < 8; j++)
            #pragma unroll
            for (int q = 0; q < 4; q++) acc[i][j][q] = 0.f;

    for (int it = 0; it < 16; ++it) {
        const size_t kc0 = (size_t)it * 64;
        #pragma unroll
        for (int u = 0; u < 4; u++) {
            const int s = tid + u * 256;
            const int row = s >> 3, seg = s & 7;
            const uint32_t so = (uint32_t)(row * 128 + ((seg * 16) ^ ((row & 7) << 4)));
            const size_t ga = (size_t)(m0 + row) * 1024 + kc0 + seg * 8;
            const size_t gb = (size_t)(n0 + row) * 1024 + kc0 + seg * 8;
            CP_ASYNC16(sA + so, g_Xf + ga);
            CP_ASYNC16(sB + so, g_Wif + gb);
        }
        CP_COMMIT();
        CP_WAIT0();
        __syncthreads();

        #pragma unroll
        for (int ks = 0; ks < 4; ks++) {
            uint32_t ah[2][4];
            #pragma unroll
            for (int mt = 0; mt < 2; mt++) {
                const int row = wm * 32 + mt * 16 + (lane & 15);
                const uint32_t r4 = (row & 7) << 4;
                const uint32_t cb = (uint32_t)(ks * 32 + ((lane >> 4) << 4));
                const uint32_t ad = sA + row * 128 + (cb ^ r4);
                LDSM4(ah[mt][0], ah[mt][1], ah[mt][2], ah[mt][3], ad);
            }
            uint32_t bh[8][2];
            #pragma unroll
            for (int nt2 = 0; nt2 < 4; nt2++) {
                const int n = wn * 64 + nt2 * 16 + (lane & 7) + ((lane >> 4) << 3);
                const uint32_t r4 = (n & 7) << 4;
                const uint32_t cb = (uint32_t)(ks * 32 + (((lane >> 3) & 1) << 4));
                const uint32_t ad = sB + n * 128 + (cb ^ r4);
                LDSM4(bh[2*nt2][0], bh[2*nt2][1], bh[2*nt2+1][0], bh[2*nt2+1][1], ad);
            }
            #pragma unroll
            for (int mt = 0; mt < 2; mt++)
                #pragma unroll
                for (int nt = 0; nt < 8; nt++)
                    mma_f16(acc[mt][nt], ah[mt], bh[nt]);
        }
        __syncthreads();
    }

    {
        float* stage = (float*)dsm;          // [128][65] floats = 33 KB
        const bool is_v = (bx < 8);
        const int cbase = (is_v ? bx : bx - 8) * 128;
        #pragma unroll
        for (int h = 0; h < 2; h++) {
            __syncthreads();
            if (wn == h) {
                #pragma unroll
                for (int mt = 0; mt < 2; mt++) {
                    const int rl = wm * 32 + mt * 16 + (lane >> 2);
                    #pragma unroll
                    for (int nt = 0; nt < 8; nt++) {
                        const int cl = nt * 8 + ((lane & 3) << 1);
                        stage[rl * 65 + cl]           = acc[mt][nt][0];
                        stage[rl * 65 + cl + 1]       = acc[mt][nt][1];
                        stage[(rl + 8) * 65 + cl]     = acc[mt][nt][2];
                        stage[(rl + 8) * 65 + cl + 1] = acc[mt][nt][3];
                    }
                }
            }
            __syncthreads();
            const int cl  = tid >> 2;
            const int mch = (tid & 3) << 5;
            const int c   = cbase + h * 64 + cl;
            const float b = is_v ? bias[3*c] : bias[3*c + 2];
            float* dst = (is_v ? g_Vcm : g_X2t) + (size_t)c * MTOT + m0 + mch;
            #pragma unroll
            for (int j = 0; j < 32; j += 4) {
                float4 o = make_float4(stage[(mch+j)*65   + cl] + b,
                                       stage[(mch+j+1)*65 + cl] + b,
                                       stage[(mch+j+2)*65 + cl] + b,
                                       stage[(mch+j+3)*65 + cl] + b);
                *(float4*)&dst[j] = o;
            }
        }
    }
}

// ============================================================================
// out-proj GEMM (fp16 single-term; frozen)
// ============================================================================
__global__ __launch_bounds__(256, 2) void gemm_out_tc(
    const float* __restrict__ bias, float* __restrict__ out)
{
    extern __shared__ char dsm[];
    const uint32_t sb  = smem_u32(dsm);
    const uint32_t sA = sb, sB = sb + 32768;

    const int tid  = threadIdx.x;
    const int lane = tid & 31;
    const int wid  = tid >> 5;
    const int wm   = wid >> 1;
    const int wn   = wid & 1;
    const int m0   = blockIdx.y * 128;
    const int n0   = blockIdx.x * 128;

    float acc[2][8][4];
    #pragma unroll
    for (int i = 0; i < 2; i++)
        #pragma unroll
        for (int j = 0; j < 8; j++)
            #pragma unroll
            for (int q = 0; q < 4; q++) acc[i][j][q] = 0.f;

    for (int it = 0; it < 16; ++it) {
        const size_t kc0 = (size_t)it * 64;
        #pragma unroll
        for (int u = 0; u < 4; u++) {
            const int s = tid + u * 256;
            const int row = s >> 4, seg = s & 15;
            const uint32_t so = (uint32_t)(row * 256 + ((seg * 16) ^ ((row & 7) << 4)));
            const size_t ga = (size_t)(kc0 + row) * MTOT + m0 + seg * 8;
            CP_ASYNC16(sA + so, g_Gf + ga);
        }
        #pragma unroll
        for (int u = 0; u < 4; u++) {
            const int s = tid + u * 256;
            const int row = s >> 3, seg = s & 7;
            const uint32_t so = (uint32_t)(row * 128 + ((seg * 16) ^ ((row & 7) << 4)));
            const size_t gb = (size_t)(n0 + row) * 1024 + kc0 + seg * 8;
            CP_ASYNC16(sB + so, g_Wof + gb);
        }
        CP_COMMIT();
        CP_WAIT0();
        __syncthreads();

        #pragma unroll
        for (int ks = 0; ks < 4; ks++) {
            uint32_t ah[2][4];
            #pragma unroll
            for (int mt = 0; mt < 2; mt++) {
                const int rowk = ks * 16 + (lane & 7) + ((lane >> 4) << 3);
                const int mcol = wm * 32 + mt * 16 + (((lane >> 3) & 1) << 3);
                const uint32_t ad = sA + rowk * 256 +
                    (((uint32_t)(2 * mcol)) ^ ((uint32_t)(rowk & 7) << 4));
                LDSM4T(ah[mt][0], ah[mt][1], ah[mt][2], ah[mt][3], ad);
            }
            uint32_t bh[8][2];
            #pragma unroll
            for (int nt2 = 0; nt2 < 4; nt2++) {
                const int n = wn * 64 + nt2 * 16 + (lane & 7) + ((lane >> 4) << 3);
                const uint32_t r4 = (n & 7) << 4;
                const uint32_t cb = (uint32_t)(ks * 32 + (((lane >> 3) & 1) << 4));
                const uint32_t ad = sB + n * 128 + (cb ^ r4);
                LDSM4(bh[2*nt2][0], bh[2*nt2][1], bh[2*nt2+1][0], bh[2*nt2+1][1], ad);
            }
            #pragma unroll
            for (int mt = 0; mt < 2; mt++)
                #pragma unroll
                for (int nt = 0; nt < 8; nt++)
                    mma_f16(acc[mt][nt], ah[mt], bh[nt]);
        }
        __syncthreads();
    }

    #pragma unroll
    for (int mt = 0; mt < 2; mt++) {
        const int r = m0 + wm * 32 + mt * 16 + (lane >> 2);
        #pragma unroll
        for (int nt = 0; nt < 8; nt++) {
            const int c = n0 + wn * 64 + nt * 8 + ((lane & 3) << 1);
            const float b0 = bias[c], b1 = bias[c + 1];
            *(float2*)&out[(size_t)r * CH + c] =
                make_float2(acc[mt][nt][0] + b0, acc[mt][nt][1] + b1);
            *(float2*)&out[(size_t)(r + 8) * CH + c] =
                make_float2(acc[mt][nt][2] + b0, acc[mt][nt][3] + b1);
        }
    }
}

// ============================================================================
// FFT convolution — radix-16 passes, padded smem, smem Hermitian half-
// spectrum.  NOW 1024 THREADS with register-diet twiddle chains:
// one group per thread per pass; twiddles via geometric chain (2 float2 held).
// ============================================================================
#define FFT_T    1024
#define ZI(i) ((i) + ((i) >> 4))
#define Z_PAD_SZ  17408                 // float2
#define HS_PAD_SZ 8232                  // float2
#define COS_SZ    4104                  // floats
#define HsI(k) ((k) + ((k) >> 8))
#define FFT_SMEM ((Z_PAD_SZ + HS_PAD_SZ) * 8 + COS_SZ * 4)

__device__ __forceinline__ int digrev4_14(int j) {
    unsigned r = __brev((unsigned)j) >> 18;
    return (int)(((r & 0x2AAAu) >> 1) | ((r & 0x1555u) << 1));
}
__device__ __forceinline__ int digrev4_10(int g) {
    unsigned r = __brev((unsigned)g) >> 22;
    return (int)(((r & 0x155u) << 1) | ((r >> 1) & 0x155u));
}
__device__ __forceinline__ float2 twc(const float* __restrict__ C, int k) {
    return make_float2(C[k], -C[4096 - k]);
}
__device__ __forceinline__ float conv3(const float* __restrict__ q, int l,
                                       float w0, float w1, float w2, float b) {
    float s = w1 * q[l] + b;
    if (l > 0)        s += w0 * q[l-1];
    if (l < LSEQ - 1) s += w2 * q[l+1];
    return s;
}

__device__ void fft_dif_first(float2* Z, const float* C,
                              const float* __restrict__ re, int tid) {
    for (int p = tid; p < 4096; p += FFT_T) {
        float2 a = make_float2(re[p], 0.f);
        float2 b = make_float2(re[p + 4096], 0.f);
        float2 w1 = twc(C, p);
        float2 w2 = cmulf(w1, w1);
        float2 w3 = cmulf(w2, w1);
        Z[ZI(p)]         = caddf(a, b);
        Z[ZI(p + 4096)]  = cmulf(make_float2(a.x + b.y, a.y - b.x), w1);
        Z[ZI(p + 8192)]  = cmulf(csubf(a, b),                       w2);
        Z[ZI(p + 12288)] = cmulf(make_float2(a.x - b.y, a.y + b.x), w3);
    }
    __syncthreads();
}

__device__ void fft_dif_first_conv(float2* Z, const float* C,
                                   const float* __restrict__ v0,
                                   float w0, float w1, float w2, float cb, int tid) {
    const float* v1 = v0 + LSEQ;
    for (int p = tid; p < 4096; p += FFT_T) {
        float2 a = make_float2(conv3(v0, p, w0, w1, w2, cb),
                               conv3(v1, p, w0, w1, w2, cb));
        float2 b = make_float2(conv3(v0, p + 4096, w0, w1, w2, cb),
                               conv3(v1, p + 4096, w0, w1, w2, cb));
        float2 t1 = twc(C, p);
        float2 t2 = cmulf(t1, t1);
        float2 t3 = cmulf(t2, t1);
        Z[ZI(p)]         = caddf(a, b);
        Z[ZI(p + 4096)]  = cmulf(make_float2(a.x + b.y, a.y - b.x), t1);
        Z[ZI(p + 8192)]  = cmulf(csubf(a, b),                       t2);
        Z[ZI(p + 12288)] = cmulf(make_float2(a.x - b.y, a.y + b.x), t3);
    }
    __syncthreads();
}

// Forward DIF paired radix-16 pass.  One group per thread (FFT_T == NFFT/16).
// Stage-A twiddles via geometric chain: w((p2+a*qB)<<TWA) = wA * wstep^a.
template<int LA, int TWA>
__device__ void fft_dif_pass16(float2* Z, const float* C, int tid) {
    constexpr int qA = LA / 4, qB = LA / 16;
    constexpr int TWB = TWA + 2;
    const int p2   = tid & (qB - 1);
    const int base = (tid / qB) * LA + p2;
    float2 x[4][4];
    #pragma unroll
    for (int b = 0; b < 4; b++)
        #pragma unroll
        for (int a = 0; a < 4; a++)
            x[b][a] = Z[ZI(base + a*qB + b*qA)];
    float2 wA = twc(C, p2 << TWA);
    const float2 wstep = twc(C, qB << TWA);
    #pragma unroll
    for (int a = 0; a < 4; a++) {
        const float2 wA2 = cmulf(wA, wA);
        const float2 wA3 = cmulf(wA2, wA);
        float2 t0 = caddf(x[0][a], x[2][a]);
        float2 t1 = csubf(x[0][a], x[2][a]);
        float2 t2 = caddf(x[1][a], x[3][a]);
        float2 bd = csubf(x[1][a], x[3][a]);
        float2 t3 = make_float2(bd.y, -bd.x);
        x[0][a] = caddf(t0, t2);
        x[1][a] = cmulf(caddf(t1, t3), wA);
        x[2][a] = cmulf(csubf(t0, t2), wA2);
        x[3][a] = cmulf(csubf(t1, t3), wA3);
        if (a < 3) wA = cmulf(wA, wstep);
    }
    const float2 wB1 = twc(C, p2 << TWB);
    const float2 wB2 = cmulf(wB1, wB1);
    const float2 wB3 = cmulf(wB2, wB1);
    #pragma unroll
    for (int b = 0; b < 4; b++) {
        float2 t0 = caddf(x[b][0], x[b][2]);
        float2 t1 = csubf(x[b][0], x[b][2]);
        float2 t2 = caddf(x[b][1], x[b][3]);
        float2 bd = csubf(x[b][1], x[b][3]);
        float2 t3 = make_float2(bd.y, -bd.x);
        Z[ZI(base + 0*qB + b*qA)] = caddf(t0, t2);
        Z[ZI(base + 1*qB + b*qA)] = cmulf(caddf(t1, t3), wB1);
        Z[ZI(base + 2*qB + b*qA)] = cmulf(csubf(t0, t2), wB2);
        Z[ZI(base + 3*qB + b*qA)] = cmulf(csubf(t1, t3), wB3);
    }
    __syncthreads();
}

// Final FILTER pass (LA=16, qB=1, stage-B twiddles=1) fused with Hs stash.
__device__ void fft_dif_pass16_stash(float2* Z, const float* C,
                                     float2* __restrict__ Hs, int tid) {
    const int base = tid * 16;
    const int kg = digrev4_10(tid);
    float2 x[4][4];
    #pragma unroll
    for (int b = 0; b < 4; b++)
        #pragma unroll
        for (int a = 0; a < 4; a++)
            x[b][a] = Z[ZI(base + a + 4*b)];
    float2 wA = make_float2(1.f, 0.f);
    const float2 wstep = twc(C, 1 << 10);
    #pragma unroll
    for (int a = 0; a < 4; a++) {
        const float2 wA2 = cmulf(wA, wA);
        const float2 wA3 = cmulf(wA2, wA);
        float2 t0 = caddf(x[0][a], x[2][a]);
        float2 t1 = csubf(x[0][a], x[2][a]);
        float2 t2 = caddf(x[1][a], x[3][a]);
        float2 bd = csubf(x[1][a], x[3][a]);
        float2 t3 = make_float2(bd.y, -bd.x);
        x[0][a] = caddf(t0, t2);
        x[1][a] = cmulf(caddf(t1, t3), wA);
        x[2][a] = cmulf(csubf(t0, t2), wA2);
        x[3][a] = cmulf(csubf(t1, t3), wA3);
        if (a < 3) wA = cmulf(wA, wstep);
    }
    #pragma unroll
    for (int b = 0; b < 4; b++) {
        float2 t0 = caddf(x[b][0], x[b][2]);
        float2 t1 = csubf(x[b][0], x[b][2]);
        float2 t2 = caddf(x[b][1], x[b][3]);
        float2 bd = csubf(x[b][1], x[b][3]);
        float2 t3 = make_float2(bd.y, -bd.x);
        const int k0 = kg + b * 1024;
        Hs[HsI(k0)]        = caddf(t0, t2);      // o=0
        Hs[HsI(k0 + 4096)] = caddf(t1, t3);      // o=1
        if (k0 == 0) Hs[HsI(8192)] = csubf(t0, t2);  // k=8192 edge
    }
    __syncthreads();
}

__device__ void ifft_first_mult(float2* Z, const float2* __restrict__ Hs, int tid) {
    for (int b = tid; b < NFFT/4; b += FFT_T) {
        const int i0 = 4*b;
        const int kb = digrev4_14(i0);
        float2 zz[4];
        #pragma unroll
        for (int s2 = 0; s2 < 4; s2++) {
            const int k = kb + s2 * 4096;
            float2 H;
            if (k <= 8192) H = Hs[HsI(k)];
            else { const int kc = 16384 - k; H = Hs[HsI(kc)]; H.y = -H.y; }
            zz[s2] = cmulf(Z[ZI(i0 + s2)], H);
        }
        float2 t0 = caddf(zz[0], zz[2]), t1 = csubf(zz[0], zz[2]);
        float2 t2 = caddf(zz[1], zz[3]);
        float2 bd = csubf(zz[1], zz[3]);
        float2 t3 = make_float2(-bd.y, bd.x);
        Z[ZI(i0)]     = caddf(t0, t2);
        Z[ZI(i0 + 1)] = caddf(t1, t3);
        Z[ZI(i0 + 2)] = csubf(t0, t2);
        Z[ZI(i0 + 3)] = csubf(t1, t3);
    }
    __syncthreads();
}

// Inverse DIT paired radix-16 pass.  One group per thread; stage-2 twiddles
// via geometric chain.
template<int L1, int TW1>
__device__ void ifft_dit_pass16(float2* Z, const float* C, int tid) {
    constexpr int q1 = L1 / 4, L2 = 4 * L1;
    constexpr int TW2 = TW1 - 2;
    const int p    = tid & (q1 - 1);
    const int base = (tid / q1) * L2 + p;
    float2 x[4][4];
    #pragma unroll
    for (int b = 0; b < 4; b++)
        #pragma unroll
        for (int a = 0; a < 4; a++)
            x[b][a] = Z[ZI(base + a*q1 + b*L1)];
    {
        const float2 u1 = twc(C, p << TW1);
        const float2 u2 = cmulf(u1, u1);
        const float2 u3 = cmulf(u2, u1);
        #pragma unroll
        for (int b = 0; b < 4; b++) {
            float2 a0 = x[b][0];
            float2 a1 = cmulconjf(x[b][1], u1);
            float2 a2 = cmulconjf(x[b][2], u2);
            float2 a3 = cmulconjf(x[b][3], u3);
            float2 t0 = caddf(a0, a2), t1 = csubf(a0, a2);
            float2 t2 = caddf(a1, a3);
            float2 bd = csubf(a1, a3);
            float2 t3 = make_float2(-bd.y, bd.x);
            x[b][0] = caddf(t0, t2);
            x[b][1] = caddf(t1, t3);
            x[b][2] = csubf(t0, t2);
            x[b][3] = csubf(t1, t3);
        }
    }
    float2 v = twc(C, p << TW2);
    const float2 vstep = twc(C, q1 << TW2);
    #pragma unroll
    for (int a = 0; a < 4; a++) {
        const float2 v2 = cmulf(v, v);
        const float2 v3 = cmulf(v2, v);
        float2 b0 = x[0][a];
        float2 b1 = cmulconjf(x[1][a], v);
        float2 b2 = cmulconjf(x[2][a], v2);
        float2 b3 = cmulconjf(x[3][a], v3);
        float2 t0 = caddf(b0, b2), t1 = csubf(b0, b2);
        float2 t2 = caddf(b1, b3);
        float2 bd = csubf(b1, b3);
        float2 t3 = make_float2(-bd.y, bd.x);
        Z[ZI(base + a*q1 + 0*L1)] = caddf(t0, t2);
        Z[ZI(base + a*q1 + 1*L1)] = caddf(t1, t3);
        Z[ZI(base + a*q1 + 2*L1)] = csubf(t0, t2);
        Z[ZI(base + a*q1 + 3*L1)] = csubf(t1, t3);
        if (a < 3) v = cmulf(v, vstep);
    }
    __syncthreads();
}

__global__ __launch_bounds__(FFT_T, 1) void fft_conv_kernel(
    const float* __restrict__ sw, const float* __restrict__ sb)
{
    extern __shared__ float2 sm[];
    float2* Z  = sm;
    float2* Hs = sm + Z_PAD_SZ;
    float*  C  = (float*)(sm + Z_PAD_SZ + HS_PAD_SZ);
    const int c   = blockIdx.x;
    const int tid = threadIdx.x;

    for (int k = tid; k <= 4096; k += FFT_T)
        C[k] = cosf(3.834951969714103e-4f * (float)k);   // cos(2*pi*k/16384)
    __syncthreads();

    // ---- filter FFT; final pass writes half-spectrum straight to smem Hs ----
    fft_dif_first(Z, C, g_COEFt + (size_t)c * LSEQ, tid);
    fft_dif_pass16<4096, 2>(Z, C, tid);
    fft_dif_pass16<256, 6>(Z, C, tid);
    fft_dif_pass16_stash(Z, C, Hs, tid);

    // ---- v FFT with fused depthwise short-conv ----
    const float w0 = sw[c*3], w1 = sw[c*3+1], w2 = sw[c*3+2], cb = sb[c];
    fft_dif_first_conv(Z, C, g_Vcm + (size_t)c * MTOT, w0, w1, w2, cb, tid);
    fft_dif_pass16<4096, 2>(Z, C, tid);
    fft_dif_pass16<256, 6>(Z, C, tid);
    fft_dif_pass16<16, 10>(Z, C, tid);

    // ---- inverse: multiply (from smem half-spectrum) fused into len-4 stage
    ifft_first_mult(Z, Hs, tid);
    ifft_dit_pass16<16, 10>(Z, C, tid);
    ifft_dit_pass16<256, 6>(Z, C, tid);

    // ---- final paired pass fused with gate + fp16 store ([c][m]) ----
    const float* x2 = g_X2t + (size_t)c * MTOT;
    __half* go = g_Gf + (size_t)c * MTOT;
    const float scale = 1.0f / (float)NFFT;
    {
        const int p = tid;                   // 1024 threads cover p in [0,1024)
        float2 x[4][4];
        #pragma unroll
        for (int b = 0; b < 4; b++)
            #pragma unroll
            for (int a = 0; a < 4; a++)
                x[b][a] = Z[ZI(p + a*1024 + b*4096)];
        {
            const float2 u1 = twc(C, p << 2);
            const float2 u2 = cmulf(u1, u1);
            const float2 u3 = cmulf(u2, u1);
            #pragma unroll
            for (int b = 0; b < 4; b++) {
                float2 a0 = x[b][0];
                float2 a1 = cmulconjf(x[b][1], u1);
                float2 a2 = cmulconjf(x[b][2], u2);
                float2 a3 = cmulconjf(x[b][3], u3);
                float2 t0 = caddf(a0, a2), t1 = csubf(a0, a2);
                float2 t2 = caddf(a1, a3);
                float2 bd = csubf(a1, a3);
                float2 t3 = make_float2(-bd.y, bd.x);
                x[b][0] = caddf(t0, t2);
                x[b][1] = caddf(t1, t3);
                x[b][2] = csubf(t0, t2);
                x[b][3] = csubf(t1, t3);
            }
        }
        float2 q1 = twc(C, p);
        const float2 qstep = twc(C, 1024);
        #pragma unroll
        for (int a = 0; a < 4; a++) {
            const float2 q2 = cmulf(q1, q1);
            const float2 q3 = cmulf(q2, q1);
            float2 b0 = x[0][a];
            float2 b1 = cmulconjf(x[1][a], q1);
            float2 b2 = cmulconjf(x[2][a], q2);
            float2 b3 = cmulconjf(x[3][a], q3);
            float2 t0 = caddf(b0, b2), t1 = csubf(b0, b2);
            float2 t2 = caddf(b1, b3);
            float2 bd = csubf(b1, b3);
            float2 t3 = make_float2(-bd.y, bd.x);
            float2 o0 = caddf(t0, t2);         // time t
            float2 o1 = caddf(t1, t3);         // time t+4096
            const int t = p + a*1024;
            go[t]               = __float2half(x2[t]               * (o0.x * scale));
            go[LSEQ + t]        = __float2half(x2[LSEQ + t]        * (o0.y * scale));
            go[t + 4096]        = __float2half(x2[t + 4096]        * (o1.x * scale));
            go[LSEQ + t + 4096] = __float2half(x2[LSEQ + t + 4096] * (o1.y * scale));
            if (a < 3) q1 = cmulf(q1, qstep);
        }
    }
}

// ============================================================================
extern "C" void kernel_launch(void* const* d_in, const int* in_sizes, int n_in,
                              void* d_out, int out_size)
{
    const float* x   = (const float*)d_in[0];
    const float* ipw = (const float*)d_in[1];
    const float* ipb = (const float*)d_in[2];
    const float* sw  = (const float*)d_in[3];
    const float* sb  = (const float*)d_in[4];
    const float* fw1 = (const float*)d_in[5];
    const float* fb1 = (const float*)d_in[6];
    const float* fw2 = (const float*)d_in[7];
    const float* fb2 = (const float*)d_in[8];
    const float* fw3 = (const float*)d_in[9];
    const float* fb3 = (const float*)d_in[10];
    const float* ow  = (const float*)d_in[11];
    const float* ob  = (const float*)d_in[12];
    float* out = (float*)d_out;

    cudaFuncSetAttribute(fft_conv_kernel,
                         cudaFuncAttributeMaxDynamicSharedMemorySize, FFT_SMEM);
    cudaFuncSetAttribute(gemm0_coef,
                         cudaFuncAttributeMaxDynamicSharedMemorySize, GSM_BYTES);
    cudaFuncSetAttribute(gemm_out_tc,
                         cudaFuncAttributeMaxDynamicSharedMemorySize, GSM_BYTES);

    // 1) one prep kernel: x fp16 + weight gathers + filter MLP h2
    prep_split<<<22528, 256>>>(x, ipw, ow, fw1, fb1, fw2, fb2);
    // 2) merged launch: coef GEMM tiles (first) + in_proj GEMM tiles (fp16)
    gemm0_coef<<<NCOEF_B + 2048, 256, GSM_BYTES>>>(ipb, fw3, fb3);
    // 3) FFT long conv, 1024 threads (fused short-conv, stash, mult, gate)
    fft_conv_kernel<<<CH, FFT_T, FFT_SMEM>>>(sw, sb);
    // 4) out GEMM (fp16) reads gated activations k-major via ldmatrix.trans
    gemm_out_tc<<<dim3(8, 128), 256, GSM_BYTES>>>(ob, out);
}

// round 17
// speedup vs baseline: 2.7424x; 1.0480x over previous
#include <cuda_runtime.h>
#include <cuda_fp16.h>
#include <math.h>
#include <stdint.h>

// Problem constants
#define LSEQ   8192
#define NFFT   16384
#define CH     1024
#define BATCH  2
#define MTOT   (BATCH*LSEQ)      // 16384 rows

// ---------------- scratch (device globals; no allocations allowed) ----------
__device__ float g_Vcm  [CH*MTOT];     // in_proj v branch, channel-major [c][m]
__device__ float g_X2t  [CH*MTOT];     // x2 branch, channel-major [c][m]
__device__ float g_H2   [LSEQ*128];    // filter MLP hidden (L x 128)
__device__ float g_COEFt[CH*LSEQ];     // filter coefs order-1, channel-major [c][l]

// fp16 operands for the tensor-core GEMMs (single-term)
__device__ __half g_Xf [MTOT*CH];      // x, [m][k]
__device__ __half g_Gf [CH*MTOT];      // gated, [c][m] (k-major)
__device__ __half g_Wif[2048*CH];      // in_proj cols, [n][k]
__device__ __half g_Wof[CH*CH];        // out_w^T, [n][k]

// ---------------- generic helpers -------------------------------------------
__device__ __forceinline__ float gelu_exact(float x) {
    return 0.5f * x * (1.0f + erff(x * 0.70710678118654752f));
}
__device__ __forceinline__ float2 cmulf(float2 a, float2 b) {
    return make_float2(a.x*b.x - a.y*b.y, a.x*b.y + a.y*b.x);
}
__device__ __forceinline__ float2 cmulconjf(float2 a, float2 w) {  // a * conj(w)
    return make_float2(a.x*w.x + a.y*w.y, a.y*w.x - a.x*w.y);
}
__device__ __forceinline__ float2 caddf(float2 a, float2 b) {
    return make_float2(a.x + b.x, a.y + b.y);
}
__device__ __forceinline__ float2 csubf(float2 a, float2 b) {
    return make_float2(a.x - b.x, a.y - b.y);
}
__device__ __forceinline__ uint32_t smem_u32(const void* p) {
    uint32_t a;
    asm("{ .reg .u64 t; cvta.to.shared.u64 t, %1; cvt.u32.u64 %0, t; }"
        : "=r"(a) : "l"(p));
    return a;
}

#define CP_ASYNC16(sm, gp) \
    asm volatile("cp.async.cg.shared.global [%0], [%1], 16;" \
                 :: "r"(sm), "l"(__cvta_generic_to_global(gp)) : "memory")
#define CP_COMMIT() asm volatile("cp.async.commit_group;" ::: "memory")
#define CP_WAIT0()  asm volatile("cp.async.wait_group 0;" ::: "memory")

#define LDSM4(r0, r1, r2, r3, ad) \
    asm volatile("ldmatrix.sync.aligned.m8n8.x4.shared.b16 {%0,%1,%2,%3}, [%4];" \
                 : "=r"(r0), "=r"(r1), "=r"(r2), "=r"(r3) : "r"(ad))
#define LDSM4T(r0, r1, r2, r3, ad) \
    asm volatile("ldmatrix.sync.aligned.m8n8.x4.trans.shared.b16 {%0,%1,%2,%3}, [%4];" \
                 : "=r"(r0), "=r"(r1), "=r"(r2), "=r"(r3) : "r"(ad))

__device__ __forceinline__ void mma_f16(float* c, const uint32_t* a, const uint32_t* b) {
    asm volatile("mma.sync.aligned.m16n8k16.row.col.f32.f16.f16.f32 "
        "{%0,%1,%2,%3}, {%4,%5,%6,%7}, {%8,%9}, {%0,%1,%2,%3};"
        : "+f"(c[0]), "+f"(c[1]), "+f"(c[2]), "+f"(c[3])
        : "r"(a[0]), "r"(a[1]), "r"(a[2]), "r"(a[3]), "r"(b[0]), "r"(b[1]));
}

// ============================================================================
// prep_split: one kernel, four roles by block range. (frozen)
// ============================================================================
__global__ __launch_bounds__(256) void prep_split(
    const float* __restrict__ x, const float* __restrict__ ipw,
    const float* __restrict__ ow,
    const float* __restrict__ fw1, const float* __restrict__ fb1,
    const float* __restrict__ fw2, const float* __restrict__ fb2)
{
    const int b   = blockIdx.x;
    const int tid = threadIdx.x;

    if (b < 16384) {
        size_t i = ((size_t)b * 256 + tid) * 4;
        float4 v = *(const float4*)&x[i];
        *(__half2*)&g_Xf[i]   = __floats2half2_rn(v.x, v.y);
        *(__half2*)&g_Xf[i+2] = __floats2half2_rn(v.z, v.w);
        return;
    }

    if (b < 17408) {
        __shared__ float s[32][97];
        const int bid2 = b - 16384;
        const int c0 = (bid2 & 31) * 32;
        const int k0 = (bid2 >> 5) * 32;
        for (int idx = tid; idx < 32*96; idx += 256) {
            const int r = idx / 96, cc = idx % 96;
            s[r][cc] = ipw[(size_t)(k0 + r) * 3072 + 3*c0 + cc];
        }
        __syncthreads();
        const int dc = tid >> 3;
        const int kq = (tid & 7) * 4;
        const int c  = c0 + dc;
        const size_t ov = (size_t)c * 1024 + k0 + kq;
        const size_t ox = (size_t)(1024 + c) * 1024 + k0 + kq;
        *(__half2*)&g_Wif[ov]   = __floats2half2_rn(s[kq+0][3*dc], s[kq+1][3*dc]);
        *(__half2*)&g_Wif[ov+2] = __floats2half2_rn(s[kq+2][3*dc], s[kq+3][3*dc]);
        *(__half2*)&g_Wif[ox]   = __floats2half2_rn(s[kq+0][3*dc+2], s[kq+1][3*dc+2]);
        *(__half2*)&g_Wif[ox+2] = __floats2half2_rn(s[kq+2][3*dc+2], s[kq+3][3*dc+2]);
        return;
    }

    if (b < 18432) {
        __shared__ float s[32][33];
        const int bid2 = b - 17408;
        const int c0 = (bid2 & 31) * 32;
        const int k0 = (bid2 >> 5) * 32;
        const int tx  = tid & 31;
        const int ty0 = tid >> 5;            // 0..7
        #pragma unroll
        for (int rr = 0; rr < 4; rr++) {
            const int r = ty0 + rr * 8;
            s[r][tx] = ow[(size_t)(k0 + r) * CH + c0 + tx];
        }
        __syncthreads();
        #pragma unroll
        for (int rr = 0; rr < 4; rr++) {
            const int ty = ty0 + rr * 8;
            g_Wof[(size_t)(c0 + ty) * 1024 + k0 + tx] = __float2half(s[tx][ty]);
        }
        return;
    }

    {
        // filter MLP: 2 sequence positions per CTA
        __shared__ float h1s[2][64];
        const int lb  = (b - 18432) * 2;
        const int sub = tid >> 7;            // 0/1
        const int t   = tid & 127;
        const int l   = lb + sub;
        const float pos = (float)l / (float)(LSEQ - 1);
        if (t < 64) h1s[sub][t] = gelu_exact(pos * fw1[t] + fb1[t]);
        __syncthreads();
        float s = fb2[t];
        #pragma unroll 8
        for (int j = 0; j < 64; j++) s += h1s[sub][j] * fw2[j*128 + t];
        g_H2[(size_t)l*128 + t] = gelu_exact(s);
    }
}

// ============================================================================
// gemm0_coef: merged launch.
//   blocks [0, 512)      : coef GEMM tiles (COEFt transposed epilogue, frozen)
//   blocks [512, 2560)   : in_proj GEMM tiles (fp16, DOUBLE-BUFFERED pipeline)
// ============================================================================
#define GSM_BYTES 65536
#define NCOEF_B   512

__global__ __launch_bounds__(256, 2) void gemm0_coef(
    const float* __restrict__ bias,
    const float* __restrict__ fw3, const float* __restrict__ fb3)
{
    extern __shared__ char dsm[];
    const int tid = threadIdx.x;

    if (blockIdx.x < NCOEF_B) {
        float* As    = (float*)dsm;               // [8][128]
        float* Bs    = As + 8*128;                // [8][128]
        float* stage = Bs + 8*128;                // [128*65]
        const int bid = blockIdx.x;
        const int tx = tid & 15, ty = tid >> 4;
        const int m0 = (bid >> 3) * 128;
        const int n0 = (bid & 7) * 128;

        float acc[8][8];
        #pragma unroll
        for (int i = 0; i < 8; i++)
            #pragma unroll
            for (int j = 0; j < 8; j++) acc[i][j] = 0.f;

        const int arow = tid >> 1, akq = (tid & 1) * 4;
        const int bn = tid & 127;
        const int jm = 2 * (n0 + bn) + 1;
        const int kk0 = (tid >> 7) * 4;

        for (int k0 = 0; k0 < 128; k0 += 8) {
            float4 av = *(const float4*)&g_H2[(size_t)(m0 + arow) * 128 + k0 + akq];
            As[(akq+0)*128 + arow] = av.x; As[(akq+1)*128 + arow] = av.y;
            As[(akq+2)*128 + arow] = av.z; As[(akq+3)*128 + arow] = av.w;
            #pragma unroll
            for (int r = 0; r < 4; r++)
                Bs[(kk0 + r)*128 + bn] = fw3[(size_t)(k0 + kk0 + r) * 2048 + jm];
            __syncthreads();
            #pragma unroll
            for (int kk = 0; kk < 8; kk++) {
                float a[8], bb[8];
                #pragma unroll
                for (int i = 0; i < 8; i++) a[i] = As[kk*128 + ty*8 + i];
                #pragma unroll
                for (int j = 0; j < 8; j++) bb[j] = Bs[kk*128 + tx*8 + j];
                #pragma unroll
                for (int i = 0; i < 8; i++)
                    #pragma unroll
                    for (int j = 0; j < 8; j++) acc[i][j] += a[i] * bb[j];
            }
            __syncthreads();
        }

        float bo[8];
        #pragma unroll
        for (int j = 0; j < 8; j++) bo[j] = fb3[2*(n0 + tx*8 + j) + 1];

        #pragma unroll
        for (int h = 0; h < 2; h++) {
            __syncthreads();
            if ((tx >> 3) == h) {
                #pragma unroll
                for (int i = 0; i < 8; i++)
                    #pragma unroll
                    for (int j = 0; j < 8; j++)
                        stage[(ty*8 + i) * 65 + (tx & 7) * 8 + j] = acc[i][j] + bo[j];
            }
            __syncthreads();
            const int cl  = tid >> 2;
            const int lch = (tid & 3) << 5;
            const int c   = n0 + h * 64 + cl;
            float* dst = g_COEFt + (size_t)c * LSEQ + m0 + lch;
            #pragma unroll
            for (int j = 0; j < 32; j += 4) {
                float4 o = make_float4(stage[(lch+j)*65   + cl],
                                       stage[(lch+j+1)*65 + cl],
                                       stage[(lch+j+2)*65 + cl],
                                       stage[(lch+j+3)*65 + cl]);
                *(float4*)&dst[j] = o;
            }
        }
        return;
    }

    // ---------- in_proj GEMM (fp16, double-buffered one-sync pipeline) -------
    const uint32_t sb  = smem_u32(dsm);
    const int lane = tid & 31;
    const int wid  = tid >> 5;
    const int wm   = wid >> 1;
    const int wn   = wid & 1;
    const int gbid = blockIdx.x - NCOEF_B;
    const int bx   = gbid & 15;
    const int m0   = (gbid >> 4) * 128;
    const int n0   = bx * 128;

    float acc[2][8][4];
    #pragma unroll
    for (int i = 0; i < 2; i++)
        #pragma unroll
        for (int j = 0; j < 8; j++)
            #pragma unroll
            for (int q = 0; q < 4; q++) acc[i][j][q] = 0.f;

    auto load_chunk = [&](int it, int buf) {
        const size_t kc0 = (size_t)it * 64;
        const uint32_t sA = sb + (uint32_t)buf * 32768u;
        const uint32_t sB = sA + 16384u;
        #pragma unroll
        for (int u = 0; u < 4; u++) {
            const int s = tid + u * 256;
            const int row = s >> 3, seg = s & 7;
            const uint32_t so = (uint32_t)(row * 128 + ((seg * 16) ^ ((row & 7) << 4)));
            CP_ASYNC16(sA + so, g_Xf + (size_t)(m0 + row) * 1024 + kc0 + seg * 8);
            CP_ASYNC16(sB + so, g_Wif + (size_t)(n0 + row) * 1024 + kc0 + seg * 8);
        }
        CP_COMMIT();
    };

    auto compute_chunk = [&](int buf) {
        const uint32_t sA = sb + (uint32_t)buf * 32768u;
        const uint32_t sB = sA + 16384u;
        #pragma unroll
        for (int ks = 0; ks < 4; ks++) {
            uint32_t ah[2][4];
            #pragma unroll
            for (int mt = 0; mt < 2; mt++) {
                const int row = wm * 32 + mt * 16 + (lane & 15);
                const uint32_t r4 = (row & 7) << 4;
                const uint32_t cb = (uint32_t)(ks * 32 + ((lane >> 4) << 4));
                const uint32_t ad = sA + row * 128 + (cb ^ r4);
                LDSM4(ah[mt][0], ah[mt][1], ah[mt][2], ah[mt][3], ad);
            }
            uint32_t bh[8][2];
            #pragma unroll
            for (int nt2 = 0; nt2 < 4; nt2++) {
                const int n = wn * 64 + nt2 * 16 + (lane & 7) + ((lane >> 4) << 3);
                const uint32_t r4 = (n & 7) << 4;
                const uint32_t cb = (uint32_t)(ks * 32 + (((lane >> 3) & 1) << 4));
                const uint32_t ad = sB + n * 128 + (cb ^ r4);
                LDSM4(bh[2*nt2][0], bh[2*nt2][1], bh[2*nt2+1][0], bh[2*nt2+1][1], ad);
            }
            #pragma unroll
            for (int mt = 0; mt < 2; mt++)
                #pragma unroll
                for (int nt = 0; nt < 8; nt++)
                    mma_f16(acc[mt][nt], ah[mt], bh[nt]);
        }
    };

    load_chunk(0, 0);
    for (int it = 0; it < 16; ++it) {
        CP_WAIT0();
        __syncthreads();
        if (it + 1 < 16) load_chunk(it + 1, (it + 1) & 1);
        compute_chunk(it & 1);
    }
    __syncthreads();

    {
        float* stage = (float*)dsm;          // [128][65] floats = 33 KB
        const bool is_v = (bx < 8);
        const int cbase = (is_v ? bx : bx - 8) * 128;
        #pragma unroll
        for (int h = 0; h < 2; h++) {
            __syncthreads();
            if (wn == h) {
                #pragma unroll
                for (int mt = 0; mt < 2; mt++) {
                    const int rl = wm * 32 + mt * 16 + (lane >> 2);
                    #pragma unroll
                    for (int nt = 0; nt < 8; nt++) {
                        const int cl = nt * 8 + ((lane & 3) << 1);
                        stage[rl * 65 + cl]           = acc[mt][nt][0];
                        stage[rl * 65 + cl + 1]       = acc[mt][nt][1];
                        stage[(rl + 8) * 65 + cl]     = acc[mt][nt][2];
                        stage[(rl + 8) * 65 + cl + 1] = acc[mt][nt][3];
                    }
                }
            }
            __syncthreads();
            const int cl  = tid >> 2;
            const int mch = (tid & 3) << 5;
            const int c   = cbase + h * 64 + cl;
            const float b = is_v ? bias[3*c] : bias[3*c + 2];
            float* dst = (is_v ? g_Vcm : g_X2t) + (size_t)c * MTOT + m0 + mch;
            #pragma unroll
            for (int j = 0; j < 32; j += 4) {
                float4 o = make_float4(stage[(mch+j)*65   + cl] + b,
                                       stage[(mch+j+1)*65 + cl] + b,
                                       stage[(mch+j+2)*65 + cl] + b,
                                       stage[(mch+j+3)*65 + cl] + b);
                *(float4*)&dst[j] = o;
            }
        }
    }
}

// ============================================================================
// out-proj GEMM (fp16, double-buffered one-sync pipeline)
// ============================================================================
__global__ __launch_bounds__(256, 2) void gemm_out_tc(
    const float* __restrict__ bias, float* __restrict__ out)
{
    extern __shared__ char dsm[];
    const uint32_t sb  = smem_u32(dsm);

    const int tid  = threadIdx.x;
    const int lane = tid & 31;
    const int wid  = tid >> 5;
    const int wm   = wid >> 1;
    const int wn   = wid & 1;
    const int m0   = blockIdx.y * 128;
    const int n0   = blockIdx.x * 128;

    float acc[2][8][4];
    #pragma unroll
    for (int i = 0; i < 2; i++)
        #pragma unroll
        for (int j = 0; j < 8; j++)
            #pragma unroll
            for (int q = 0; q < 4; q++) acc[i][j][q] = 0.f;

    auto load_chunk = [&](int it, int buf) {
        const size_t kc0 = (size_t)it * 64;
        const uint32_t sA = sb + (uint32_t)buf * 32768u;
        const uint32_t sB = sA + 16384u;
        // A: 64 k-rows x 256B ([k][m], contiguous along m)
        #pragma unroll
        for (int u = 0; u < 4; u++) {
            const int s = tid + u * 256;
            const int row = s >> 4, seg = s & 15;
            const uint32_t so = (uint32_t)(row * 256 + ((seg * 16) ^ ((row & 7) << 4)));
            CP_ASYNC16(sA + so, g_Gf + (size_t)(kc0 + row) * MTOT + m0 + seg * 8);
        }
        // B: 128 n-rows x 128B
        #pragma unroll
        for (int u = 0; u < 4; u++) {
            const int s = tid + u * 256;
            const int row = s >> 3, seg = s & 7;
            const uint32_t so = (uint32_t)(row * 128 + ((seg * 16) ^ ((row & 7) << 4)));
            CP_ASYNC16(sB + so, g_Wof + (size_t)(n0 + row) * 1024 + kc0 + seg * 8);
        }
        CP_COMMIT();
    };

    auto compute_chunk = [&](int buf) {
        const uint32_t sA = sb + (uint32_t)buf * 32768u;
        const uint32_t sB = sA + 16384u;
        #pragma unroll
        for (int ks = 0; ks < 4; ks++) {
            uint32_t ah[2][4];
            #pragma unroll
            for (int mt = 0; mt < 2; mt++) {
                const int rowk = ks * 16 + (lane & 7) + ((lane >> 4) << 3);
                const int mcol = wm * 32 + mt * 16 + (((lane >> 3) & 1) << 3);
                const uint32_t ad = sA + rowk * 256 +
                    (((uint32_t)(2 * mcol)) ^ ((uint32_t)(rowk & 7) << 4));
                LDSM4T(ah[mt][0], ah[mt][1], ah[mt][2], ah[mt][3], ad);
            }
            uint32_t bh[8][2];
            #pragma unroll
            for (int nt2 = 0; nt2 < 4; nt2++) {
                const int n = wn * 64 + nt2 * 16 + (lane & 7) + ((lane >> 4) << 3);
                const uint32_t r4 = (n & 7) << 4;
                const uint32_t cb = (uint32_t)(ks * 32 + (((lane >> 3) & 1) << 4));
                const uint32_t ad = sB + n * 128 + (cb ^ r4);
                LDSM4(bh[2*nt2][0], bh[2*nt2][1], bh[2*nt2+1][0], bh[2*nt2+1][1], ad);
            }
            #pragma unroll
            for (int mt = 0; mt < 2; mt++)
                #pragma unroll
                for (int nt = 0; nt < 8; nt++)
                    mma_f16(acc[mt][nt], ah[mt], bh[nt]);
        }
    };

    load_chunk(0, 0);
    for (int it = 0; it < 16; ++it) {
        CP_WAIT0();
        __syncthreads();
        if (it + 1 < 16) load_chunk(it + 1, (it + 1) & 1);
        compute_chunk(it & 1);
    }

    #pragma unroll
    for (int mt = 0; mt < 2; mt++) {
        const int r = m0 + wm * 32 + mt * 16 + (lane >> 2);
        #pragma unroll
        for (int nt = 0; nt < 8; nt++) {
            const int c = n0 + wn * 64 + nt * 8 + ((lane & 3) << 1);
            const float b0 = bias[c], b1 = bias[c + 1];
            *(float2*)&out[(size_t)r * CH + c] =
                make_float2(acc[mt][nt][0] + b0, acc[mt][nt][1] + b1);
            *(float2*)&out[(size_t)(r + 8) * CH + c] =
                make_float2(acc[mt][nt][2] + b0, acc[mt][nt][3] + b1);
        }
    }
}

// ============================================================================
// FFT convolution — 1024 threads, radix-16 passes, padded smem, smem
// Hermitian half-spectrum, twiddle chains. (frozen)
// ============================================================================
#define FFT_T    1024
#define ZI(i) ((i) + ((i) >> 4))
#define Z_PAD_SZ  17408                 // float2
#define HS_PAD_SZ 8232                  // float2
#define COS_SZ    4104                  // floats
#define HsI(k) ((k) + ((k) >> 8))
#define FFT_SMEM ((Z_PAD_SZ + HS_PAD_SZ) * 8 + COS_SZ * 4)

__device__ __forceinline__ int digrev4_14(int j) {
    unsigned r = __brev((unsigned)j) >> 18;
    return (int)(((r & 0x2AAAu) >> 1) | ((r & 0x1555u) << 1));
}
__device__ __forceinline__ int digrev4_10(int g) {
    unsigned r = __brev((unsigned)g) >> 22;
    return (int)(((r & 0x155u) << 1) | ((r >> 1) & 0x155u));
}
__device__ __forceinline__ float2 twc(const float* __restrict__ C, int k) {
    return make_float2(C[k], -C[4096 - k]);
}
__device__ __forceinline__ float conv3(const float* __restrict__ q, int l,
                                       float w0, float w1, float w2, float b) {
    float s = w1 * q[l] + b;
    if (l > 0)        s += w0 * q[l-1];
    if (l < LSEQ - 1) s += w2 * q[l+1];
    return s;
}

__device__ void fft_dif_first(float2* Z, const float* C,
                              const float* __restrict__ re, int tid) {
    for (int p = tid; p < 4096; p += FFT_T) {
        float2 a = make_float2(re[p], 0.f);
        float2 b = make_float2(re[p + 4096], 0.f);
        float2 w1 = twc(C, p);
        float2 w2 = cmulf(w1, w1);
        float2 w3 = cmulf(w2, w1);
        Z[ZI(p)]         = caddf(a, b);
        Z[ZI(p + 4096)]  = cmulf(make_float2(a.x + b.y, a.y - b.x), w1);
        Z[ZI(p + 8192)]  = cmulf(csubf(a, b),                       w2);
        Z[ZI(p + 12288)] = cmulf(make_float2(a.x - b.y, a.y + b.x), w3);
    }
    __syncthreads();
}

__device__ void fft_dif_first_conv(float2* Z, const float* C,
                                   const float* __restrict__ v0,
                                   float w0, float w1, float w2, float cb, int tid) {
    const float* v1 = v0 + LSEQ;
    for (int p = tid; p < 4096; p += FFT_T) {
        float2 a = make_float2(conv3(v0, p, w0, w1, w2, cb),
                               conv3(v1, p, w0, w1, w2, cb));
        float2 b = make_float2(conv3(v0, p + 4096, w0, w1, w2, cb),
                               conv3(v1, p + 4096, w0, w1, w2, cb));
        float2 t1 = twc(C, p);
        float2 t2 = cmulf(t1, t1);
        float2 t3 = cmulf(t2, t1);
        Z[ZI(p)]         = caddf(a, b);
        Z[ZI(p + 4096)]  = cmulf(make_float2(a.x + b.y, a.y - b.x), t1);
        Z[ZI(p + 8192)]  = cmulf(csubf(a, b),                       t2);
        Z[ZI(p + 12288)] = cmulf(make_float2(a.x - b.y, a.y + b.x), t3);
    }
    __syncthreads();
}

template<int LA, int TWA>
__device__ void fft_dif_pass16(float2* Z, const float* C, int tid) {
    constexpr int qA = LA / 4, qB = LA / 16;
    constexpr int TWB = TWA + 2;
    const int p2   = tid & (qB - 1);
    const int base = (tid / qB) * LA + p2;
    float2 x[4][4];
    #pragma unroll
    for (int b = 0; b < 4; b++)
        #pragma unroll
        for (int a = 0; a < 4; a++)
            x[b][a] = Z[ZI(base + a*qB + b*qA)];
    float2 wA = twc(C, p2 << TWA);
    const float2 wstep = twc(C, qB << TWA);
    #pragma unroll
    for (int a = 0; a < 4; a++) {
        const float2 wA2 = cmulf(wA, wA);
        const float2 wA3 = cmulf(wA2, wA);
        float2 t0 = caddf(x[0][a], x[2][a]);
        float2 t1 = csubf(x[0][a], x[2][a]);
        float2 t2 = caddf(x[1][a], x[3][a]);
        float2 bd = csubf(x[1][a], x[3][a]);
        float2 t3 = make_float2(bd.y, -bd.x);
        x[0][a] = caddf(t0, t2);
        x[1][a] = cmulf(caddf(t1, t3), wA);
        x[2][a] = cmulf(csubf(t0, t2), wA2);
        x[3][a] = cmulf(csubf(t1, t3), wA3);
        if (a < 3) wA = cmulf(wA, wstep);
    }
    const float2 wB1 = twc(C, p2 << TWB);
    const float2 wB2 = cmulf(wB1, wB1);
    const float2 wB3 = cmulf(wB2, wB1);
    #pragma unroll
    for (int b = 0; b < 4; b++) {
        float2 t0 = caddf(x[b][0], x[b][2]);
        float2 t1 = csubf(x[b][0], x[b][2]);
        float2 t2 = caddf(x[b][1], x[b][3]);
        float2 bd = csubf(x[b][1], x[b][3]);
        float2 t3 = make_float2(bd.y, -bd.x);
        Z[ZI(base + 0*qB + b*qA)] = caddf(t0, t2);
        Z[ZI(base + 1*qB + b*qA)] = cmulf(caddf(t1, t3), wB1);
        Z[ZI(base + 2*qB + b*qA)] = cmulf(csubf(t0, t2), wB2);
        Z[ZI(base + 3*qB + b*qA)] = cmulf(csubf(t1, t3), wB3);
    }
    __syncthreads();
}

__device__ void fft_dif_pass16_stash(float2* Z, const float* C,
                                     float2* __restrict__ Hs, int tid) {
    const int base = tid * 16;
    const int kg = digrev4_10(tid);
    float2 x[4][4];
    #pragma unroll
    for (int b = 0; b < 4; b++)
        #pragma unroll
        for (int a = 0; a < 4; a++)
            x[b][a] = Z[ZI(base + a + 4*b)];
    float2 wA = make_float2(1.f, 0.f);
    const float2 wstep = twc(C, 1 << 10);
    #pragma unroll
    for (int a = 0; a < 4; a++) {
        const float2 wA2 = cmulf(wA, wA);
        const float2 wA3 = cmulf(wA2, wA);
        float2 t0 = caddf(x[0][a], x[2][a]);
        float2 t1 = csubf(x[0][a], x[2][a]);
        float2 t2 = caddf(x[1][a], x[3][a]);
        float2 bd = csubf(x[1][a], x[3][a]);
        float2 t3 = make_float2(bd.y, -bd.x);
        x[0][a] = caddf(t0, t2);
        x[1][a] = cmulf(caddf(t1, t3), wA);
        x[2][a] = cmulf(csubf(t0, t2), wA2);
        x[3][a] = cmulf(csubf(t1, t3), wA3);
        if (a < 3) wA = cmulf(wA, wstep);
    }
    #pragma unroll
    for (int b = 0; b < 4; b++) {
        float2 t0 = caddf(x[b][0], x[b][2]);
        float2 t1 = csubf(x[b][0], x[b][2]);
        float2 t2 = caddf(x[b][1], x[b][3]);
        float2 bd = csubf(x[b][1], x[b][3]);
        float2 t3 = make_float2(bd.y, -bd.x);
        const int k0 = kg + b * 1024;
        Hs[HsI(k0)]        = caddf(t0, t2);      // o=0
        Hs[HsI(k0 + 4096)] = caddf(t1, t3);      // o=1
        if (k0 == 0) Hs[HsI(8192)] = csubf(t0, t2);  // k=8192 edge
    }
    __syncthreads();
}

__device__ void ifft_first_mult(float2* Z, const float2* __restrict__ Hs, int tid) {
    for (int b = tid; b < NFFT/4; b += FFT_T) {
        const int i0 = 4*b;
        const int kb = digrev4_14(i0);
        float2 zz[4];
        #pragma unroll
        for (int s2 = 0; s2 < 4; s2++) {
            const int k = kb + s2 * 4096;
            float2 H;
            if (k <= 8192) H = Hs[HsI(k)];
            else { const int kc = 16384 - k; H = Hs[HsI(kc)]; H.y = -H.y; }
            zz[s2] = cmulf(Z[ZI(i0 + s2)], H);
        }
        float2 t0 = caddf(zz[0], zz[2]), t1 = csubf(zz[0], zz[2]);
        float2 t2 = caddf(zz[1], zz[3]);
        float2 bd = csubf(zz[1], zz[3]);
        float2 t3 = make_float2(-bd.y, bd.x);
        Z[ZI(i0)]     = caddf(t0, t2);
        Z[ZI(i0 + 1)] = caddf(t1, t3);
        Z[ZI(i0 + 2)] = csubf(t0, t2);
        Z[ZI(i0 + 3)] = csubf(t1, t3);
    }
    __syncthreads();
}

template<int L1, int TW1>
__device__ void ifft_dit_pass16(float2* Z, const float* C, int tid) {
    constexpr int q1 = L1 / 4, L2 = 4 * L1;
    constexpr int TW2 = TW1 - 2;
    const int p    = tid & (q1 - 1);
    const int base = (tid / q1) * L2 + p;
    float2 x[4][4];
    #pragma unroll
    for (int b = 0; b < 4; b++)
        #pragma unroll
        for (int a = 0; a < 4; a++)
            x[b][a] = Z[ZI(base + a*q1 + b*L1)];
    {
        const float2 u1 = twc(C, p << TW1);
        const float2 u2 = cmulf(u1, u1);
        const float2 u3 = cmulf(u2, u1);
        #pragma unroll
        for (int b = 0; b < 4; b++) {
            float2 a0 = x[b][0];
            float2 a1 = cmulconjf(x[b][1], u1);
            float2 a2 = cmulconjf(x[b][2], u2);
            float2 a3 = cmulconjf(x[b][3], u3);
            float2 t0 = caddf(a0, a2), t1 = csubf(a0, a2);
            float2 t2 = caddf(a1, a3);
            float2 bd = csubf(a1, a3);
            float2 t3 = make_float2(-bd.y, bd.x);
            x[b][0] = caddf(t0, t2);
            x[b][1] = caddf(t1, t3);
            x[b][2] = csubf(t0, t2);
            x[b][3] = csubf(t1, t3);
        }
    }
    float2 v = twc(C, p << TW2);
    const float2 vstep = twc(C, q1 << TW2);
    #pragma unroll
    for (int a = 0; a < 4; a++) {
        const float2 v2 = cmulf(v, v);
        const float2 v3 = cmulf(v2, v);
        float2 b0 = x[0][a];
        float2 b1 = cmulconjf(x[1][a], v);
        float2 b2 = cmulconjf(x[2][a], v2);
        float2 b3 = cmulconjf(x[3][a], v3);
        float2 t0 = caddf(b0, b2), t1 = csubf(b0, b2);
        float2 t2 = caddf(b1, b3);
        float2 bd = csubf(b1, b3);
        float2 t3 = make_float2(-bd.y, bd.x);
        Z[ZI(base + a*q1 + 0*L1)] = caddf(t0, t2);
        Z[ZI(base + a*q1 + 1*L1)] = caddf(t1, t3);
        Z[ZI(base + a*q1 + 2*L1)] = csubf(t0, t2);
        Z[ZI(base + a*q1 + 3*L1)] = csubf(t1, t3);
        if (a < 3) v = cmulf(v, vstep);
    }
    __syncthreads();
}

__global__ __launch_bounds__(FFT_T, 1) void fft_conv_kernel(
    const float* __restrict__ sw, const float* __restrict__ sb)
{
    extern __shared__ float2 sm[];
    float2* Z  = sm;
    float2* Hs = sm + Z_PAD_SZ;
    float*  C  = (float*)(sm + Z_PAD_SZ + HS_PAD_SZ);
    const int c   = blockIdx.x;
    const int tid = threadIdx.x;

    for (int k = tid; k <= 4096; k += FFT_T)
        C[k] = cosf(3.834951969714103e-4f * (float)k);   // cos(2*pi*k/16384)
    __syncthreads();

    // ---- filter FFT; final pass writes half-spectrum straight to smem Hs ----
    fft_dif_first(Z, C, g_COEFt + (size_t)c * LSEQ, tid);
    fft_dif_pass16<4096, 2>(Z, C, tid);
    fft_dif_pass16<256, 6>(Z, C, tid);
    fft_dif_pass16_stash(Z, C, Hs, tid);

    // ---- v FFT with fused depthwise short-conv ----
    const float w0 = sw[c*3], w1 = sw[c*3+1], w2 = sw[c*3+2], cb = sb[c];
    fft_dif_first_conv(Z, C, g_Vcm + (size_t)c * MTOT, w0, w1, w2, cb, tid);
    fft_dif_pass16<4096, 2>(Z, C, tid);
    fft_dif_pass16<256, 6>(Z, C, tid);
    fft_dif_pass16<16, 10>(Z, C, tid);

    // ---- inverse: multiply (from smem half-spectrum) fused into len-4 stage
    ifft_first_mult(Z, Hs, tid);
    ifft_dit_pass16<16, 10>(Z, C, tid);
    ifft_dit_pass16<256, 6>(Z, C, tid);

    // ---- final paired pass fused with gate + fp16 store ([c][m]) ----
    const float* x2 = g_X2t + (size_t)c * MTOT;
    __half* go = g_Gf + (size_t)c * MTOT;
    const float scale = 1.0f / (float)NFFT;
    {
        const int p = tid;                   // 1024 threads cover p in [0,1024)
        float2 x[4][4];
        #pragma unroll
        for (int b = 0; b < 4; b++)
            #pragma unroll
            for (int a = 0; a < 4; a++)
                x[b][a] = Z[ZI(p + a*1024 + b*4096)];
        {
            const float2 u1 = twc(C, p << 2);
            const float2 u2 = cmulf(u1, u1);
            const float2 u3 = cmulf(u2, u1);
            #pragma unroll
            for (int b = 0; b < 4; b++) {
                float2 a0 = x[b][0];
                float2 a1 = cmulconjf(x[b][1], u1);
                float2 a2 = cmulconjf(x[b][2], u2);
                float2 a3 = cmulconjf(x[b][3], u3);
                float2 t0 = caddf(a0, a2), t1 = csubf(a0, a2);
                float2 t2 = caddf(a1, a3);
                float2 bd = csubf(a1, a3);
                float2 t3 = make_float2(-bd.y, bd.x);
                x[b][0] = caddf(t0, t2);
                x[b][1] = caddf(t1, t3);
                x[b][2] = csubf(t0, t2);
                x[b][3] = csubf(t1, t3);
            }
        }
        float2 q1 = twc(C, p);
        const float2 qstep = twc(C, 1024);
        #pragma unroll
        for (int a = 0; a < 4; a++) {
            const float2 q2 = cmulf(q1, q1);
            const float2 q3 = cmulf(q2, q1);
            float2 b0 = x[0][a];
            float2 b1 = cmulconjf(x[1][a], q1);
            float2 b2 = cmulconjf(x[2][a], q2);
            float2 b3 = cmulconjf(x[3][a], q3);
            float2 t0 = caddf(b0, b2), t1 = csubf(b0, b2);
            float2 t2 = caddf(b1, b3);
            float2 bd = csubf(b1, b3);
            float2 t3 = make_float2(-bd.y, bd.x);
            float2 o0 = caddf(t0, t2);         // time t
            float2 o1 = caddf(t1, t3);         // time t+4096
            const int t = p + a*1024;
            go[t]               = __float2half(x2[t]               * (o0.x * scale));
            go[LSEQ + t]        = __float2half(x2[LSEQ + t]        * (o0.y * scale));
            go[t + 4096]        = __float2half(x2[t + 4096]        * (o1.x * scale));
            go[LSEQ + t + 4096] = __float2half(x2[LSEQ + t + 4096] * (o1.y * scale));
            if (a < 3) q1 = cmulf(q1, qstep);
        }
    }
}

// ============================================================================
extern "C" void kernel_launch(void* const* d_in, const int* in_sizes, int n_in,
                              void* d_out, int out_size)
{
    const float* x   = (const float*)d_in[0];
    const float* ipw = (const float*)d_in[1];
    const float* ipb = (const float*)d_in[2];
    const float* sw  = (const float*)d_in[3];
    const float* sb  = (const float*)d_in[4];
    const float* fw1 = (const float*)d_in[5];
    const float* fb1 = (const float*)d_in[6];
    const float* fw2 = (const float*)d_in[7];
    const float* fb2 = (const float*)d_in[8];
    const float* fw3 = (const float*)d_in[9];
    const float* fb3 = (const float*)d_in[10];
    const float* ow  = (const float*)d_in[11];
    const float* ob  = (const float*)d_in[12];
    float* out = (float*)d_out;

    cudaFuncSetAttribute(fft_conv_kernel,
                         cudaFuncAttributeMaxDynamicSharedMemorySize, FFT_SMEM);
    cudaFuncSetAttribute(gemm0_coef,
                         cudaFuncAttributeMaxDynamicSharedMemorySize, GSM_BYTES);
    cudaFuncSetAttribute(gemm_out_tc,
                         cudaFuncAttributeMaxDynamicSharedMemorySize, GSM_BYTES);

    // 1) one prep kernel: x fp16 + weight gathers + filter MLP h2
    prep_split<<<22528, 256>>>(x, ipw, ow, fw1, fb1, fw2, fb2);
    // 2) merged launch: coef GEMM tiles (first) + in_proj GEMM tiles (fp16,
    //    double-buffered pipeline)
    gemm0_coef<<<NCOEF_B + 2048, 256, GSM_BYTES>>>(ipb, fw3, fb3);
    // 3) FFT long conv, 1024 threads (fused short-conv, stash, mult, gate)
    fft_conv_kernel<<<CH, FFT_T, FFT_SMEM>>>(sw, sb);
    // 4) out GEMM (fp16, double-buffered pipeline)
    gemm_out_tc<<<dim3(8, 128), 256, GSM_BYTES>>>(ob, out);
}